// round 9
// baseline (speedup 1.0000x reference)
#include <cuda_runtime.h>
#include <cuda_bf16.h>
#include <cstdint>
#include <math.h>

#define NN 50000
#define NE 800000
#define DD 64
#define HH 128
#define GG 128
#define NL 3
#define NT2 (NE / 128)   // 6250 tiles of 128 edges

// ---------------- device scratch ----------------
__device__ float g_x[NN * DD];             // pre-BN node features
__device__ float g_AB[(size_t)NN * 256];   // [A=x'@W1a+b1 | B=x'@W1b]
__device__ float g_aggr[(size_t)NN * HH];
__device__ float g_stats[2][128];
__device__ float g_pool[GG * DD];
__device__ float g_cnt[GG];
__device__ int   g_hist[NN];
__device__ int   g_bsum[64];
__device__ int   g_perm[NE];

__device__ __forceinline__ float softplusf(float x) {
    return fmaxf(x, 0.0f) + __logf(1.0f + __expf(-fabsf(x)));
}
// fast softplus: 1 MUFU + poly for ln(1+u), u=e^-|x| in [0,1]
__device__ __forceinline__ float spf(float x) {
    float u = __expf(-fabsf(x));
    float p = fmaf(0.0834f, u, -0.2474f);
    p = fmaf(p, u, 0.4427f);
    float l = 0.6931472f * u * fmaf(1.0f - u, p, 1.0f);
    return fmaxf(x, 0.0f) + l;
}
__device__ __forceinline__ unsigned to_tf32(float x) {
    unsigned u;
    asm("cvt.rna.tf32.f32 %0, %1;" : "=r"(u) : "f"(x));
    return u;
}
__device__ __forceinline__ unsigned pack_bf16(float lo, float hi) {
    unsigned r;
    asm("cvt.rn.bf16x2.f32 %0, %1, %2;" : "=r"(r) : "f"(hi), "f"(lo));
    return r;
}
__device__ __forceinline__ void mma8(float* c, unsigned a0, unsigned a1,
                                     unsigned a2, unsigned a3,
                                     unsigned b0, unsigned b1) {
    asm volatile(
        "mma.sync.aligned.m16n8k8.row.col.f32.tf32.tf32.f32 "
        "{%0,%1,%2,%3}, {%4,%5,%6,%7}, {%8,%9}, {%0,%1,%2,%3};"
        : "+f"(c[0]), "+f"(c[1]), "+f"(c[2]), "+f"(c[3])
        : "r"(a0), "r"(a1), "r"(a2), "r"(a3), "r"(b0), "r"(b1));
}
__device__ __forceinline__ void mma16bf(float* c, unsigned a0, unsigned a1,
                                        unsigned a2, unsigned a3,
                                        unsigned b0, unsigned b1) {
    asm volatile(
        "mma.sync.aligned.m16n8k16.row.col.f32.bf16.bf16.f32 "
        "{%0,%1,%2,%3}, {%4,%5,%6,%7}, {%8,%9}, {%0,%1,%2,%3};"
        : "+f"(c[0]), "+f"(c[1]), "+f"(c[2]), "+f"(c[3])
        : "r"(a0), "r"(a1), "r"(a2), "r"(a3), "r"(b0), "r"(b1));
}
__device__ __forceinline__ void bn_coeff(int l, int c, const float* gamma,
                                         const float* beta, float& S, float& T) {
    if (l == 0) { S = 1.0f; T = 0.0f; return; }
    const float* sb = g_stats[(l - 1) & 1];
    const float invN = 1.0f / (float)NN;
    float mu = sb[c] * invN;
    float var = sb[64 + c] * invN - mu * mu;
    float gi = gamma[(l - 1) * 64 + c] * rsqrtf(var + 1e-5f);
    S = gi;
    T = beta[(l - 1) * 64 + c] - mu * gi;
}

// ---------------- k0: embedding gather (+ zero g_hist) ----------------
__global__ void k0_embed(const int* __restrict__ az, const float* __restrict__ emb) {
    int idx = blockIdx.x * blockDim.x + threadIdx.x;
    if (idx < NN) g_hist[idx] = 0;
    if (idx >= NN * DD) return;
    int i = idx >> 6, c = idx & 63;
    g_x[idx] = emb[az[i] * DD + c];
}

// ---------------- counting sort ----------------
__global__ void k_hist(const int* __restrict__ ei) {
    int e = blockIdx.x * blockDim.x + threadIdx.x;
    if (e < NE) atomicAdd(&g_hist[ei[NE + e]], 1);
}
__global__ void k_scan_part() {
    __shared__ int wsum[32];
    int tid = threadIdx.x, lane = tid & 31, wid = tid >> 5;
    int i = blockIdx.x * 1024 + tid;
    int v = (i < NN) ? g_hist[i] : 0;
    int x = v;
    #pragma unroll
    for (int off = 1; off < 32; off <<= 1) {
        int y = __shfl_up_sync(0xffffffffu, x, off);
        if (lane >= off) x += y;
    }
    if (lane == 31) wsum[wid] = x;
    __syncthreads();
    if (wid == 0) {
        int s = wsum[lane];
        #pragma unroll
        for (int off = 1; off < 32; off <<= 1) {
            int y = __shfl_up_sync(0xffffffffu, s, off);
            if (lane >= off) s += y;
        }
        wsum[lane] = s;
    }
    __syncthreads();
    int woff = (wid > 0) ? wsum[wid - 1] : 0;
    if (i < NN) g_hist[i] = x - v + woff;   // block-local exclusive
    if (tid == 1023) g_bsum[blockIdx.x] = x + woff;
}
__global__ void k_scan_top() {
    __shared__ int s[64];
    int tid = threadIdx.x;
    int nb = (NN + 1023) / 1024;
    int v = (tid < nb) ? g_bsum[tid] : 0;
    s[tid] = v;
    __syncthreads();
    for (int off = 1; off < 64; off <<= 1) {
        int t = (tid >= off) ? s[tid - off] : 0;
        __syncthreads();
        s[tid] += t;
        __syncthreads();
    }
    if (tid < nb) g_bsum[tid] = s[tid] - v;
}
__global__ void k_scatter(const int* __restrict__ ei) {
    int e = blockIdx.x * blockDim.x + threadIdx.x;
    if (e >= NE) return;
    int d = ei[NE + e];
    int pos = atomicAdd(&g_hist[d], 1) + g_bsum[d >> 10];
    g_perm[pos] = e;
}
__global__ void kzero_pool() {
    int i = blockIdx.x * blockDim.x + threadIdx.x;
    if (i < GG * DD) g_pool[i] = 0.0f;
    if (i < GG) g_cnt[i] = 0.0f;
}

// ---------------- k1: AB = x' @ [W1a | W1b]; zeroes aggr + stats ----------------
__global__ void __launch_bounds__(256) k1_AB(int l, const float* __restrict__ W1,
                                             const float* __restrict__ b1,
                                             const float* __restrict__ gamma,
                                             const float* __restrict__ beta) {
    __shared__ float xs[64 * 68];
    __shared__ unsigned ws[128 * 20];
    __shared__ float bnS[64], bnT[64];
    int tid = threadIdx.x, warp = tid >> 5, lane = tid & 31;
    int g = lane >> 2, tg = lane & 3;
    int n0 = blockIdx.x * 64;
    int half = blockIdx.y;
    int mb = (warp & 3) * 16, nb = (warp >> 2) * 64;

    if (tid < 64) bn_coeff(l, tid, gamma, beta, bnS[tid], bnT[tid]);
    if (blockIdx.x == 0 && half == 0 && tid < 128) g_stats[l & 1][tid] = 0.0f;
    {
        float4 z = make_float4(0.f, 0.f, 0.f, 0.f);
        float4* Az = (float4*)g_aggr;
        #pragma unroll
        for (int it = 0; it < 4; ++it) {
            int idx = tid + it * 256;
            int i = idx >> 4, qc = idx & 15;
            int node = n0 + i;
            if (node < NN) Az[(size_t)node * 32 + half * 16 + qc] = z;
        }
    }
    __syncthreads();

    #pragma unroll
    for (int it = 0; it < 16; ++it) {
        int idx = tid + it * 256;
        int i = idx >> 6, c = idx & 63;
        int node = n0 + i;
        float v = (node < NN) ? g_x[(size_t)node * DD + c] : 0.0f;
        xs[i * 68 + c] = v * bnS[c] + bnT[c];
    }
    const float* Wp = W1 + ((size_t)l * 129 + half * 64) * 128;

    float acc[8][4] = {};
    for (int k0 = 0; k0 < 64; k0 += 16) {
        __syncthreads();
        #pragma unroll
        for (int it = 0; it < 8; ++it) {
            int idx = tid + it * 256;
            int col = idx & 127, kk = idx >> 7;
            ws[col * 20 + kk] = to_tf32(Wp[(size_t)(k0 + kk) * 128 + col]);
        }
        __syncthreads();
        #pragma unroll
        for (int ks = 0; ks < 16; ks += 8) {
            unsigned a0 = to_tf32(xs[(mb + g) * 68 + k0 + ks + tg]);
            unsigned a1 = to_tf32(xs[(mb + g + 8) * 68 + k0 + ks + tg]);
            unsigned a2 = to_tf32(xs[(mb + g) * 68 + k0 + ks + tg + 4]);
            unsigned a3 = to_tf32(xs[(mb + g + 8) * 68 + k0 + ks + tg + 4]);
            #pragma unroll
            for (int nt = 0; nt < 8; ++nt) {
                unsigned b0 = ws[(nb + nt * 8 + g) * 20 + ks + tg];
                unsigned b1r = ws[(nb + nt * 8 + g) * 20 + ks + tg + 4];
                mma8(acc[nt], a0, a1, a2, a3, b0, b1r);
            }
        }
    }
    int row0 = n0 + mb + g, row1 = row0 + 8;
    #pragma unroll
    for (int nt = 0; nt < 8; ++nt) {
        int c0 = nb + nt * 8 + 2 * tg;
        float bb0 = (half == 0) ? b1[l * 128 + c0] : 0.0f;
        float bb1 = (half == 0) ? b1[l * 128 + c0 + 1] : 0.0f;
        if (row0 < NN) {
            g_AB[(size_t)row0 * 256 + half * 128 + c0]     = acc[nt][0] + bb0;
            g_AB[(size_t)row0 * 256 + half * 128 + c0 + 1] = acc[nt][1] + bb1;
        }
        if (row1 < NN) {
            g_AB[(size_t)row1 * 256 + half * 128 + c0]     = acc[nt][2] + bb0;
            g_AB[(size_t)row1 * 256 + half * 128 + c0 + 1] = acc[nt][3] + bb1;
        }
    }
}

// ---------------- k2: persistent edge MLP, bf16 mma, 128-edge tiles ----------------
// smem (bytes): w2b bf16[128][136]@0 (34816) | h1/m bf16[128][136]@34816 (34816)
//   srcs[2][128]@69632 | dsts[2][128]@70656 | es[2][128]@71680
//   w1e[128]@72704 | b2s[128]@73216 ; total 73728
#define K2_GRID 296
#define K2_SMEM 73728
__global__ void __launch_bounds__(256, 2) k2_edge(int l, const int* __restrict__ ei,
                                                  const float* __restrict__ eattr,
                                                  const float* __restrict__ W1,
                                                  const float* __restrict__ W2,
                                                  const float* __restrict__ b2) {
    extern __shared__ char sm8[];
    __nv_bfloat16* w2b = (__nv_bfloat16*)sm8;
    __nv_bfloat16* h1b = (__nv_bfloat16*)(sm8 + 34816);
    int* srcs = (int*)(sm8 + 69632);
    int* dsts = (int*)(sm8 + 70656);
    float* es = (float*)(sm8 + 71680);
    float* w1e = (float*)(sm8 + 72704);
    float* b2s = (float*)(sm8 + 73216);

    int tid = threadIdx.x, warp = tid >> 5, lane = tid & 31;
    int g = lane >> 2, tg = lane & 3;
    int mb = (warp & 3) * 32, nb = (warp >> 2) * 64;

    // stage W2 bf16 [col][k] pitch 136 (once)
    #pragma unroll
    for (int it = 0; it < 64; ++it) {
        int idx = tid + it * 256;              // 16384
        int col = idx & 127, kk = idx >> 7;
        w2b[col * 136 + kk] = __float2bfloat16(W2[((size_t)l * 128 + kk) * 128 + col]);
    }
    if (tid < 128) w1e[tid] = W1[((size_t)l * 129 + 128) * 128 + tid];
    else b2s[tid - 128] = b2[l * 128 + (tid - 128)];

    const float4* AB4 = (const float4*)g_AB;
    const float4* w1e4 = (const float4*)w1e;

    auto stage = [&](int tt, int s) {
        int e = g_perm[tt * 128 + tid];
        srcs[s * 128 + tid] = ei[e];
        dsts[s * 128 + tid] = ei[NE + e];
        es[s * 128 + tid] = eattr[e];
    };
    // phase A: 16 edges per warp, lane = col-quad; A[dst] reused along runs
    auto phaseA = [&](int s) {
        int q = lane;
        int eb = warp * 16;
        const int* S = srcs + s * 128;
        const int* D = dsts + s * 128;
        const float* E = es + s * 128;
        float4 w = w1e4[q];
        float4 aq = make_float4(0.f, 0.f, 0.f, 0.f);
        int prevd = -1;
        #pragma unroll
        for (int j = 0; j < 16; ++j) {
            int e = eb + j;
            int d = D[e];
            if (d != prevd) { aq = AB4[(size_t)d * 64 + q]; prevd = d; }
            float4 b = AB4[(size_t)S[e] * 64 + 32 + q];
            float ev = E[e];
            uint2 r;
            r.x = pack_bf16(spf(aq.x + b.x + ev * w.x), spf(aq.y + b.y + ev * w.y));
            r.y = pack_bf16(spf(aq.z + b.z + ev * w.z), spf(aq.w + b.w + ev * w.w));
            *(uint2*)(h1b + e * 136 + q * 4) = r;
        }
    };

    int t0 = blockIdx.x;
    if (t0 < NT2 && tid < 128) stage(t0, 0);
    __syncthreads();

    int i = 0;
    for (int t = t0; t < NT2; t += K2_GRID, ++i) {
        int sc = i & 1, sn = sc ^ 1;
        int tn = t + K2_GRID;

        // phase A into h1 (reduce of prev tile already synced)
        phaseA(sc);
        __syncthreads();

        // phase B: D = h1 @ W2, bf16 m16n8k16; 2 M-tiles per warp (B-frag reuse)
        float acc[2][8][4] = {};
        #pragma unroll
        for (int kc = 0; kc < 128; kc += 16) {
            unsigned a[2][4];
            #pragma unroll
            for (int mt = 0; mt < 2; ++mt) {
                int r0 = mb + mt * 16 + g;
                a[mt][0] = *(const unsigned*)(h1b + r0 * 136 + kc + 2 * tg);
                a[mt][1] = *(const unsigned*)(h1b + (r0 + 8) * 136 + kc + 2 * tg);
                a[mt][2] = *(const unsigned*)(h1b + r0 * 136 + kc + 2 * tg + 8);
                a[mt][3] = *(const unsigned*)(h1b + (r0 + 8) * 136 + kc + 2 * tg + 8);
            }
            #pragma unroll
            for (int nt = 0; nt < 8; ++nt) {
                int col = nb + nt * 8 + g;
                unsigned b0 = *(const unsigned*)(w2b + col * 136 + kc + 2 * tg);
                unsigned b1r = *(const unsigned*)(w2b + col * 136 + kc + 2 * tg + 8);
                mma16bf(acc[0][nt], a[0][0], a[0][1], a[0][2], a[0][3], b0, b1r);
                mma16bf(acc[1][nt], a[1][0], a[1][1], a[1][2], a[1][3], b0, b1r);
            }
        }
        // stage next tile's indices while regs hold acc
        if (tn < NT2 && tid < 128) stage(tn, sn);
        __syncthreads();   // all h1 reads done; staging visible

        // epilogue: m = spf(D + b2) -> bf16 over h1
        #pragma unroll
        for (int mt = 0; mt < 2; ++mt) {
            int r0 = mb + mt * 16 + g;
            #pragma unroll
            for (int nt = 0; nt < 8; ++nt) {
                int c0 = nb + nt * 8 + 2 * tg;
                unsigned u0 = pack_bf16(spf(acc[mt][nt][0] + b2s[c0]),
                                        spf(acc[mt][nt][1] + b2s[c0 + 1]));
                unsigned u1 = pack_bf16(spf(acc[mt][nt][2] + b2s[c0]),
                                        spf(acc[mt][nt][3] + b2s[c0 + 1]));
                *(unsigned*)(h1b + r0 * 136 + c0) = u0;
                *(unsigned*)(h1b + (r0 + 8) * 136 + c0) = u1;
            }
        }
        __syncthreads();

        // segmented reduction over sorted dst runs (bf16 m)
        {
            const int* D = dsts + sc * 128;
            int c = tid & 127;
            int r0 = (tid >> 7) * 64;
            float racc = 0.0f;
            int prev = D[r0];
            #pragma unroll 4
            for (int r = r0; r < r0 + 64; ++r) {
                int d = D[r];
                if (d != prev) {
                    atomicAdd(&g_aggr[(size_t)prev * 128 + c], racc);
                    racc = 0.0f;
                    prev = d;
                }
                racc += __bfloat162float(h1b[r * 136 + c]);
            }
            atomicAdd(&g_aggr[(size_t)prev * 128 + c], racc);
        }
        __syncthreads();   // reduce done before next phaseA overwrites h1/m
    }
}

// ---------------- k3: node MLP (M=64, tf32 mma) + residual + BN stats ----------------
#define K3_SMEM 61440
__global__ void __launch_bounds__(256, 3) k3_node(int l, const float* __restrict__ W1,
                                                  const float* __restrict__ b1,
                                                  const float* __restrict__ W2,
                                                  const float* __restrict__ b2,
                                                  const float* __restrict__ gamma,
                                                  const float* __restrict__ beta) {
    extern __shared__ char sm3[];
    float* hs = (float*)sm3;
    unsigned* ws = (unsigned*)(sm3 + 50176);
    float* ssum = (float*)(sm3 + 60416);
    float* ssq = (float*)(sm3 + 60672);
    float* bnS = (float*)(sm3 + 60928);
    float* bnT = (float*)(sm3 + 61184);

    int tid = threadIdx.x, warp = tid >> 5, lane = tid & 31;
    int g = lane >> 2, tg = lane & 3;
    int mb = (warp & 3) * 16, nb = (warp >> 2) * 64;
    int n0 = blockIdx.x * 64;

    if (tid < 64) {
        ssum[tid] = 0.0f; ssq[tid] = 0.0f;
        bn_coeff(l, tid, gamma, beta, bnS[tid], bnT[tid]);
    }
    __syncthreads();

    for (int it = 0; it < 48; ++it) {
        int idx = tid + it * 256;
        int i = idx / 192, c = idx - i * 192;
        int node = n0 + i;
        float v = 0.0f;
        if (node < NN) {
            if (c < 64) v = g_x[(size_t)node * DD + c] * bnS[c] + bnT[c];
            else v = g_aggr[(size_t)node * HH + (c - 64)];
        }
        hs[i * 196 + c] = v;
    }

    float acc[8][4] = {};
    for (int k0 = 0; k0 < 192; k0 += 16) {
        __syncthreads();
        #pragma unroll
        for (int it = 0; it < 8; ++it) {
            int idx = tid + it * 256;
            int col = idx & 127, kk = idx >> 7;
            ws[col * 20 + kk] = to_tf32(W1[((size_t)l * 192 + k0 + kk) * 128 + col]);
        }
        __syncthreads();
        #pragma unroll
        for (int ks = 0; ks < 16; ks += 8) {
            unsigned a0 = to_tf32(hs[(mb + g) * 196 + k0 + ks + tg]);
            unsigned a1 = to_tf32(hs[(mb + g + 8) * 196 + k0 + ks + tg]);
            unsigned a2 = to_tf32(hs[(mb + g) * 196 + k0 + ks + tg + 4]);
            unsigned a3 = to_tf32(hs[(mb + g + 8) * 196 + k0 + ks + tg + 4]);
            #pragma unroll
            for (int nt = 0; nt < 8; ++nt) {
                unsigned b0 = ws[(nb + nt * 8 + g) * 20 + ks + tg];
                unsigned b1r = ws[(nb + nt * 8 + g) * 20 + ks + tg + 4];
                mma8(acc[nt], a0, a1, a2, a3, b0, b1r);
            }
        }
    }
    __syncthreads();
    #pragma unroll
    for (int nt = 0; nt < 8; ++nt) {
        int c0 = nb + nt * 8 + 2 * tg;
        hs[(mb + g) * 196 + 64 + c0]         = spf(acc[nt][0] + b1[l * 128 + c0]);
        hs[(mb + g) * 196 + 64 + c0 + 1]     = spf(acc[nt][1] + b1[l * 128 + c0 + 1]);
        hs[(mb + g + 8) * 196 + 64 + c0]     = spf(acc[nt][2] + b1[l * 128 + c0]);
        hs[(mb + g + 8) * 196 + 64 + c0 + 1] = spf(acc[nt][3] + b1[l * 128 + c0 + 1]);
    }

    int nb2 = (warp >> 2) * 32;
    float acc2[4][4] = {};
    for (int k0 = 0; k0 < 128; k0 += 16) {
        __syncthreads();
        #pragma unroll
        for (int it = 0; it < 4; ++it) {
            int idx = tid + it * 256;
            int col = idx & 63, kk = idx >> 6;
            ws[col * 20 + kk] = to_tf32(W2[((size_t)l * 128 + k0 + kk) * 64 + col]);
        }
        __syncthreads();
        #pragma unroll
        for (int ks = 0; ks < 16; ks += 8) {
            unsigned a0 = to_tf32(hs[(mb + g) * 196 + 64 + k0 + ks + tg]);
            unsigned a1 = to_tf32(hs[(mb + g + 8) * 196 + 64 + k0 + ks + tg]);
            unsigned a2 = to_tf32(hs[(mb + g) * 196 + 64 + k0 + ks + tg + 4]);
            unsigned a3 = to_tf32(hs[(mb + g + 8) * 196 + 64 + k0 + ks + tg + 4]);
            #pragma unroll
            for (int nt = 0; nt < 4; ++nt) {
                unsigned b0 = ws[(nb2 + nt * 8 + g) * 20 + ks + tg];
                unsigned b1r = ws[(nb2 + nt * 8 + g) * 20 + ks + tg + 4];
                mma8(acc2[nt], a0, a1, a2, a3, b0, b1r);
            }
        }
    }

    #pragma unroll
    for (int nt = 0; nt < 4; ++nt) {
        int c0 = nb2 + nt * 8 + 2 * tg;
        float bb0 = b2[l * 64 + c0], bb1 = b2[l * 64 + c0 + 1];
        int row0 = mb + g, row1 = mb + g + 8;
        int node0 = n0 + row0, node1 = n0 + row1;
        if (node0 < NN) {
            float y0 = acc2[nt][0] + bb0 + hs[row0 * 196 + c0];
            float y1 = acc2[nt][1] + bb1 + hs[row0 * 196 + c0 + 1];
            g_x[(size_t)node0 * DD + c0] = y0;
            g_x[(size_t)node0 * DD + c0 + 1] = y1;
            atomicAdd(&ssum[c0], y0);     atomicAdd(&ssum[c0 + 1], y1);
            atomicAdd(&ssq[c0], y0 * y0); atomicAdd(&ssq[c0 + 1], y1 * y1);
        }
        if (node1 < NN) {
            float y2 = acc2[nt][2] + bb0 + hs[row1 * 196 + c0];
            float y3 = acc2[nt][3] + bb1 + hs[row1 * 196 + c0 + 1];
            g_x[(size_t)node1 * DD + c0] = y2;
            g_x[(size_t)node1 * DD + c0 + 1] = y3;
            atomicAdd(&ssum[c0], y2);     atomicAdd(&ssum[c0 + 1], y3);
            atomicAdd(&ssq[c0], y2 * y2); atomicAdd(&ssq[c0 + 1], y3 * y3);
        }
    }
    __syncthreads();
    if (tid < 64) {
        atomicAdd(&g_stats[l & 1][tid], ssum[tid]);
        atomicAdd(&g_stats[l & 1][64 + tid], ssq[tid]);
    }
}

// ---------------- k5: global mean pool (applies final BN) ----------------
__global__ void k5_pool(const int* __restrict__ batch,
                        const float* __restrict__ gamma, const float* __restrict__ beta) {
    int idx = blockIdx.x * blockDim.x + threadIdx.x;
    if (idx >= NN * DD) return;
    int i = idx >> 6, c = idx & 63;
    const float* sb = g_stats[(NL - 1) & 1];
    const float invN = 1.0f / (float)NN;
    float mu = sb[c] * invN;
    float var = sb[64 + c] * invN - mu * mu;
    float gi = gamma[(NL - 1) * 64 + c] * rsqrtf(var + 1e-5f);
    float v = g_x[idx] * gi + (beta[(NL - 1) * 64 + c] - mu * gi);
    int b = batch[i];
    atomicAdd(&g_pool[b * DD + c], v);
    if (c == 0) atomicAdd(&g_cnt[b], 1.0f);
}

// ---------------- k6: output MLP ----------------
__global__ void k6_out(const float* __restrict__ W1, const float* __restrict__ b1,
                       const float* __restrict__ W2, const float* __restrict__ b2,
                       float* __restrict__ out) {
    __shared__ float p[64];
    __shared__ float red[128];
    int g = blockIdx.x, c = threadIdx.x;
    if (c < 64) p[c] = g_pool[g * DD + c] / fmaxf(g_cnt[g], 1.0f);
    __syncthreads();
    float acc = b1[c];
    #pragma unroll
    for (int d = 0; d < 64; ++d) acc = fmaf(p[d], W1[d * 128 + c], acc);
    red[c] = softplusf(acc) * W2[c];
    __syncthreads();
    for (int s = 64; s > 0; s >>= 1) {
        if (c < s) red[c] += red[c + s];
        __syncthreads();
    }
    if (c == 0) out[g] = red[0] + b2[0];
}

// ---------------- launcher ----------------
extern "C" void kernel_launch(void* const* d_in, const int* in_sizes, int n_in,
                              void* d_out, int out_size) {
    const int*   atom_z = (const int*)  d_in[0];
    const int*   ei     = (const int*)  d_in[1];
    const float* eattr  = (const float*)d_in[2];
    const int*   batch  = (const int*)  d_in[3];
    const float* emb    = (const float*)d_in[4];
    const float* eW1    = (const float*)d_in[5];
    const float* eb1    = (const float*)d_in[6];
    const float* eW2    = (const float*)d_in[7];
    const float* eb2    = (const float*)d_in[8];
    const float* nW1    = (const float*)d_in[9];
    const float* nb1    = (const float*)d_in[10];
    const float* nW2    = (const float*)d_in[11];
    const float* nb2    = (const float*)d_in[12];
    const float* bng    = (const float*)d_in[13];
    const float* bnb    = (const float*)d_in[14];
    const float* oW1    = (const float*)d_in[15];
    const float* ob1    = (const float*)d_in[16];
    const float* oW2    = (const float*)d_in[17];
    const float* ob2    = (const float*)d_in[18];
    float* out = (float*)d_out;

    cudaFuncSetAttribute(k2_edge, cudaFuncAttributeMaxDynamicSharedMemorySize, K2_SMEM);
    cudaFuncSetAttribute(k3_node, cudaFuncAttributeMaxDynamicSharedMemorySize, K3_SMEM);

    int nsb = (NN + 1023) / 1024;

    k0_embed<<<(NN * DD + 255) / 256, 256>>>(atom_z, emb);
    k_hist<<<(NE + 255) / 256, 256>>>(ei);
    k_scan_part<<<nsb, 1024>>>();
    k1_AB<<<dim3((NN + 63) / 64, 2), 256>>>(0, eW1, eb1, bng, bnb);
    k_scan_top<<<1, 64>>>();
    k_scatter<<<(NE + 255) / 256, 256>>>(ei);

    k2_edge<<<K2_GRID, 256, K2_SMEM>>>(0, ei, eattr, eW1, eW2, eb2);
    k3_node<<<(NN + 63) / 64, 256, K3_SMEM>>>(0, nW1, nb1, nW2, nb2, bng, bnb);
    for (int l = 1; l < NL; ++l) {
        k1_AB<<<dim3((NN + 63) / 64, 2), 256>>>(l, eW1, eb1, bng, bnb);
        k2_edge<<<K2_GRID, 256, K2_SMEM>>>(l, ei, eattr, eW1, eW2, eb2);
        k3_node<<<(NN + 63) / 64, 256, K3_SMEM>>>(l, nW1, nb1, nW2, nb2, bng, bnb);
    }
    kzero_pool<<<(GG * DD + 255) / 256, 256>>>();
    k5_pool<<<(NN * DD + 255) / 256, 256>>>(batch, bng, bnb);
    k6_out<<<GG, 128>>>(oW1, ob1, oW2, ob2, out);
}

// round 10
// speedup vs baseline: 1.0348x; 1.0348x over previous
#include <cuda_runtime.h>
#include <cuda_bf16.h>
#include <cstdint>
#include <math.h>

#define NN 50000
#define NE 800000
#define DD 64
#define HH 128
#define GG 128
#define NL 3
#define NT (NE / 64)

// ---------------- device scratch ----------------
__device__ float g_x[NN * DD];             // pre-BN node features
__device__ float g_AB[(size_t)NN * 256];   // [A=x'@W1a+b1 | B=x'@W1b]
__device__ float g_aggr[(size_t)NN * HH];
__device__ float g_stats[2][128];
__device__ float g_pool[GG * DD];
__device__ float g_cnt[GG];
__device__ int   g_hist[NN];
__device__ int   g_bsum[64];
__device__ int   g_ssrc[NE];               // dst-sorted edge arrays
__device__ int   g_sdst[NE];
__device__ float g_seat[NE];

__device__ __forceinline__ float softplusf(float x) {
    return fmaxf(x, 0.0f) + __logf(1.0f + __expf(-fabsf(x)));
}
// fast softplus: 1 MUFU + poly for ln(1+u), u=e^-|x| in [0,1]
__device__ __forceinline__ float spf(float x) {
    float u = __expf(-fabsf(x));
    float p = fmaf(0.0834f, u, -0.2474f);
    p = fmaf(p, u, 0.4427f);
    float l = 0.6931472f * u * fmaf(1.0f - u, p, 1.0f);
    return fmaxf(x, 0.0f) + l;
}
__device__ __forceinline__ unsigned to_tf32(float x) {
    unsigned u;
    asm("cvt.rna.tf32.f32 %0, %1;" : "=r"(u) : "f"(x));
    return u;
}
__device__ __forceinline__ unsigned pack_bf16(float lo, float hi) {
    unsigned r;
    asm("cvt.rn.bf16x2.f32 %0, %1, %2;" : "=r"(r) : "f"(hi), "f"(lo));
    return r;
}
__device__ __forceinline__ void mma8(float* c, unsigned a0, unsigned a1,
                                     unsigned a2, unsigned a3,
                                     unsigned b0, unsigned b1) {
    asm volatile(
        "mma.sync.aligned.m16n8k8.row.col.f32.tf32.tf32.f32 "
        "{%0,%1,%2,%3}, {%4,%5,%6,%7}, {%8,%9}, {%0,%1,%2,%3};"
        : "+f"(c[0]), "+f"(c[1]), "+f"(c[2]), "+f"(c[3])
        : "r"(a0), "r"(a1), "r"(a2), "r"(a3), "r"(b0), "r"(b1));
}
__device__ __forceinline__ void mma16bf(float* c, unsigned a0, unsigned a1,
                                        unsigned a2, unsigned a3,
                                        unsigned b0, unsigned b1) {
    asm volatile(
        "mma.sync.aligned.m16n8k16.row.col.f32.bf16.bf16.f32 "
        "{%0,%1,%2,%3}, {%4,%5,%6,%7}, {%8,%9}, {%0,%1,%2,%3};"
        : "+f"(c[0]), "+f"(c[1]), "+f"(c[2]), "+f"(c[3])
        : "r"(a0), "r"(a1), "r"(a2), "r"(a3), "r"(b0), "r"(b1));
}
__device__ __forceinline__ void bn_coeff(int l, int c, const float* gamma,
                                         const float* beta, float& S, float& T) {
    if (l == 0) { S = 1.0f; T = 0.0f; return; }
    const float* sb = g_stats[(l - 1) & 1];
    const float invN = 1.0f / (float)NN;
    float mu = sb[c] * invN;
    float var = sb[64 + c] * invN - mu * mu;
    float gi = gamma[(l - 1) * 64 + c] * rsqrtf(var + 1e-5f);
    S = gi;
    T = beta[(l - 1) * 64 + c] - mu * gi;
}

// ---------------- k0: embedding gather (+ zero g_hist, pool) ----------------
__global__ void k0_embed(const int* __restrict__ az, const float* __restrict__ emb) {
    int idx = blockIdx.x * blockDim.x + threadIdx.x;
    if (idx < NN) g_hist[idx] = 0;
    if (idx < GG * DD) g_pool[idx] = 0.0f;
    if (idx < GG) g_cnt[idx] = 0.0f;
    if (idx >= NN * DD) return;
    int i = idx >> 6, c = idx & 63;
    g_x[idx] = emb[az[i] * DD + c];
}

// ---------------- counting sort (materializes sorted arrays) ----------------
__global__ void k_hist(const int* __restrict__ ei) {
    int e = blockIdx.x * blockDim.x + threadIdx.x;
    if (e < NE) atomicAdd(&g_hist[ei[NE + e]], 1);
}
__global__ void k_scan_part() {
    __shared__ int wsum[32];
    int tid = threadIdx.x, lane = tid & 31, wid = tid >> 5;
    int i = blockIdx.x * 1024 + tid;
    int v = (i < NN) ? g_hist[i] : 0;
    int x = v;
    #pragma unroll
    for (int off = 1; off < 32; off <<= 1) {
        int y = __shfl_up_sync(0xffffffffu, x, off);
        if (lane >= off) x += y;
    }
    if (lane == 31) wsum[wid] = x;
    __syncthreads();
    if (wid == 0) {
        int s = wsum[lane];
        #pragma unroll
        for (int off = 1; off < 32; off <<= 1) {
            int y = __shfl_up_sync(0xffffffffu, s, off);
            if (lane >= off) s += y;
        }
        wsum[lane] = s;
    }
    __syncthreads();
    int woff = (wid > 0) ? wsum[wid - 1] : 0;
    if (i < NN) g_hist[i] = x - v + woff;   // block-local exclusive
    if (tid == 1023) g_bsum[blockIdx.x] = x + woff;
}
__global__ void k_scan_top() {
    __shared__ int s[64];
    int tid = threadIdx.x;
    int nb = (NN + 1023) / 1024;
    int v = (tid < nb) ? g_bsum[tid] : 0;
    s[tid] = v;
    __syncthreads();
    for (int off = 1; off < 64; off <<= 1) {
        int t = (tid >= off) ? s[tid - off] : 0;
        __syncthreads();
        s[tid] += t;
        __syncthreads();
    }
    if (tid < nb) g_bsum[tid] = s[tid] - v;
}
__global__ void k_scatter(const int* __restrict__ ei, const float* __restrict__ eattr) {
    int e = blockIdx.x * blockDim.x + threadIdx.x;
    if (e >= NE) return;
    int d = ei[NE + e];
    int pos = atomicAdd(&g_hist[d], 1) + g_bsum[d >> 10];
    g_ssrc[pos] = ei[e];
    g_sdst[pos] = d;
    g_seat[pos] = eattr[e];
}

// ---------------- k1: AB = x' @ [W1a | W1b] (both halves); zeroes aggr + stats ----------------
__global__ void __launch_bounds__(256) k1_AB(int l, const float* __restrict__ W1,
                                             const float* __restrict__ b1,
                                             const float* __restrict__ gamma,
                                             const float* __restrict__ beta) {
    __shared__ unsigned xs[64 * 68];       // tf32, BN applied
    __shared__ unsigned ws[128 * 20];
    __shared__ float bnS[64], bnT[64];
    int tid = threadIdx.x, warp = tid >> 5, lane = tid & 31;
    int g = lane >> 2, tg = lane & 3;
    int n0 = blockIdx.x * 64;
    int mb = (warp & 3) * 16, nb = (warp >> 2) * 64;

    if (tid < 64) bn_coeff(l, tid, gamma, beta, bnS[tid], bnT[tid]);
    if (blockIdx.x == 0 && tid < 128) g_stats[l & 1][tid] = 0.0f;
    // zero aggr rows n0..n0+63 (all 128 cols)
    {
        float4 z = make_float4(0.f, 0.f, 0.f, 0.f);
        float4* Az = (float4*)g_aggr;
        #pragma unroll
        for (int it = 0; it < 8; ++it) {
            int idx = tid + it * 256;          // 2048
            int i = idx >> 5, qc = idx & 31;
            int node = n0 + i;
            if (node < NN) Az[(size_t)node * 32 + qc] = z;
        }
    }
    __syncthreads();   // bnS ready

    // stage xs as tf32 (float4 loads)
    {
        const float4* X4 = (const float4*)g_x;
        #pragma unroll
        for (int it = 0; it < 4; ++it) {
            int idx = tid + it * 256;          // 1024
            int i = idx >> 4, q = idx & 15;
            int node = n0 + i;
            float4 v = make_float4(0.f, 0.f, 0.f, 0.f);
            if (node < NN) v = X4[(size_t)node * 16 + q];
            int c = q * 4;
            uint4 r;
            r.x = to_tf32(v.x * bnS[c] + bnT[c]);
            r.y = to_tf32(v.y * bnS[c + 1] + bnT[c + 1]);
            r.z = to_tf32(v.z * bnS[c + 2] + bnT[c + 2]);
            r.w = to_tf32(v.w * bnS[c + 3] + bnT[c + 3]);
            *(uint4*)(xs + i * 68 + c) = r;
        }
    }

    for (int half = 0; half < 2; ++half) {
        const float* Wp = W1 + ((size_t)l * 129 + half * 64) * 128;
        float acc[8][4] = {};
        for (int k0 = 0; k0 < 64; k0 += 16) {
            __syncthreads();
            #pragma unroll
            for (int it = 0; it < 8; ++it) {
                int idx = tid + it * 256;
                int col = idx & 127, kk = idx >> 7;
                ws[col * 20 + kk] = to_tf32(Wp[(size_t)(k0 + kk) * 128 + col]);
            }
            __syncthreads();
            #pragma unroll
            for (int ks = 0; ks < 16; ks += 8) {
                unsigned a0 = xs[(mb + g) * 68 + k0 + ks + tg];
                unsigned a1 = xs[(mb + g + 8) * 68 + k0 + ks + tg];
                unsigned a2 = xs[(mb + g) * 68 + k0 + ks + tg + 4];
                unsigned a3 = xs[(mb + g + 8) * 68 + k0 + ks + tg + 4];
                #pragma unroll
                for (int nt = 0; nt < 8; ++nt) {
                    unsigned b0 = ws[(nb + nt * 8 + g) * 20 + ks + tg];
                    unsigned b1r = ws[(nb + nt * 8 + g) * 20 + ks + tg + 4];
                    mma8(acc[nt], a0, a1, a2, a3, b0, b1r);
                }
            }
        }
        int row0 = n0 + mb + g, row1 = row0 + 8;
        #pragma unroll
        for (int nt = 0; nt < 8; ++nt) {
            int c0 = nb + nt * 8 + 2 * tg;
            float bb0 = (half == 0) ? b1[l * 128 + c0] : 0.0f;
            float bb1 = (half == 0) ? b1[l * 128 + c0 + 1] : 0.0f;
            if (row0 < NN) {
                g_AB[(size_t)row0 * 256 + half * 128 + c0]     = acc[nt][0] + bb0;
                g_AB[(size_t)row0 * 256 + half * 128 + c0 + 1] = acc[nt][1] + bb1;
            }
            if (row1 < NN) {
                g_AB[(size_t)row1 * 256 + half * 128 + c0]     = acc[nt][2] + bb0;
                g_AB[(size_t)row1 * 256 + half * 128 + c0 + 1] = acc[nt][3] + bb1;
            }
        }
        if (half == 0) __syncthreads();   // ws reuse safe for next half
    }
}

// ---------------- k2: persistent, software-pipelined edge MLP (R6 structure) ----------------
// smem: w2b bf16[128][136]@0 | h1 bf16[2][64*136]@34816 (m overlays in bf16)
//       srcs2[2][64]@69632 | es2[2][64]@70144 | dsts3[3][64]@70656
//       w1e[128]@71424 | b2s[128]@71936 ; total 72448
#define K2_GRID 444
#define K2_SMEM 72448
__global__ void __launch_bounds__(256, 3) k2_edge(int l,
                                                  const float* __restrict__ W1,
                                                  const float* __restrict__ W2,
                                                  const float* __restrict__ b2) {
    extern __shared__ char sm8[];
    __nv_bfloat16* w2b = (__nv_bfloat16*)sm8;
    __nv_bfloat16* h1base = (__nv_bfloat16*)(sm8 + 34816);
    int* srcs2 = (int*)(sm8 + 69632);
    float* es2 = (float*)(sm8 + 70144);
    int* dsts3 = (int*)(sm8 + 70656);
    float* w1e = (float*)(sm8 + 71424);
    float* b2s = (float*)(sm8 + 71936);

    int tid = threadIdx.x, warp = tid >> 5, lane = tid & 31;
    int g = lane >> 2, tg = lane & 3;
    int mb = (warp & 3) * 16, nb = (warp >> 2) * 64;

    // stage W2 bf16 [col][k] pitch 136 (once)
    #pragma unroll
    for (int it = 0; it < 64; ++it) {
        int idx = tid + it * 256;
        int col = idx & 127, kk = idx >> 7;
        w2b[col * 136 + kk] = __float2bfloat16(W2[((size_t)l * 128 + kk) * 128 + col]);
    }
    if (tid < 128) w1e[tid] = W1[((size_t)l * 129 + 128) * 128 + tid];
    else b2s[tid - 128] = b2[l * 128 + (tid - 128)];

    const float4* AB4 = (const float4*)g_AB;
    const float4* w1e4 = (const float4*)w1e;

    auto stage = [&](int tt, int s, int ds) {
        int i4 = tt * 64 + tid;                // coalesced sorted-array reads
        srcs2[s * 64 + tid] = g_ssrc[i4];
        dsts3[ds * 64 + tid] = g_sdst[i4];
        es2[s * 64 + tid] = g_seat[i4];
    };
    auto phaseA = [&](__nv_bfloat16* H, int s, int ds) {
        int q = lane;
        int eb = warp * 8;
        const int* S = srcs2 + s * 64;
        const float* E = es2 + s * 64;
        const int* D = dsts3 + ds * 64;
        float4 w = w1e4[q];
        float4 aq = make_float4(0.f, 0.f, 0.f, 0.f);
        int prevd = -1;
        #pragma unroll
        for (int j = 0; j < 8; ++j) {
            int e = eb + j;
            int d = D[e];
            if (d != prevd) { aq = AB4[(size_t)d * 64 + q]; prevd = d; }
            float4 b = AB4[(size_t)S[e] * 64 + 32 + q];
            float ev = E[e];
            uint2 r;
            r.x = pack_bf16(spf(aq.x + b.x + ev * w.x), spf(aq.y + b.y + ev * w.y));
            r.y = pack_bf16(spf(aq.z + b.z + ev * w.z), spf(aq.w + b.w + ev * w.w));
            *(uint2*)(H + e * 136 + q * 4) = r;
        }
    };

    int t0 = blockIdx.x;
    if (t0 < NT && tid < 64) stage(t0, 0, 0);
    __syncthreads();
    if (t0 < NT) phaseA(h1base, 0, 0);
    if (t0 + K2_GRID < NT && tid < 64) stage(t0 + K2_GRID, 1, 1);
    __syncthreads();

    int i = 0;
    for (int t = t0; t < NT; t += K2_GRID, ++i) {
        int p = i & 1, q2 = 1 - p;
        int d_cur = i % 3, d_nxt = (i + 1) % 3, d_stg = (i + 2) % 3;
        __nv_bfloat16* h1p = h1base + p * (64 * 136);
        __nv_bfloat16* h1q = h1base + q2 * (64 * 136);

        // 1. phase B on h1p
        float acc[8][4] = {};
        #pragma unroll
        for (int kc = 0; kc < 128; kc += 16) {
            unsigned a0 = *(const unsigned*)(h1p + (mb + g) * 136 + kc + 2 * tg);
            unsigned a1 = *(const unsigned*)(h1p + (mb + g + 8) * 136 + kc + 2 * tg);
            unsigned a2 = *(const unsigned*)(h1p + (mb + g) * 136 + kc + 2 * tg + 8);
            unsigned a3 = *(const unsigned*)(h1p + (mb + g + 8) * 136 + kc + 2 * tg + 8);
            #pragma unroll
            for (int nt = 0; nt < 8; ++nt) {
                int col = nb + nt * 8 + g;
                unsigned b0 = *(const unsigned*)(w2b + col * 136 + kc + 2 * tg);
                unsigned b1r = *(const unsigned*)(w2b + col * 136 + kc + 2 * tg + 8);
                mma16bf(acc[nt], a0, a1, a2, a3, b0, b1r);
            }
        }

        // 2. phase A for t+G into h1q (overlaps MMA tail)
        int tn = t + K2_GRID;
        if (tn < NT) phaseA(h1q, q2, d_nxt);

        // 3. stage idx for t+2G
        int ts = t + 2 * K2_GRID;
        if (ts < NT && tid < 64) stage(ts, p, d_stg);
        __syncthreads();

        // 4. epilogue: m = spf(D + b2) -> bf16 over h1p
        #pragma unroll
        for (int nt = 0; nt < 8; ++nt) {
            int c0 = nb + nt * 8 + 2 * tg;
            unsigned u0 = pack_bf16(spf(acc[nt][0] + b2s[c0]), spf(acc[nt][1] + b2s[c0 + 1]));
            unsigned u1 = pack_bf16(spf(acc[nt][2] + b2s[c0]), spf(acc[nt][3] + b2s[c0 + 1]));
            *(unsigned*)(h1p + (mb + g) * 136 + c0) = u0;
            *(unsigned*)(h1p + (mb + g + 8) * 136 + c0) = u1;
        }
        __syncthreads();

        // 5. segmented reduction over sorted dst runs
        {
            const int* D = dsts3 + d_cur * 64;
            int c = tid & 127;
            int r0 = (tid >> 7) * 32;
            float racc = 0.0f;
            int prev = D[r0];
            #pragma unroll 4
            for (int r = r0; r < r0 + 32; ++r) {
                int d = D[r];
                if (d != prev) {
                    atomicAdd(&g_aggr[(size_t)prev * 128 + c], racc);
                    racc = 0.0f;
                    prev = d;
                }
                racc += __bfloat162float(h1p[r * 136 + c]);
            }
            atomicAdd(&g_aggr[(size_t)prev * 128 + c], racc);
        }
        __syncthreads();
    }
}

// ---------------- k3: node MLP (M=64, tf32 mma) + residual + BN stats ----------------
#define K3_SMEM 61440
__global__ void __launch_bounds__(256, 3) k3_node(int l, const float* __restrict__ W1,
                                                  const float* __restrict__ b1,
                                                  const float* __restrict__ W2,
                                                  const float* __restrict__ b2,
                                                  const float* __restrict__ gamma,
                                                  const float* __restrict__ beta) {
    extern __shared__ char sm3[];
    float* hs = (float*)sm3;
    unsigned* ws = (unsigned*)(sm3 + 50176);
    float* ssum = (float*)(sm3 + 60416);
    float* ssq = (float*)(sm3 + 60672);
    float* bnS = (float*)(sm3 + 60928);
    float* bnT = (float*)(sm3 + 61184);

    int tid = threadIdx.x, warp = tid >> 5, lane = tid & 31;
    int g = lane >> 2, tg = lane & 3;
    int mb = (warp & 3) * 16, nb = (warp >> 2) * 64;
    int n0 = blockIdx.x * 64;

    if (tid < 64) {
        ssum[tid] = 0.0f; ssq[tid] = 0.0f;
        bn_coeff(l, tid, gamma, beta, bnS[tid], bnT[tid]);
    }
    __syncthreads();

    for (int it = 0; it < 48; ++it) {
        int idx = tid + it * 256;
        int i = idx / 192, c = idx - i * 192;
        int node = n0 + i;
        float v = 0.0f;
        if (node < NN) {
            if (c < 64) v = g_x[(size_t)node * DD + c] * bnS[c] + bnT[c];
            else v = g_aggr[(size_t)node * HH + (c - 64)];
        }
        hs[i * 196 + c] = v;
    }

    float acc[8][4] = {};
    for (int k0 = 0; k0 < 192; k0 += 16) {
        __syncthreads();
        #pragma unroll
        for (int it = 0; it < 8; ++it) {
            int idx = tid + it * 256;
            int col = idx & 127, kk = idx >> 7;
            ws[col * 20 + kk] = to_tf32(W1[((size_t)l * 192 + k0 + kk) * 128 + col]);
        }
        __syncthreads();
        #pragma unroll
        for (int ks = 0; ks < 16; ks += 8) {
            unsigned a0 = to_tf32(hs[(mb + g) * 196 + k0 + ks + tg]);
            unsigned a1 = to_tf32(hs[(mb + g + 8) * 196 + k0 + ks + tg]);
            unsigned a2 = to_tf32(hs[(mb + g) * 196 + k0 + ks + tg + 4]);
            unsigned a3 = to_tf32(hs[(mb + g + 8) * 196 + k0 + ks + tg + 4]);
            #pragma unroll
            for (int nt = 0; nt < 8; ++nt) {
                unsigned b0 = ws[(nb + nt * 8 + g) * 20 + ks + tg];
                unsigned b1r = ws[(nb + nt * 8 + g) * 20 + ks + tg + 4];
                mma8(acc[nt], a0, a1, a2, a3, b0, b1r);
            }
        }
    }
    __syncthreads();
    #pragma unroll
    for (int nt = 0; nt < 8; ++nt) {
        int c0 = nb + nt * 8 + 2 * tg;
        hs[(mb + g) * 196 + 64 + c0]         = spf(acc[nt][0] + b1[l * 128 + c0]);
        hs[(mb + g) * 196 + 64 + c0 + 1]     = spf(acc[nt][1] + b1[l * 128 + c0 + 1]);
        hs[(mb + g + 8) * 196 + 64 + c0]     = spf(acc[nt][2] + b1[l * 128 + c0]);
        hs[(mb + g + 8) * 196 + 64 + c0 + 1] = spf(acc[nt][3] + b1[l * 128 + c0 + 1]);
    }

    int nb2 = (warp >> 2) * 32;
    float acc2[4][4] = {};
    for (int k0 = 0; k0 < 128; k0 += 16) {
        __syncthreads();
        #pragma unroll
        for (int it = 0; it < 4; ++it) {
            int idx = tid + it * 256;
            int col = idx & 63, kk = idx >> 6;
            ws[col * 20 + kk] = to_tf32(W2[((size_t)l * 128 + k0 + kk) * 64 + col]);
        }
        __syncthreads();
        #pragma unroll
        for (int ks = 0; ks < 16; ks += 8) {
            unsigned a0 = to_tf32(hs[(mb + g) * 196 + 64 + k0 + ks + tg]);
            unsigned a1 = to_tf32(hs[(mb + g + 8) * 196 + 64 + k0 + ks + tg]);
            unsigned a2 = to_tf32(hs[(mb + g) * 196 + 64 + k0 + ks + tg + 4]);
            unsigned a3 = to_tf32(hs[(mb + g + 8) * 196 + 64 + k0 + ks + tg + 4]);
            #pragma unroll
            for (int nt = 0; nt < 4; ++nt) {
                unsigned b0 = ws[(nb2 + nt * 8 + g) * 20 + ks + tg];
                unsigned b1r = ws[(nb2 + nt * 8 + g) * 20 + ks + tg + 4];
                mma8(acc2[nt], a0, a1, a2, a3, b0, b1r);
            }
        }
    }

    #pragma unroll
    for (int nt = 0; nt < 4; ++nt) {
        int c0 = nb2 + nt * 8 + 2 * tg;
        float bb0 = b2[l * 64 + c0], bb1 = b2[l * 64 + c0 + 1];
        int row0 = mb + g, row1 = mb + g + 8;
        int node0 = n0 + row0, node1 = n0 + row1;
        if (node0 < NN) {
            float y0 = acc2[nt][0] + bb0 + hs[row0 * 196 + c0];
            float y1 = acc2[nt][1] + bb1 + hs[row0 * 196 + c0 + 1];
            g_x[(size_t)node0 * DD + c0] = y0;
            g_x[(size_t)node0 * DD + c0 + 1] = y1;
            atomicAdd(&ssum[c0], y0);     atomicAdd(&ssum[c0 + 1], y1);
            atomicAdd(&ssq[c0], y0 * y0); atomicAdd(&ssq[c0 + 1], y1 * y1);
        }
        if (node1 < NN) {
            float y2 = acc2[nt][2] + bb0 + hs[row1 * 196 + c0];
            float y3 = acc2[nt][3] + bb1 + hs[row1 * 196 + c0 + 1];
            g_x[(size_t)node1 * DD + c0] = y2;
            g_x[(size_t)node1 * DD + c0 + 1] = y3;
            atomicAdd(&ssum[c0], y2);     atomicAdd(&ssum[c0 + 1], y3);
            atomicAdd(&ssq[c0], y2 * y2); atomicAdd(&ssq[c0 + 1], y3 * y3);
        }
    }
    __syncthreads();
    if (tid < 64) {
        atomicAdd(&g_stats[l & 1][tid], ssum[tid]);
        atomicAdd(&g_stats[l & 1][64 + tid], ssq[tid]);
    }
}

// ---------------- k5: global mean pool (applies final BN) ----------------
__global__ void k5_pool(const int* __restrict__ batch,
                        const float* __restrict__ gamma, const float* __restrict__ beta) {
    int idx = blockIdx.x * blockDim.x + threadIdx.x;
    if (idx >= NN * DD) return;
    int i = idx >> 6, c = idx & 63;
    const float* sb = g_stats[(NL - 1) & 1];
    const float invN = 1.0f / (float)NN;
    float mu = sb[c] * invN;
    float var = sb[64 + c] * invN - mu * mu;
    float gi = gamma[(NL - 1) * 64 + c] * rsqrtf(var + 1e-5f);
    float v = g_x[idx] * gi + (beta[(NL - 1) * 64 + c] - mu * gi);
    int b = batch[i];
    atomicAdd(&g_pool[b * DD + c], v);
    if (c == 0) atomicAdd(&g_cnt[b], 1.0f);
}

// ---------------- k6: output MLP ----------------
__global__ void k6_out(const float* __restrict__ W1, const float* __restrict__ b1,
                       const float* __restrict__ W2, const float* __restrict__ b2,
                       float* __restrict__ out) {
    __shared__ float p[64];
    __shared__ float red[128];
    int g = blockIdx.x, c = threadIdx.x;
    if (c < 64) p[c] = g_pool[g * DD + c] / fmaxf(g_cnt[g], 1.0f);
    __syncthreads();
    float acc = b1[c];
    #pragma unroll
    for (int d = 0; d < 64; ++d) acc = fmaf(p[d], W1[d * 128 + c], acc);
    red[c] = softplusf(acc) * W2[c];
    __syncthreads();
    for (int s = 64; s > 0; s >>= 1) {
        if (c < s) red[c] += red[c + s];
        __syncthreads();
    }
    if (c == 0) out[g] = red[0] + b2[0];
}

// ---------------- launcher ----------------
extern "C" void kernel_launch(void* const* d_in, const int* in_sizes, int n_in,
                              void* d_out, int out_size) {
    const int*   atom_z = (const int*)  d_in[0];
    const int*   ei     = (const int*)  d_in[1];
    const float* eattr  = (const float*)d_in[2];
    const int*   batch  = (const int*)  d_in[3];
    const float* emb    = (const float*)d_in[4];
    const float* eW1    = (const float*)d_in[5];
    const float* eb1    = (const float*)d_in[6];
    const float* eW2    = (const float*)d_in[7];
    const float* eb2    = (const float*)d_in[8];
    const float* nW1    = (const float*)d_in[9];
    const float* nb1    = (const float*)d_in[10];
    const float* nW2    = (const float*)d_in[11];
    const float* nb2    = (const float*)d_in[12];
    const float* bng    = (const float*)d_in[13];
    const float* bnb    = (const float*)d_in[14];
    const float* oW1    = (const float*)d_in[15];
    const float* ob1    = (const float*)d_in[16];
    const float* oW2    = (const float*)d_in[17];
    const float* ob2    = (const float*)d_in[18];
    float* out = (float*)d_out;

    cudaFuncSetAttribute(k2_edge, cudaFuncAttributeMaxDynamicSharedMemorySize, K2_SMEM);
    cudaFuncSetAttribute(k3_node, cudaFuncAttributeMaxDynamicSharedMemorySize, K3_SMEM);

    int nsb = (NN + 1023) / 1024;

    k0_embed<<<(NN * DD + 255) / 256, 256>>>(atom_z, emb);
    k_hist<<<(NE + 255) / 256, 256>>>(ei);
    k_scan_part<<<nsb, 1024>>>();
    k1_AB<<<(NN + 63) / 64, 256>>>(0, eW1, eb1, bng, bnb);
    k_scan_top<<<1, 64>>>();
    k_scatter<<<(NE + 255) / 256, 256>>>(ei, eattr);

    k2_edge<<<K2_GRID, 256, K2_SMEM>>>(0, eW1, eW2, eb2);
    k3_node<<<(NN + 63) / 64, 256, K3_SMEM>>>(0, nW1, nb1, nW2, nb2, bng, bnb);
    for (int l = 1; l < NL; ++l) {
        k1_AB<<<(NN + 63) / 64, 256>>>(l, eW1, eb1, bng, bnb);
        k2_edge<<<K2_GRID, 256, K2_SMEM>>>(l, eW1, eW2, eb2);
        k3_node<<<(NN + 63) / 64, 256, K3_SMEM>>>(l, nW1, nb1, nW2, nb2, bng, bnb);
    }
    k5_pool<<<(NN * DD + 255) / 256, 256>>>(batch, bng, bnb);
    k6_out<<<GG, 128>>>(oW1, ob1, oW2, ob2, out);
}

// round 11
// speedup vs baseline: 1.0695x; 1.0336x over previous
#include <cuda_runtime.h>
#include <cuda_bf16.h>
#include <cstdint>
#include <math.h>

#define NN 50000
#define NE 800000
#define DD 64
#define HH 128
#define GG 128
#define NL 3
#define NT (NE / 64)

// ---------------- device scratch ----------------
__device__ float g_x[NN * DD];             // pre-BN node features
__device__ float g_AB[(size_t)NN * 256];   // [A=x'@W1a+b1 | B=x'@W1b]
__device__ float g_aggr[(size_t)NN * HH];
__device__ float g_stats[2][128];
__device__ float g_pool[GG * DD];
__device__ float g_cnt[GG];
__device__ int   g_hist[NN];
__device__ int   g_bsum[64];
__device__ int   g_ssrc[NE];               // dst-sorted edge arrays
__device__ int   g_sdst[NE];
__device__ float g_seat[NE];

__device__ __forceinline__ float softplusf(float x) {
    return fmaxf(x, 0.0f) + __logf(1.0f + __expf(-fabsf(x)));
}
// fast softplus: 1 MUFU + poly for ln(1+u), u=e^-|x| in [0,1]
__device__ __forceinline__ float spf(float x) {
    float u = __expf(-fabsf(x));
    float p = fmaf(0.0834f, u, -0.2474f);
    p = fmaf(p, u, 0.4427f);
    float l = 0.6931472f * u * fmaf(1.0f - u, p, 1.0f);
    return fmaxf(x, 0.0f) + l;
}
__device__ __forceinline__ unsigned to_tf32(float x) {
    unsigned u;
    asm("cvt.rna.tf32.f32 %0, %1;" : "=r"(u) : "f"(x));
    return u;
}
__device__ __forceinline__ unsigned pack_bf16(float lo, float hi) {
    unsigned r;
    asm("cvt.rn.bf16x2.f32 %0, %1, %2;" : "=r"(r) : "f"(hi), "f"(lo));
    return r;
}
__device__ __forceinline__ void mma8(float* c, unsigned a0, unsigned a1,
                                     unsigned a2, unsigned a3,
                                     unsigned b0, unsigned b1) {
    asm volatile(
        "mma.sync.aligned.m16n8k8.row.col.f32.tf32.tf32.f32 "
        "{%0,%1,%2,%3}, {%4,%5,%6,%7}, {%8,%9}, {%0,%1,%2,%3};"
        : "+f"(c[0]), "+f"(c[1]), "+f"(c[2]), "+f"(c[3])
        : "r"(a0), "r"(a1), "r"(a2), "r"(a3), "r"(b0), "r"(b1));
}
__device__ __forceinline__ void mma16bf(float* c, unsigned a0, unsigned a1,
                                        unsigned a2, unsigned a3,
                                        unsigned b0, unsigned b1) {
    asm volatile(
        "mma.sync.aligned.m16n8k16.row.col.f32.bf16.bf16.f32 "
        "{%0,%1,%2,%3}, {%4,%5,%6,%7}, {%8,%9}, {%0,%1,%2,%3};"
        : "+f"(c[0]), "+f"(c[1]), "+f"(c[2]), "+f"(c[3])
        : "r"(a0), "r"(a1), "r"(a2), "r"(a3), "r"(b0), "r"(b1));
}
__device__ __forceinline__ void bn_coeff(int l, int c, const float* gamma,
                                         const float* beta, float& S, float& T) {
    if (l == 0) { S = 1.0f; T = 0.0f; return; }
    const float* sb = g_stats[(l - 1) & 1];
    const float invN = 1.0f / (float)NN;
    float mu = sb[c] * invN;
    float var = sb[64 + c] * invN - mu * mu;
    float gi = gamma[(l - 1) * 64 + c] * rsqrtf(var + 1e-5f);
    S = gi;
    T = beta[(l - 1) * 64 + c] - mu * gi;
}

// ---------------- k0: embedding gather (+ zero g_hist, pool) ----------------
__global__ void k0_embed(const int* __restrict__ az, const float* __restrict__ emb) {
    int idx = blockIdx.x * blockDim.x + threadIdx.x;
    if (idx < NN) g_hist[idx] = 0;
    if (idx < GG * DD) g_pool[idx] = 0.0f;
    if (idx < GG) g_cnt[idx] = 0.0f;
    if (idx >= NN * DD) return;
    int i = idx >> 6, c = idx & 63;
    g_x[idx] = emb[az[i] * DD + c];
}

// ---------------- counting sort (materializes sorted arrays) ----------------
__global__ void k_hist(const int* __restrict__ ei) {
    int e = blockIdx.x * blockDim.x + threadIdx.x;
    if (e < NE) atomicAdd(&g_hist[ei[NE + e]], 1);
}
__global__ void k_scan_part() {
    __shared__ int wsum[32];
    int tid = threadIdx.x, lane = tid & 31, wid = tid >> 5;
    int i = blockIdx.x * 1024 + tid;
    int v = (i < NN) ? g_hist[i] : 0;
    int x = v;
    #pragma unroll
    for (int off = 1; off < 32; off <<= 1) {
        int y = __shfl_up_sync(0xffffffffu, x, off);
        if (lane >= off) x += y;
    }
    if (lane == 31) wsum[wid] = x;
    __syncthreads();
    if (wid == 0) {
        int s = wsum[lane];
        #pragma unroll
        for (int off = 1; off < 32; off <<= 1) {
            int y = __shfl_up_sync(0xffffffffu, s, off);
            if (lane >= off) s += y;
        }
        wsum[lane] = s;
    }
    __syncthreads();
    int woff = (wid > 0) ? wsum[wid - 1] : 0;
    if (i < NN) g_hist[i] = x - v + woff;   // block-local exclusive
    if (tid == 1023) g_bsum[blockIdx.x] = x + woff;
}
__global__ void k_scan_top() {
    __shared__ int s[64];
    int tid = threadIdx.x;
    int nb = (NN + 1023) / 1024;
    int v = (tid < nb) ? g_bsum[tid] : 0;
    s[tid] = v;
    __syncthreads();
    for (int off = 1; off < 64; off <<= 1) {
        int t = (tid >= off) ? s[tid - off] : 0;
        __syncthreads();
        s[tid] += t;
        __syncthreads();
    }
    if (tid < nb) g_bsum[tid] = s[tid] - v;
}
__global__ void k_scatter(const int* __restrict__ ei, const float* __restrict__ eattr) {
    int e = blockIdx.x * blockDim.x + threadIdx.x;
    if (e >= NE) return;
    int d = ei[NE + e];
    int pos = atomicAdd(&g_hist[d], 1) + g_bsum[d >> 10];
    g_ssrc[pos] = ei[e];
    g_sdst[pos] = d;
    g_seat[pos] = eattr[e];
}

// ---------------- k1: AB = x' @ [W1a | W1b] (per-half, R6 shape); zeroes aggr + stats ----------------
__global__ void __launch_bounds__(256) k1_AB(int l, const float* __restrict__ W1,
                                             const float* __restrict__ b1,
                                             const float* __restrict__ gamma,
                                             const float* __restrict__ beta) {
    __shared__ unsigned xs[64 * 68];       // tf32, BN applied
    __shared__ unsigned ws[128 * 20];
    __shared__ float bnS[64], bnT[64];
    int tid = threadIdx.x, warp = tid >> 5, lane = tid & 31;
    int g = lane >> 2, tg = lane & 3;
    int n0 = blockIdx.x * 64;
    int half = blockIdx.y;
    int mb = (warp & 3) * 16, nb = (warp >> 2) * 64;

    if (tid < 64) bn_coeff(l, tid, gamma, beta, bnS[tid], bnT[tid]);
    if (blockIdx.x == 0 && half == 0 && tid < 128) g_stats[l & 1][tid] = 0.0f;
    // zero this block's slice of g_aggr (nodes n0..n0+63, cols half*64..+63)
    {
        float4 z = make_float4(0.f, 0.f, 0.f, 0.f);
        float4* Az = (float4*)g_aggr;
        #pragma unroll
        for (int it = 0; it < 4; ++it) {
            int idx = tid + it * 256;          // 1024
            int i = idx >> 4, qc = idx & 15;
            int node = n0 + i;
            if (node < NN) Az[(size_t)node * 32 + half * 16 + qc] = z;
        }
    }
    __syncthreads();   // bnS ready

    // stage xs as tf32 (float4 loads)
    {
        const float4* X4 = (const float4*)g_x;
        #pragma unroll
        for (int it = 0; it < 4; ++it) {
            int idx = tid + it * 256;          // 1024
            int i = idx >> 4, q = idx & 15;
            int node = n0 + i;
            float4 v = make_float4(0.f, 0.f, 0.f, 0.f);
            if (node < NN) v = X4[(size_t)node * 16 + q];
            int c = q * 4;
            uint4 r;
            r.x = to_tf32(v.x * bnS[c] + bnT[c]);
            r.y = to_tf32(v.y * bnS[c + 1] + bnT[c + 1]);
            r.z = to_tf32(v.z * bnS[c + 2] + bnT[c + 2]);
            r.w = to_tf32(v.w * bnS[c + 3] + bnT[c + 3]);
            *(uint4*)(xs + i * 68 + c) = r;
        }
    }
    const float* Wp = W1 + ((size_t)l * 129 + half * 64) * 128;

    float acc[8][4] = {};
    for (int k0 = 0; k0 < 64; k0 += 16) {
        __syncthreads();
        #pragma unroll
        for (int it = 0; it < 8; ++it) {
            int idx = tid + it * 256;
            int col = idx & 127, kk = idx >> 7;
            ws[col * 20 + kk] = to_tf32(Wp[(size_t)(k0 + kk) * 128 + col]);
        }
        __syncthreads();
        #pragma unroll
        for (int ks = 0; ks < 16; ks += 8) {
            unsigned a0 = xs[(mb + g) * 68 + k0 + ks + tg];
            unsigned a1 = xs[(mb + g + 8) * 68 + k0 + ks + tg];
            unsigned a2 = xs[(mb + g) * 68 + k0 + ks + tg + 4];
            unsigned a3 = xs[(mb + g + 8) * 68 + k0 + ks + tg + 4];
            #pragma unroll
            for (int nt = 0; nt < 8; ++nt) {
                unsigned b0 = ws[(nb + nt * 8 + g) * 20 + ks + tg];
                unsigned b1r = ws[(nb + nt * 8 + g) * 20 + ks + tg + 4];
                mma8(acc[nt], a0, a1, a2, a3, b0, b1r);
            }
        }
    }
    int row0 = n0 + mb + g, row1 = row0 + 8;
    #pragma unroll
    for (int nt = 0; nt < 8; ++nt) {
        int c0 = nb + nt * 8 + 2 * tg;
        float bb0 = (half == 0) ? b1[l * 128 + c0] : 0.0f;
        float bb1 = (half == 0) ? b1[l * 128 + c0 + 1] : 0.0f;
        if (row0 < NN) {
            g_AB[(size_t)row0 * 256 + half * 128 + c0]     = acc[nt][0] + bb0;
            g_AB[(size_t)row0 * 256 + half * 128 + c0 + 1] = acc[nt][1] + bb1;
        }
        if (row1 < NN) {
            g_AB[(size_t)row1 * 256 + half * 128 + c0]     = acc[nt][2] + bb0;
            g_AB[(size_t)row1 * 256 + half * 128 + c0 + 1] = acc[nt][3] + bb1;
        }
    }
}

// ---------------- k2: persistent, software-pipelined edge MLP (R6 structure, sorted arrays) ----------------
// smem: w2b bf16[128][136]@0 | h1 bf16[2][64*136]@34816 (m overlays in bf16)
//       srcs2[2][64]@69632 | es2[2][64]@70144 | dsts3[3][64]@70656
//       w1e[128]@71424 | b2s[128]@71936 ; total 72448
#define K2_GRID 444
#define K2_SMEM 72448
__global__ void __launch_bounds__(256, 3) k2_edge(int l,
                                                  const float* __restrict__ W1,
                                                  const float* __restrict__ W2,
                                                  const float* __restrict__ b2) {
    extern __shared__ char sm8[];
    __nv_bfloat16* w2b = (__nv_bfloat16*)sm8;
    __nv_bfloat16* h1base = (__nv_bfloat16*)(sm8 + 34816);
    int* srcs2 = (int*)(sm8 + 69632);
    float* es2 = (float*)(sm8 + 70144);
    int* dsts3 = (int*)(sm8 + 70656);
    float* w1e = (float*)(sm8 + 71424);
    float* b2s = (float*)(sm8 + 71936);

    int tid = threadIdx.x, warp = tid >> 5, lane = tid & 31;
    int g = lane >> 2, tg = lane & 3;
    int mb = (warp & 3) * 16, nb = (warp >> 2) * 64;

    // stage W2 bf16 [col][k] pitch 136 (once)
    #pragma unroll
    for (int it = 0; it < 64; ++it) {
        int idx = tid + it * 256;
        int col = idx & 127, kk = idx >> 7;
        w2b[col * 136 + kk] = __float2bfloat16(W2[((size_t)l * 128 + kk) * 128 + col]);
    }
    if (tid < 128) w1e[tid] = W1[((size_t)l * 129 + 128) * 128 + tid];
    else b2s[tid - 128] = b2[l * 128 + (tid - 128)];

    const float4* AB4 = (const float4*)g_AB;
    const float4* w1e4 = (const float4*)w1e;

    auto stage = [&](int tt, int s, int ds) {
        int i4 = tt * 64 + tid;                // coalesced sorted-array reads
        srcs2[s * 64 + tid] = g_ssrc[i4];
        dsts3[ds * 64 + tid] = g_sdst[i4];
        es2[s * 64 + tid] = g_seat[i4];
    };
    auto phaseA = [&](__nv_bfloat16* H, int s, int ds) {
        int q = lane;
        int eb = warp * 8;
        const int* S = srcs2 + s * 64;
        const float* E = es2 + s * 64;
        const int* D = dsts3 + ds * 64;
        float4 w = w1e4[q];
        float4 aq = make_float4(0.f, 0.f, 0.f, 0.f);
        int prevd = -1;
        #pragma unroll
        for (int j = 0; j < 8; ++j) {
            int e = eb + j;
            int d = D[e];
            if (d != prevd) { aq = AB4[(size_t)d * 64 + q]; prevd = d; }
            float4 b = AB4[(size_t)S[e] * 64 + 32 + q];
            float ev = E[e];
            uint2 r;
            r.x = pack_bf16(spf(aq.x + b.x + ev * w.x), spf(aq.y + b.y + ev * w.y));
            r.y = pack_bf16(spf(aq.z + b.z + ev * w.z), spf(aq.w + b.w + ev * w.w));
            *(uint2*)(H + e * 136 + q * 4) = r;
        }
    };

    int t0 = blockIdx.x;
    if (t0 < NT && tid < 64) stage(t0, 0, 0);
    __syncthreads();
    if (t0 < NT) phaseA(h1base, 0, 0);
    if (t0 + K2_GRID < NT && tid < 64) stage(t0 + K2_GRID, 1, 1);
    __syncthreads();

    int i = 0;
    for (int t = t0; t < NT; t += K2_GRID, ++i) {
        int p = i & 1, q2 = 1 - p;
        int d_cur = i % 3, d_nxt = (i + 1) % 3, d_stg = (i + 2) % 3;
        __nv_bfloat16* h1p = h1base + p * (64 * 136);
        __nv_bfloat16* h1q = h1base + q2 * (64 * 136);

        // 1. phase B on h1p
        float acc[8][4] = {};
        #pragma unroll
        for (int kc = 0; kc < 128; kc += 16) {
            unsigned a0 = *(const unsigned*)(h1p + (mb + g) * 136 + kc + 2 * tg);
            unsigned a1 = *(const unsigned*)(h1p + (mb + g + 8) * 136 + kc + 2 * tg);
            unsigned a2 = *(const unsigned*)(h1p + (mb + g) * 136 + kc + 2 * tg + 8);
            unsigned a3 = *(const unsigned*)(h1p + (mb + g + 8) * 136 + kc + 2 * tg + 8);
            #pragma unroll
            for (int nt = 0; nt < 8; ++nt) {
                int col = nb + nt * 8 + g;
                unsigned b0 = *(const unsigned*)(w2b + col * 136 + kc + 2 * tg);
                unsigned b1r = *(const unsigned*)(w2b + col * 136 + kc + 2 * tg + 8);
                mma16bf(acc[nt], a0, a1, a2, a3, b0, b1r);
            }
        }

        // 2. phase A for t+G into h1q (overlaps MMA tail)
        int tn = t + K2_GRID;
        if (tn < NT) phaseA(h1q, q2, d_nxt);

        // 3. stage idx for t+2G
        int ts = t + 2 * K2_GRID;
        if (ts < NT && tid < 64) stage(ts, p, d_stg);
        __syncthreads();

        // 4. epilogue: m = spf(D + b2) -> bf16 over h1p
        #pragma unroll
        for (int nt = 0; nt < 8; ++nt) {
            int c0 = nb + nt * 8 + 2 * tg;
            unsigned u0 = pack_bf16(spf(acc[nt][0] + b2s[c0]), spf(acc[nt][1] + b2s[c0 + 1]));
            unsigned u1 = pack_bf16(spf(acc[nt][2] + b2s[c0]), spf(acc[nt][3] + b2s[c0 + 1]));
            *(unsigned*)(h1p + (mb + g) * 136 + c0) = u0;
            *(unsigned*)(h1p + (mb + g + 8) * 136 + c0) = u1;
        }
        __syncthreads();

        // 5. segmented reduction over sorted dst runs
        {
            const int* D = dsts3 + d_cur * 64;
            int c = tid & 127;
            int r0 = (tid >> 7) * 32;
            float racc = 0.0f;
            int prev = D[r0];
            #pragma unroll 4
            for (int r = r0; r < r0 + 32; ++r) {
                int d = D[r];
                if (d != prev) {
                    atomicAdd(&g_aggr[(size_t)prev * 128 + c], racc);
                    racc = 0.0f;
                    prev = d;
                }
                racc += __bfloat162float(h1p[r * 136 + c]);
            }
            atomicAdd(&g_aggr[(size_t)prev * 128 + c], racc);
        }
        __syncthreads();
    }
}

// ---------------- k3: node MLP (M=64, tf32 mma) + residual + BN stats ----------------
#define K3_SMEM 61440
__global__ void __launch_bounds__(256, 3) k3_node(int l, const float* __restrict__ W1,
                                                  const float* __restrict__ b1,
                                                  const float* __restrict__ W2,
                                                  const float* __restrict__ b2,
                                                  const float* __restrict__ gamma,
                                                  const float* __restrict__ beta) {
    extern __shared__ char sm3[];
    float* hs = (float*)sm3;
    unsigned* ws = (unsigned*)(sm3 + 50176);
    float* ssum = (float*)(sm3 + 60416);
    float* ssq = (float*)(sm3 + 60672);
    float* bnS = (float*)(sm3 + 60928);
    float* bnT = (float*)(sm3 + 61184);

    int tid = threadIdx.x, warp = tid >> 5, lane = tid & 31;
    int g = lane >> 2, tg = lane & 3;
    int mb = (warp & 3) * 16, nb = (warp >> 2) * 64;
    int n0 = blockIdx.x * 64;

    if (tid < 64) {
        ssum[tid] = 0.0f; ssq[tid] = 0.0f;
        bn_coeff(l, tid, gamma, beta, bnS[tid], bnT[tid]);
    }
    __syncthreads();

    for (int it = 0; it < 48; ++it) {
        int idx = tid + it * 256;
        int i = idx / 192, c = idx - i * 192;
        int node = n0 + i;
        float v = 0.0f;
        if (node < NN) {
            if (c < 64) v = g_x[(size_t)node * DD + c] * bnS[c] + bnT[c];
            else v = g_aggr[(size_t)node * HH + (c - 64)];
        }
        hs[i * 196 + c] = v;
    }

    float acc[8][4] = {};
    for (int k0 = 0; k0 < 192; k0 += 16) {
        __syncthreads();
        #pragma unroll
        for (int it = 0; it < 8; ++it) {
            int idx = tid + it * 256;
            int col = idx & 127, kk = idx >> 7;
            ws[col * 20 + kk] = to_tf32(W1[((size_t)l * 192 + k0 + kk) * 128 + col]);
        }
        __syncthreads();
        #pragma unroll
        for (int ks = 0; ks < 16; ks += 8) {
            unsigned a0 = to_tf32(hs[(mb + g) * 196 + k0 + ks + tg]);
            unsigned a1 = to_tf32(hs[(mb + g + 8) * 196 + k0 + ks + tg]);
            unsigned a2 = to_tf32(hs[(mb + g) * 196 + k0 + ks + tg + 4]);
            unsigned a3 = to_tf32(hs[(mb + g + 8) * 196 + k0 + ks + tg + 4]);
            #pragma unroll
            for (int nt = 0; nt < 8; ++nt) {
                unsigned b0 = ws[(nb + nt * 8 + g) * 20 + ks + tg];
                unsigned b1r = ws[(nb + nt * 8 + g) * 20 + ks + tg + 4];
                mma8(acc[nt], a0, a1, a2, a3, b0, b1r);
            }
        }
    }
    __syncthreads();
    #pragma unroll
    for (int nt = 0; nt < 8; ++nt) {
        int c0 = nb + nt * 8 + 2 * tg;
        hs[(mb + g) * 196 + 64 + c0]         = spf(acc[nt][0] + b1[l * 128 + c0]);
        hs[(mb + g) * 196 + 64 + c0 + 1]     = spf(acc[nt][1] + b1[l * 128 + c0 + 1]);
        hs[(mb + g + 8) * 196 + 64 + c0]     = spf(acc[nt][2] + b1[l * 128 + c0]);
        hs[(mb + g + 8) * 196 + 64 + c0 + 1] = spf(acc[nt][3] + b1[l * 128 + c0 + 1]);
    }

    int nb2 = (warp >> 2) * 32;
    float acc2[4][4] = {};
    for (int k0 = 0; k0 < 128; k0 += 16) {
        __syncthreads();
        #pragma unroll
        for (int it = 0; it < 4; ++it) {
            int idx = tid + it * 256;
            int col = idx & 63, kk = idx >> 6;
            ws[col * 20 + kk] = to_tf32(W2[((size_t)l * 128 + k0 + kk) * 64 + col]);
        }
        __syncthreads();
        #pragma unroll
        for (int ks = 0; ks < 16; ks += 8) {
            unsigned a0 = to_tf32(hs[(mb + g) * 196 + 64 + k0 + ks + tg]);
            unsigned a1 = to_tf32(hs[(mb + g + 8) * 196 + 64 + k0 + ks + tg]);
            unsigned a2 = to_tf32(hs[(mb + g) * 196 + 64 + k0 + ks + tg + 4]);
            unsigned a3 = to_tf32(hs[(mb + g + 8) * 196 + 64 + k0 + ks + tg + 4]);
            #pragma unroll
            for (int nt = 0; nt < 4; ++nt) {
                unsigned b0 = ws[(nb2 + nt * 8 + g) * 20 + ks + tg];
                unsigned b1r = ws[(nb2 + nt * 8 + g) * 20 + ks + tg + 4];
                mma8(acc2[nt], a0, a1, a2, a3, b0, b1r);
            }
        }
    }

    #pragma unroll
    for (int nt = 0; nt < 4; ++nt) {
        int c0 = nb2 + nt * 8 + 2 * tg;
        float bb0 = b2[l * 64 + c0], bb1 = b2[l * 64 + c0 + 1];
        int row0 = mb + g, row1 = mb + g + 8;
        int node0 = n0 + row0, node1 = n0 + row1;
        if (node0 < NN) {
            float y0 = acc2[nt][0] + bb0 + hs[row0 * 196 + c0];
            float y1 = acc2[nt][1] + bb1 + hs[row0 * 196 + c0 + 1];
            g_x[(size_t)node0 * DD + c0] = y0;
            g_x[(size_t)node0 * DD + c0 + 1] = y1;
            atomicAdd(&ssum[c0], y0);     atomicAdd(&ssum[c0 + 1], y1);
            atomicAdd(&ssq[c0], y0 * y0); atomicAdd(&ssq[c0 + 1], y1 * y1);
        }
        if (node1 < NN) {
            float y2 = acc2[nt][2] + bb0 + hs[row1 * 196 + c0];
            float y3 = acc2[nt][3] + bb1 + hs[row1 * 196 + c0 + 1];
            g_x[(size_t)node1 * DD + c0] = y2;
            g_x[(size_t)node1 * DD + c0 + 1] = y3;
            atomicAdd(&ssum[c0], y2);     atomicAdd(&ssum[c0 + 1], y3);
            atomicAdd(&ssq[c0], y2 * y2); atomicAdd(&ssq[c0 + 1], y3 * y3);
        }
    }
    __syncthreads();
    if (tid < 64) {
        atomicAdd(&g_stats[l & 1][tid], ssum[tid]);
        atomicAdd(&g_stats[l & 1][64 + tid], ssq[tid]);
    }
}

// ---------------- k5: global mean pool (applies final BN) ----------------
__global__ void k5_pool(const int* __restrict__ batch,
                        const float* __restrict__ gamma, const float* __restrict__ beta) {
    int idx = blockIdx.x * blockDim.x + threadIdx.x;
    if (idx >= NN * DD) return;
    int i = idx >> 6, c = idx & 63;
    const float* sb = g_stats[(NL - 1) & 1];
    const float invN = 1.0f / (float)NN;
    float mu = sb[c] * invN;
    float var = sb[64 + c] * invN - mu * mu;
    float gi = gamma[(NL - 1) * 64 + c] * rsqrtf(var + 1e-5f);
    float v = g_x[idx] * gi + (beta[(NL - 1) * 64 + c] - mu * gi);
    int b = batch[i];
    atomicAdd(&g_pool[b * DD + c], v);
    if (c == 0) atomicAdd(&g_cnt[b], 1.0f);
}

// ---------------- k6: output MLP ----------------
__global__ void k6_out(const float* __restrict__ W1, const float* __restrict__ b1,
                       const float* __restrict__ W2, const float* __restrict__ b2,
                       float* __restrict__ out) {
    __shared__ float p[64];
    __shared__ float red[128];
    int g = blockIdx.x, c = threadIdx.x;
    if (c < 64) p[c] = g_pool[g * DD + c] / fmaxf(g_cnt[g], 1.0f);
    __syncthreads();
    float acc = b1[c];
    #pragma unroll
    for (int d = 0; d < 64; ++d) acc = fmaf(p[d], W1[d * 128 + c], acc);
    red[c] = softplusf(acc) * W2[c];
    __syncthreads();
    for (int s = 64; s > 0; s >>= 1) {
        if (c < s) red[c] += red[c + s];
        __syncthreads();
    }
    if (c == 0) out[g] = red[0] + b2[0];
}

// ---------------- launcher ----------------
extern "C" void kernel_launch(void* const* d_in, const int* in_sizes, int n_in,
                              void* d_out, int out_size) {
    const int*   atom_z = (const int*)  d_in[0];
    const int*   ei     = (const int*)  d_in[1];
    const float* eattr  = (const float*)d_in[2];
    const int*   batch  = (const int*)  d_in[3];
    const float* emb    = (const float*)d_in[4];
    const float* eW1    = (const float*)d_in[5];
    const float* eb1    = (const float*)d_in[6];
    const float* eW2    = (const float*)d_in[7];
    const float* eb2    = (const float*)d_in[8];
    const float* nW1    = (const float*)d_in[9];
    const float* nb1    = (const float*)d_in[10];
    const float* nW2    = (const float*)d_in[11];
    const float* nb2    = (const float*)d_in[12];
    const float* bng    = (const float*)d_in[13];
    const float* bnb    = (const float*)d_in[14];
    const float* oW1    = (const float*)d_in[15];
    const float* ob1    = (const float*)d_in[16];
    const float* oW2    = (const float*)d_in[17];
    const float* ob2    = (const float*)d_in[18];
    float* out = (float*)d_out;

    cudaFuncSetAttribute(k2_edge, cudaFuncAttributeMaxDynamicSharedMemorySize, K2_SMEM);
    cudaFuncSetAttribute(k3_node, cudaFuncAttributeMaxDynamicSharedMemorySize, K3_SMEM);

    int nsb = (NN + 1023) / 1024;

    k0_embed<<<(NN * DD + 255) / 256, 256>>>(atom_z, emb);
    k_hist<<<(NE + 255) / 256, 256>>>(ei);
    k_scan_part<<<nsb, 1024>>>();
    k1_AB<<<dim3((NN + 63) / 64, 2), 256>>>(0, eW1, eb1, bng, bnb);
    k_scan_top<<<1, 64>>>();
    k_scatter<<<(NE + 255) / 256, 256>>>(ei, eattr);

    k2_edge<<<K2_GRID, 256, K2_SMEM>>>(0, eW1, eW2, eb2);
    k3_node<<<(NN + 63) / 64, 256, K3_SMEM>>>(0, nW1, nb1, nW2, nb2, bng, bnb);
    for (int l = 1; l < NL; ++l) {
        k1_AB<<<dim3((NN + 63) / 64, 2), 256>>>(l, eW1, eb1, bng, bnb);
        k2_edge<<<K2_GRID, 256, K2_SMEM>>>(l, eW1, eW2, eb2);
        k3_node<<<(NN + 63) / 64, 256, K3_SMEM>>>(l, nW1, nb1, nW2, nb2, bng, bnb);
    }
    k5_pool<<<(NN * DD + 255) / 256, 256>>>(batch, bng, bnb);
    k6_out<<<GG, 128>>>(oW1, ob1, oW2, ob2, out);
}

// round 12
// speedup vs baseline: 1.1276x; 1.0543x over previous
#include <cuda_runtime.h>
#include <cuda_bf16.h>
#include <cstdint>
#include <math.h>

#define NN 50000
#define NE 800000
#define DD 64
#define HH 128
#define GG 128
#define NL 3
#define NT (NE / 64)

// ---------------- device scratch ----------------
__device__ float g_x[NN * DD];             // pre-BN node features
__device__ float g_AB[(size_t)NN * 256];   // [A=x'@W1a+b1 | B=x'@W1b]
__device__ float g_aggr[(size_t)NN * HH];
__device__ float g_stats[2][128];
__device__ float g_pool[GG * DD];
__device__ float g_cnt[GG];
__device__ int   g_hist[NN];
__device__ int   g_bsum[64];
__device__ int   g_ssrc[NE];               // dst-sorted edge arrays
__device__ int   g_sdst[NE];
__device__ float g_seat[NE];

__device__ __forceinline__ float softplusf(float x) {
    return fmaxf(x, 0.0f) + __logf(1.0f + __expf(-fabsf(x)));
}
// fast softplus: 1 MUFU + poly for ln(1+u), u=e^-|x| in [0,1]
__device__ __forceinline__ float spf(float x) {
    float u = __expf(-fabsf(x));
    float p = fmaf(0.0834f, u, -0.2474f);
    p = fmaf(p, u, 0.4427f);
    float l = 0.6931472f * u * fmaf(1.0f - u, p, 1.0f);
    return fmaxf(x, 0.0f) + l;
}
__device__ __forceinline__ unsigned pack_bf16(float lo, float hi) {
    unsigned r;
    asm("cvt.rn.bf16x2.f32 %0, %1, %2;" : "=r"(r) : "f"(hi), "f"(lo));
    return r;
}
__device__ __forceinline__ void mma16bf(float* c, unsigned a0, unsigned a1,
                                        unsigned a2, unsigned a3,
                                        unsigned b0, unsigned b1) {
    asm volatile(
        "mma.sync.aligned.m16n8k16.row.col.f32.bf16.bf16.f32 "
        "{%0,%1,%2,%3}, {%4,%5,%6,%7}, {%8,%9}, {%0,%1,%2,%3};"
        : "+f"(c[0]), "+f"(c[1]), "+f"(c[2]), "+f"(c[3])
        : "r"(a0), "r"(a1), "r"(a2), "r"(a3), "r"(b0), "r"(b1));
}
__device__ __forceinline__ void bn_coeff(int l, int c, const float* gamma,
                                         const float* beta, float& S, float& T) {
    if (l == 0) { S = 1.0f; T = 0.0f; return; }
    const float* sb = g_stats[(l - 1) & 1];
    const float invN = 1.0f / (float)NN;
    float mu = sb[c] * invN;
    float var = sb[64 + c] * invN - mu * mu;
    float gi = gamma[(l - 1) * 64 + c] * rsqrtf(var + 1e-5f);
    S = gi;
    T = beta[(l - 1) * 64 + c] - mu * gi;
}

// ---------------- k0: embedding gather (+ zero g_hist, pool) ----------------
__global__ void k0_embed(const int* __restrict__ az, const float* __restrict__ emb) {
    int idx = blockIdx.x * blockDim.x + threadIdx.x;
    if (idx < NN) g_hist[idx] = 0;
    if (idx < GG * DD) g_pool[idx] = 0.0f;
    if (idx < GG) g_cnt[idx] = 0.0f;
    if (idx >= NN * DD) return;
    int i = idx >> 6, c = idx & 63;
    g_x[idx] = emb[az[i] * DD + c];
}

// ---------------- counting sort (materializes sorted arrays) ----------------
__global__ void k_hist(const int* __restrict__ ei) {
    int e = blockIdx.x * blockDim.x + threadIdx.x;
    if (e < NE) atomicAdd(&g_hist[ei[NE + e]], 1);
}
__global__ void k_scan_part() {
    __shared__ int wsum[32];
    int tid = threadIdx.x, lane = tid & 31, wid = tid >> 5;
    int i = blockIdx.x * 1024 + tid;
    int v = (i < NN) ? g_hist[i] : 0;
    int x = v;
    #pragma unroll
    for (int off = 1; off < 32; off <<= 1) {
        int y = __shfl_up_sync(0xffffffffu, x, off);
        if (lane >= off) x += y;
    }
    if (lane == 31) wsum[wid] = x;
    __syncthreads();
    if (wid == 0) {
        int s = wsum[lane];
        #pragma unroll
        for (int off = 1; off < 32; off <<= 1) {
            int y = __shfl_up_sync(0xffffffffu, s, off);
            if (lane >= off) s += y;
        }
        wsum[lane] = s;
    }
    __syncthreads();
    int woff = (wid > 0) ? wsum[wid - 1] : 0;
    if (i < NN) g_hist[i] = x - v + woff;   // block-local exclusive
    if (tid == 1023) g_bsum[blockIdx.x] = x + woff;
}
__global__ void k_scan_top() {
    __shared__ int s[64];
    int tid = threadIdx.x;
    int nb = (NN + 1023) / 1024;
    int v = (tid < nb) ? g_bsum[tid] : 0;
    s[tid] = v;
    __syncthreads();
    for (int off = 1; off < 64; off <<= 1) {
        int t = (tid >= off) ? s[tid - off] : 0;
        __syncthreads();
        s[tid] += t;
        __syncthreads();
    }
    if (tid < nb) g_bsum[tid] = s[tid] - v;
}
__global__ void k_scatter(const int* __restrict__ ei, const float* __restrict__ eattr) {
    int e = blockIdx.x * blockDim.x + threadIdx.x;
    if (e >= NE) return;
    int d = ei[NE + e];
    int pos = atomicAdd(&g_hist[d], 1) + g_bsum[d >> 10];
    g_ssrc[pos] = ei[e];
    g_sdst[pos] = d;
    g_seat[pos] = eattr[e];
}

// ---------------- k1: AB = x' @ [W1a | W1b] (per-half, bf16 mma); zeroes aggr + stats ----------------
__global__ void __launch_bounds__(256) k1_AB(int l, const float* __restrict__ W1,
                                             const float* __restrict__ b1,
                                             const float* __restrict__ gamma,
                                             const float* __restrict__ beta) {
    __shared__ __nv_bfloat16 xs[64 * 72];  // bf16, BN applied; pitch 72
    __shared__ __nv_bfloat16 ws[128 * 24]; // W1 chunk [col][k], pitch 24
    __shared__ float bnS[64], bnT[64];
    int tid = threadIdx.x, warp = tid >> 5, lane = tid & 31;
    int g = lane >> 2, tg = lane & 3;
    int n0 = blockIdx.x * 64;
    int half = blockIdx.y;
    int mb = (warp & 3) * 16, nb = (warp >> 2) * 64;

    if (tid < 64) bn_coeff(l, tid, gamma, beta, bnS[tid], bnT[tid]);
    if (blockIdx.x == 0 && half == 0 && tid < 128) g_stats[l & 1][tid] = 0.0f;
    // zero this block's slice of g_aggr (nodes n0..n0+63, cols half*64..+63)
    {
        float4 z = make_float4(0.f, 0.f, 0.f, 0.f);
        float4* Az = (float4*)g_aggr;
        #pragma unroll
        for (int it = 0; it < 4; ++it) {
            int idx = tid + it * 256;          // 1024
            int i = idx >> 4, qc = idx & 15;
            int node = n0 + i;
            if (node < NN) Az[(size_t)node * 32 + half * 16 + qc] = z;
        }
    }
    __syncthreads();   // bnS ready

    // stage xs as bf16 (float4 loads, BN applied)
    {
        const float4* X4 = (const float4*)g_x;
        #pragma unroll
        for (int it = 0; it < 4; ++it) {
            int idx = tid + it * 256;          // 1024
            int i = idx >> 4, q = idx & 15;
            int node = n0 + i;
            float4 v = make_float4(0.f, 0.f, 0.f, 0.f);
            if (node < NN) v = X4[(size_t)node * 16 + q];
            int c = q * 4;
            uint2 r;
            r.x = pack_bf16(v.x * bnS[c] + bnT[c],     v.y * bnS[c + 1] + bnT[c + 1]);
            r.y = pack_bf16(v.z * bnS[c + 2] + bnT[c + 2], v.w * bnS[c + 3] + bnT[c + 3]);
            *(uint2*)(xs + i * 72 + c) = r;
        }
    }
    const float* Wp = W1 + ((size_t)l * 129 + half * 64) * 128;

    float acc[8][4] = {};
    for (int k0 = 0; k0 < 64; k0 += 16) {
        __syncthreads();
        // stage W1 chunk as bf16 pairs: 128 cols x 8 pairs
        #pragma unroll
        for (int it = 0; it < 4; ++it) {
            int idx = tid + it * 256;          // 1024
            int col = idx & 127, kk2 = idx >> 7;
            int k = k0 + 2 * kk2;
            *(unsigned*)(ws + col * 24 + 2 * kk2) =
                pack_bf16(Wp[(size_t)k * 128 + col], Wp[(size_t)(k + 1) * 128 + col]);
        }
        __syncthreads();
        unsigned a0 = *(const unsigned*)(xs + (mb + g) * 72 + k0 + 2 * tg);
        unsigned a1 = *(const unsigned*)(xs + (mb + g + 8) * 72 + k0 + 2 * tg);
        unsigned a2 = *(const unsigned*)(xs + (mb + g) * 72 + k0 + 2 * tg + 8);
        unsigned a3 = *(const unsigned*)(xs + (mb + g + 8) * 72 + k0 + 2 * tg + 8);
        #pragma unroll
        for (int nt = 0; nt < 8; ++nt) {
            int col = nb + nt * 8 + g;
            unsigned b0 = *(const unsigned*)(ws + col * 24 + 2 * tg);
            unsigned b1r = *(const unsigned*)(ws + col * 24 + 2 * tg + 8);
            mma16bf(acc[nt], a0, a1, a2, a3, b0, b1r);
        }
    }
    int row0 = n0 + mb + g, row1 = row0 + 8;
    #pragma unroll
    for (int nt = 0; nt < 8; ++nt) {
        int c0 = nb + nt * 8 + 2 * tg;
        float bb0 = (half == 0) ? b1[l * 128 + c0] : 0.0f;
        float bb1 = (half == 0) ? b1[l * 128 + c0 + 1] : 0.0f;
        if (row0 < NN) {
            g_AB[(size_t)row0 * 256 + half * 128 + c0]     = acc[nt][0] + bb0;
            g_AB[(size_t)row0 * 256 + half * 128 + c0 + 1] = acc[nt][1] + bb1;
        }
        if (row1 < NN) {
            g_AB[(size_t)row1 * 256 + half * 128 + c0]     = acc[nt][2] + bb0;
            g_AB[(size_t)row1 * 256 + half * 128 + c0 + 1] = acc[nt][3] + bb1;
        }
    }
}

// ---------------- k2: persistent, software-pipelined edge MLP (unchanged from R11) ----------------
// smem: w2b bf16[128][136]@0 | h1 bf16[2][64*136]@34816 (m overlays in bf16)
//       srcs2[2][64]@69632 | es2[2][64]@70144 | dsts3[3][64]@70656
//       w1e[128]@71424 | b2s[128]@71936 ; total 72448
#define K2_GRID 444
#define K2_SMEM 72448
__global__ void __launch_bounds__(256, 3) k2_edge(int l,
                                                  const float* __restrict__ W1,
                                                  const float* __restrict__ W2,
                                                  const float* __restrict__ b2) {
    extern __shared__ char sm8[];
    __nv_bfloat16* w2b = (__nv_bfloat16*)sm8;
    __nv_bfloat16* h1base = (__nv_bfloat16*)(sm8 + 34816);
    int* srcs2 = (int*)(sm8 + 69632);
    float* es2 = (float*)(sm8 + 70144);
    int* dsts3 = (int*)(sm8 + 70656);
    float* w1e = (float*)(sm8 + 71424);
    float* b2s = (float*)(sm8 + 71936);

    int tid = threadIdx.x, warp = tid >> 5, lane = tid & 31;
    int g = lane >> 2, tg = lane & 3;
    int mb = (warp & 3) * 16, nb = (warp >> 2) * 64;

    // stage W2 bf16 [col][k] pitch 136 (once)
    #pragma unroll
    for (int it = 0; it < 64; ++it) {
        int idx = tid + it * 256;
        int col = idx & 127, kk = idx >> 7;
        w2b[col * 136 + kk] = __float2bfloat16(W2[((size_t)l * 128 + kk) * 128 + col]);
    }
    if (tid < 128) w1e[tid] = W1[((size_t)l * 129 + 128) * 128 + tid];
    else b2s[tid - 128] = b2[l * 128 + (tid - 128)];

    const float4* AB4 = (const float4*)g_AB;
    const float4* w1e4 = (const float4*)w1e;

    auto stage = [&](int tt, int s, int ds) {
        int i4 = tt * 64 + tid;                // coalesced sorted-array reads
        srcs2[s * 64 + tid] = g_ssrc[i4];
        dsts3[ds * 64 + tid] = g_sdst[i4];
        es2[s * 64 + tid] = g_seat[i4];
    };
    auto phaseA = [&](__nv_bfloat16* H, int s, int ds) {
        int q = lane;
        int eb = warp * 8;
        const int* S = srcs2 + s * 64;
        const float* E = es2 + s * 64;
        const int* D = dsts3 + ds * 64;
        float4 w = w1e4[q];
        float4 aq = make_float4(0.f, 0.f, 0.f, 0.f);
        int prevd = -1;
        #pragma unroll
        for (int j = 0; j < 8; ++j) {
            int e = eb + j;
            int d = D[e];
            if (d != prevd) { aq = AB4[(size_t)d * 64 + q]; prevd = d; }
            float4 b = AB4[(size_t)S[e] * 64 + 32 + q];
            float ev = E[e];
            uint2 r;
            r.x = pack_bf16(spf(aq.x + b.x + ev * w.x), spf(aq.y + b.y + ev * w.y));
            r.y = pack_bf16(spf(aq.z + b.z + ev * w.z), spf(aq.w + b.w + ev * w.w));
            *(uint2*)(H + e * 136 + q * 4) = r;
        }
    };

    int t0 = blockIdx.x;
    if (t0 < NT && tid < 64) stage(t0, 0, 0);
    __syncthreads();
    if (t0 < NT) phaseA(h1base, 0, 0);
    if (t0 + K2_GRID < NT && tid < 64) stage(t0 + K2_GRID, 1, 1);
    __syncthreads();

    int i = 0;
    for (int t = t0; t < NT; t += K2_GRID, ++i) {
        int p = i & 1, q2 = 1 - p;
        int d_cur = i % 3, d_nxt = (i + 1) % 3, d_stg = (i + 2) % 3;
        __nv_bfloat16* h1p = h1base + p * (64 * 136);
        __nv_bfloat16* h1q = h1base + q2 * (64 * 136);

        // 1. phase B on h1p
        float acc[8][4] = {};
        #pragma unroll
        for (int kc = 0; kc < 128; kc += 16) {
            unsigned a0 = *(const unsigned*)(h1p + (mb + g) * 136 + kc + 2 * tg);
            unsigned a1 = *(const unsigned*)(h1p + (mb + g + 8) * 136 + kc + 2 * tg);
            unsigned a2 = *(const unsigned*)(h1p + (mb + g) * 136 + kc + 2 * tg + 8);
            unsigned a3 = *(const unsigned*)(h1p + (mb + g + 8) * 136 + kc + 2 * tg + 8);
            #pragma unroll
            for (int nt = 0; nt < 8; ++nt) {
                int col = nb + nt * 8 + g;
                unsigned b0 = *(const unsigned*)(w2b + col * 136 + kc + 2 * tg);
                unsigned b1r = *(const unsigned*)(w2b + col * 136 + kc + 2 * tg + 8);
                mma16bf(acc[nt], a0, a1, a2, a3, b0, b1r);
            }
        }

        // 2. phase A for t+G into h1q (overlaps MMA tail)
        int tn = t + K2_GRID;
        if (tn < NT) phaseA(h1q, q2, d_nxt);

        // 3. stage idx for t+2G
        int ts = t + 2 * K2_GRID;
        if (ts < NT && tid < 64) stage(ts, p, d_stg);
        __syncthreads();

        // 4. epilogue: m = spf(D + b2) -> bf16 over h1p
        #pragma unroll
        for (int nt = 0; nt < 8; ++nt) {
            int c0 = nb + nt * 8 + 2 * tg;
            unsigned u0 = pack_bf16(spf(acc[nt][0] + b2s[c0]), spf(acc[nt][1] + b2s[c0 + 1]));
            unsigned u1 = pack_bf16(spf(acc[nt][2] + b2s[c0]), spf(acc[nt][3] + b2s[c0 + 1]));
            *(unsigned*)(h1p + (mb + g) * 136 + c0) = u0;
            *(unsigned*)(h1p + (mb + g + 8) * 136 + c0) = u1;
        }
        __syncthreads();

        // 5. segmented reduction over sorted dst runs
        {
            const int* D = dsts3 + d_cur * 64;
            int c = tid & 127;
            int r0 = (tid >> 7) * 32;
            float racc = 0.0f;
            int prev = D[r0];
            #pragma unroll 4
            for (int r = r0; r < r0 + 32; ++r) {
                int d = D[r];
                if (d != prev) {
                    atomicAdd(&g_aggr[(size_t)prev * 128 + c], racc);
                    racc = 0.0f;
                    prev = d;
                }
                racc += __bfloat162float(h1p[r * 136 + c]);
            }
            atomicAdd(&g_aggr[(size_t)prev * 128 + c], racc);
        }
        __syncthreads();
    }
}

// ---------------- k3: node MLP (M=64, bf16 mma) + residual + BN stats ----------------
// dyn smem: hs f32[64*196]@0 | ws bf16[128*24]@50176 (6144) | ssum@60416 | ssq@60672
//           bnS@60928 | bnT@61184 ; total 61440
#define K3_SMEM 61440
__global__ void __launch_bounds__(256, 3) k3_node(int l, const float* __restrict__ W1,
                                                  const float* __restrict__ b1,
                                                  const float* __restrict__ W2,
                                                  const float* __restrict__ b2,
                                                  const float* __restrict__ gamma,
                                                  const float* __restrict__ beta) {
    extern __shared__ char sm3[];
    float* hs = (float*)sm3;
    __nv_bfloat16* ws = (__nv_bfloat16*)(sm3 + 50176);
    float* ssum = (float*)(sm3 + 60416);
    float* ssq = (float*)(sm3 + 60672);
    float* bnS = (float*)(sm3 + 60928);
    float* bnT = (float*)(sm3 + 61184);

    int tid = threadIdx.x, warp = tid >> 5, lane = tid & 31;
    int g = lane >> 2, tg = lane & 3;
    int mb = (warp & 3) * 16, nb = (warp >> 2) * 64;
    int n0 = blockIdx.x * 64;

    if (tid < 64) {
        ssum[tid] = 0.0f; ssq[tid] = 0.0f;
        bn_coeff(l, tid, gamma, beta, bnS[tid], bnT[tid]);
    }
    __syncthreads();

    for (int it = 0; it < 48; ++it) {
        int idx = tid + it * 256;
        int i = idx / 192, c = idx - i * 192;
        int node = n0 + i;
        float v = 0.0f;
        if (node < NN) {
            if (c < 64) v = g_x[(size_t)node * DD + c] * bnS[c] + bnT[c];
            else v = g_aggr[(size_t)node * HH + (c - 64)];
        }
        hs[i * 196 + c] = v;
    }

    // GEMM1: t = spf([x'|aggr] @ nW1 + b1), M=64, N=128, K=192, bf16 mma
    float acc[8][4] = {};
    for (int k0 = 0; k0 < 192; k0 += 16) {
        __syncthreads();
        #pragma unroll
        for (int it = 0; it < 4; ++it) {
            int idx = tid + it * 256;          // 1024
            int col = idx & 127, kk2 = idx >> 7;
            int k = k0 + 2 * kk2;
            *(unsigned*)(ws + col * 24 + 2 * kk2) =
                pack_bf16(W1[((size_t)l * 192 + k) * 128 + col],
                          W1[((size_t)l * 192 + k + 1) * 128 + col]);
        }
        __syncthreads();
        float2 v0 = *(const float2*)(hs + (mb + g) * 196 + k0 + 2 * tg);
        float2 v1 = *(const float2*)(hs + (mb + g + 8) * 196 + k0 + 2 * tg);
        float2 v2 = *(const float2*)(hs + (mb + g) * 196 + k0 + 2 * tg + 8);
        float2 v3 = *(const float2*)(hs + (mb + g + 8) * 196 + k0 + 2 * tg + 8);
        unsigned a0 = pack_bf16(v0.x, v0.y);
        unsigned a1 = pack_bf16(v1.x, v1.y);
        unsigned a2 = pack_bf16(v2.x, v2.y);
        unsigned a3 = pack_bf16(v3.x, v3.y);
        #pragma unroll
        for (int nt = 0; nt < 8; ++nt) {
            int col = nb + nt * 8 + g;
            unsigned b0 = *(const unsigned*)(ws + col * 24 + 2 * tg);
            unsigned b1r = *(const unsigned*)(ws + col * 24 + 2 * tg + 8);
            mma16bf(acc[nt], a0, a1, a2, a3, b0, b1r);
        }
    }
    __syncthreads();
    #pragma unroll
    for (int nt = 0; nt < 8; ++nt) {
        int c0 = nb + nt * 8 + 2 * tg;
        hs[(mb + g) * 196 + 64 + c0]         = spf(acc[nt][0] + b1[l * 128 + c0]);
        hs[(mb + g) * 196 + 64 + c0 + 1]     = spf(acc[nt][1] + b1[l * 128 + c0 + 1]);
        hs[(mb + g + 8) * 196 + 64 + c0]     = spf(acc[nt][2] + b1[l * 128 + c0]);
        hs[(mb + g + 8) * 196 + 64 + c0 + 1] = spf(acc[nt][3] + b1[l * 128 + c0 + 1]);
    }

    // GEMM2: y = t @ nW2 + b2 + x', M=64, N=64, K=128, bf16 mma
    int nb2 = (warp >> 2) * 32;
    float acc2[4][4] = {};
    for (int k0 = 0; k0 < 128; k0 += 16) {
        __syncthreads();
        #pragma unroll
        for (int it = 0; it < 2; ++it) {
            int idx = tid + it * 256;          // 512
            int col = idx & 63, kk2 = idx >> 6;
            int k = k0 + 2 * kk2;
            *(unsigned*)(ws + col * 24 + 2 * kk2) =
                pack_bf16(W2[((size_t)l * 128 + k) * 64 + col],
                          W2[((size_t)l * 128 + k + 1) * 64 + col]);
        }
        __syncthreads();
        float2 v0 = *(const float2*)(hs + (mb + g) * 196 + 64 + k0 + 2 * tg);
        float2 v1 = *(const float2*)(hs + (mb + g + 8) * 196 + 64 + k0 + 2 * tg);
        float2 v2 = *(const float2*)(hs + (mb + g) * 196 + 64 + k0 + 2 * tg + 8);
        float2 v3 = *(const float2*)(hs + (mb + g + 8) * 196 + 64 + k0 + 2 * tg + 8);
        unsigned a0 = pack_bf16(v0.x, v0.y);
        unsigned a1 = pack_bf16(v1.x, v1.y);
        unsigned a2 = pack_bf16(v2.x, v2.y);
        unsigned a3 = pack_bf16(v3.x, v3.y);
        #pragma unroll
        for (int nt = 0; nt < 4; ++nt) {
            int col = nb2 + nt * 8 + g;
            unsigned b0 = *(const unsigned*)(ws + col * 24 + 2 * tg);
            unsigned b1r = *(const unsigned*)(ws + col * 24 + 2 * tg + 8);
            mma16bf(acc2[nt], a0, a1, a2, a3, b0, b1r);
        }
    }

    #pragma unroll
    for (int nt = 0; nt < 4; ++nt) {
        int c0 = nb2 + nt * 8 + 2 * tg;
        float bb0 = b2[l * 64 + c0], bb1 = b2[l * 64 + c0 + 1];
        int row0 = mb + g, row1 = mb + g + 8;
        int node0 = n0 + row0, node1 = n0 + row1;
        if (node0 < NN) {
            float y0 = acc2[nt][0] + bb0 + hs[row0 * 196 + c0];
            float y1 = acc2[nt][1] + bb1 + hs[row0 * 196 + c0 + 1];
            g_x[(size_t)node0 * DD + c0] = y0;
            g_x[(size_t)node0 * DD + c0 + 1] = y1;
            atomicAdd(&ssum[c0], y0);     atomicAdd(&ssum[c0 + 1], y1);
            atomicAdd(&ssq[c0], y0 * y0); atomicAdd(&ssq[c0 + 1], y1 * y1);
        }
        if (node1 < NN) {
            float y2 = acc2[nt][2] + bb0 + hs[row1 * 196 + c0];
            float y3 = acc2[nt][3] + bb1 + hs[row1 * 196 + c0 + 1];
            g_x[(size_t)node1 * DD + c0] = y2;
            g_x[(size_t)node1 * DD + c0 + 1] = y3;
            atomicAdd(&ssum[c0], y2);     atomicAdd(&ssum[c0 + 1], y3);
            atomicAdd(&ssq[c0], y2 * y2); atomicAdd(&ssq[c0 + 1], y3 * y3);
        }
    }
    __syncthreads();
    if (tid < 64) {
        atomicAdd(&g_stats[l & 1][tid], ssum[tid]);
        atomicAdd(&g_stats[l & 1][64 + tid], ssq[tid]);
    }
}

// ---------------- k5: global mean pool (applies final BN) ----------------
__global__ void k5_pool(const int* __restrict__ batch,
                        const float* __restrict__ gamma, const float* __restrict__ beta) {
    int idx = blockIdx.x * blockDim.x + threadIdx.x;
    if (idx >= NN * DD) return;
    int i = idx >> 6, c = idx & 63;
    const float* sb = g_stats[(NL - 1) & 1];
    const float invN = 1.0f / (float)NN;
    float mu = sb[c] * invN;
    float var = sb[64 + c] * invN - mu * mu;
    float gi = gamma[(NL - 1) * 64 + c] * rsqrtf(var + 1e-5f);
    float v = g_x[idx] * gi + (beta[(NL - 1) * 64 + c] - mu * gi);
    int b = batch[i];
    atomicAdd(&g_pool[b * DD + c], v);
    if (c == 0) atomicAdd(&g_cnt[b], 1.0f);
}

// ---------------- k6: output MLP ----------------
__global__ void k6_out(const float* __restrict__ W1, const float* __restrict__ b1,
                       const float* __restrict__ W2, const float* __restrict__ b2,
                       float* __restrict__ out) {
    __shared__ float p[64];
    __shared__ float red[128];
    int g = blockIdx.x, c = threadIdx.x;
    if (c < 64) p[c] = g_pool[g * DD + c] / fmaxf(g_cnt[g], 1.0f);
    __syncthreads();
    float acc = b1[c];
    #pragma unroll
    for (int d = 0; d < 64; ++d) acc = fmaf(p[d], W1[d * 128 + c], acc);
    red[c] = softplusf(acc) * W2[c];
    __syncthreads();
    for (int s = 64; s > 0; s >>= 1) {
        if (c < s) red[c] += red[c + s];
        __syncthreads();
    }
    if (c == 0) out[g] = red[0] + b2[0];
}

// ---------------- launcher ----------------
extern "C" void kernel_launch(void* const* d_in, const int* in_sizes, int n_in,
                              void* d_out, int out_size) {
    const int*   atom_z = (const int*)  d_in[0];
    const int*   ei     = (const int*)  d_in[1];
    const float* eattr  = (const float*)d_in[2];
    const int*   batch  = (const int*)  d_in[3];
    const float* emb    = (const float*)d_in[4];
    const float* eW1    = (const float*)d_in[5];
    const float* eb1    = (const float*)d_in[6];
    const float* eW2    = (const float*)d_in[7];
    const float* eb2    = (const float*)d_in[8];
    const float* nW1    = (const float*)d_in[9];
    const float* nb1    = (const float*)d_in[10];
    const float* nW2    = (const float*)d_in[11];
    const float* nb2    = (const float*)d_in[12];
    const float* bng    = (const float*)d_in[13];
    const float* bnb    = (const float*)d_in[14];
    const float* oW1    = (const float*)d_in[15];
    const float* ob1    = (const float*)d_in[16];
    const float* oW2    = (const float*)d_in[17];
    const float* ob2    = (const float*)d_in[18];
    float* out = (float*)d_out;

    cudaFuncSetAttribute(k2_edge, cudaFuncAttributeMaxDynamicSharedMemorySize, K2_SMEM);
    cudaFuncSetAttribute(k3_node, cudaFuncAttributeMaxDynamicSharedMemorySize, K3_SMEM);

    int nsb = (NN + 1023) / 1024;

    k0_embed<<<(NN * DD + 255) / 256, 256>>>(atom_z, emb);
    k_hist<<<(NE + 255) / 256, 256>>>(ei);
    k_scan_part<<<nsb, 1024>>>();
    k1_AB<<<dim3((NN + 63) / 64, 2), 256>>>(0, eW1, eb1, bng, bnb);
    k_scan_top<<<1, 64>>>();
    k_scatter<<<(NE + 255) / 256, 256>>>(ei, eattr);

    k2_edge<<<K2_GRID, 256, K2_SMEM>>>(0, eW1, eW2, eb2);
    k3_node<<<(NN + 63) / 64, 256, K3_SMEM>>>(0, nW1, nb1, nW2, nb2, bng, bnb);
    for (int l = 1; l < NL; ++l) {
        k1_AB<<<dim3((NN + 63) / 64, 2), 256>>>(l, eW1, eb1, bng, bnb);
        k2_edge<<<K2_GRID, 256, K2_SMEM>>>(l, eW1, eW2, eb2);
        k3_node<<<(NN + 63) / 64, 256, K3_SMEM>>>(l, nW1, nb1, nW2, nb2, bng, bnb);
    }
    k5_pool<<<(NN * DD + 255) / 256, 256>>>(batch, bng, bnb);
    k6_out<<<GG, 128>>>(oW1, ob1, oW2, ob2, out);
}

// round 13
// speedup vs baseline: 1.1646x; 1.0328x over previous
#include <cuda_runtime.h>
#include <cuda_bf16.h>
#include <cuda_fp16.h>
#include <cstdint>
#include <math.h>

#define NN 50000
#define NE 800000
#define DD 64
#define HH 128
#define GG 128
#define NL 3
#define NT (NE / 64)

// ---------------- device scratch ----------------
__device__ float  g_x[NN * DD];             // pre-BN node features
__device__ __half g_AB[(size_t)NN * 256];   // [A=x'@W1a+b1 | B=x'@W1b] (fp16)
__device__ float  g_aggr[(size_t)NN * HH];
__device__ float  g_stats[2][128];
__device__ float  g_pool[GG * DD];
__device__ float  g_cnt[GG];
__device__ int    g_hist[NN];
__device__ int    g_bsum[64];
__device__ int    g_ssrc[NE];               // dst-sorted edge arrays
__device__ int    g_sdst[NE];
__device__ float  g_seat[NE];

__device__ __forceinline__ float softplusf(float x) {
    return fmaxf(x, 0.0f) + __logf(1.0f + __expf(-fabsf(x)));
}
// fast softplus: 1 MUFU + poly for ln(1+u), u=e^-|x| in [0,1]
__device__ __forceinline__ float spf(float x) {
    float u = __expf(-fabsf(x));
    float p = fmaf(0.0834f, u, -0.2474f);
    p = fmaf(p, u, 0.4427f);
    float l = 0.6931472f * u * fmaf(1.0f - u, p, 1.0f);
    return fmaxf(x, 0.0f) + l;
}
__device__ __forceinline__ unsigned pack_bf16(float lo, float hi) {
    unsigned r;
    asm("cvt.rn.bf16x2.f32 %0, %1, %2;" : "=r"(r) : "f"(hi), "f"(lo));
    return r;
}
__device__ __forceinline__ void mma16bf(float* c, unsigned a0, unsigned a1,
                                        unsigned a2, unsigned a3,
                                        unsigned b0, unsigned b1) {
    asm volatile(
        "mma.sync.aligned.m16n8k16.row.col.f32.bf16.bf16.f32 "
        "{%0,%1,%2,%3}, {%4,%5,%6,%7}, {%8,%9}, {%0,%1,%2,%3};"
        : "+f"(c[0]), "+f"(c[1]), "+f"(c[2]), "+f"(c[3])
        : "r"(a0), "r"(a1), "r"(a2), "r"(a3), "r"(b0), "r"(b1));
}
__device__ __forceinline__ void bn_coeff(int l, int c, const float* gamma,
                                         const float* beta, float& S, float& T) {
    if (l == 0) { S = 1.0f; T = 0.0f; return; }
    const float* sb = g_stats[(l - 1) & 1];
    const float invN = 1.0f / (float)NN;
    float mu = sb[c] * invN;
    float var = sb[64 + c] * invN - mu * mu;
    float gi = gamma[(l - 1) * 64 + c] * rsqrtf(var + 1e-5f);
    S = gi;
    T = beta[(l - 1) * 64 + c] - mu * gi;
}

// ---------------- k0: embedding gather (+ zero g_hist, pool) ----------------
__global__ void k0_embed(const int* __restrict__ az, const float* __restrict__ emb) {
    int idx = blockIdx.x * blockDim.x + threadIdx.x;
    if (idx < NN) g_hist[idx] = 0;
    if (idx < GG * DD) g_pool[idx] = 0.0f;
    if (idx < GG) g_cnt[idx] = 0.0f;
    if (idx >= NN * DD) return;
    int i = idx >> 6, c = idx & 63;
    g_x[idx] = emb[az[i] * DD + c];
}

// ---------------- counting sort (materializes sorted arrays) ----------------
__global__ void k_hist(const int* __restrict__ ei) {
    int e = blockIdx.x * blockDim.x + threadIdx.x;
    if (e < NE) atomicAdd(&g_hist[ei[NE + e]], 1);
}
__global__ void k_scan_part() {
    __shared__ int wsum[32];
    int tid = threadIdx.x, lane = tid & 31, wid = tid >> 5;
    int i = blockIdx.x * 1024 + tid;
    int v = (i < NN) ? g_hist[i] : 0;
    int x = v;
    #pragma unroll
    for (int off = 1; off < 32; off <<= 1) {
        int y = __shfl_up_sync(0xffffffffu, x, off);
        if (lane >= off) x += y;
    }
    if (lane == 31) wsum[wid] = x;
    __syncthreads();
    if (wid == 0) {
        int s = wsum[lane];
        #pragma unroll
        for (int off = 1; off < 32; off <<= 1) {
            int y = __shfl_up_sync(0xffffffffu, s, off);
            if (lane >= off) s += y;
        }
        wsum[lane] = s;
    }
    __syncthreads();
    int woff = (wid > 0) ? wsum[wid - 1] : 0;
    if (i < NN) g_hist[i] = x - v + woff;   // block-local exclusive
    if (tid == 1023) g_bsum[blockIdx.x] = x + woff;
}
__global__ void k_scan_top() {
    __shared__ int s[64];
    int tid = threadIdx.x;
    int nb = (NN + 1023) / 1024;
    int v = (tid < nb) ? g_bsum[tid] : 0;
    s[tid] = v;
    __syncthreads();
    for (int off = 1; off < 64; off <<= 1) {
        int t = (tid >= off) ? s[tid - off] : 0;
        __syncthreads();
        s[tid] += t;
        __syncthreads();
    }
    if (tid < nb) g_bsum[tid] = s[tid] - v;
}
__global__ void k_scatter(const int* __restrict__ ei, const float* __restrict__ eattr) {
    int e = blockIdx.x * blockDim.x + threadIdx.x;
    if (e >= NE) return;
    int d = ei[NE + e];
    int pos = atomicAdd(&g_hist[d], 1) + g_bsum[d >> 10];
    g_ssrc[pos] = ei[e];
    g_sdst[pos] = d;
    g_seat[pos] = eattr[e];
}

// ---------------- k1: AB = x' @ [W1a | W1b] (per-half, bf16 mma); zeroes aggr + stats ----------------
__global__ void __launch_bounds__(256) k1_AB(int l, const float* __restrict__ W1,
                                             const float* __restrict__ b1,
                                             const float* __restrict__ gamma,
                                             const float* __restrict__ beta) {
    __shared__ __nv_bfloat16 xs[64 * 72];  // bf16, BN applied; pitch 72
    __shared__ __nv_bfloat16 ws[128 * 24]; // W1 chunk [col][k], pitch 24
    __shared__ float bnS[64], bnT[64];
    int tid = threadIdx.x, warp = tid >> 5, lane = tid & 31;
    int g = lane >> 2, tg = lane & 3;
    int n0 = blockIdx.x * 64;
    int half = blockIdx.y;
    int mb = (warp & 3) * 16, nb = (warp >> 2) * 64;

    if (tid < 64) bn_coeff(l, tid, gamma, beta, bnS[tid], bnT[tid]);
    if (blockIdx.x == 0 && half == 0 && tid < 128) g_stats[l & 1][tid] = 0.0f;
    // zero this block's slice of g_aggr (nodes n0..n0+63, cols half*64..+63)
    {
        float4 z = make_float4(0.f, 0.f, 0.f, 0.f);
        float4* Az = (float4*)g_aggr;
        #pragma unroll
        for (int it = 0; it < 4; ++it) {
            int idx = tid + it * 256;          // 1024
            int i = idx >> 4, qc = idx & 15;
            int node = n0 + i;
            if (node < NN) Az[(size_t)node * 32 + half * 16 + qc] = z;
        }
    }
    __syncthreads();   // bnS ready

    // stage xs as bf16 (float4 loads, BN applied)
    {
        const float4* X4 = (const float4*)g_x;
        #pragma unroll
        for (int it = 0; it < 4; ++it) {
            int idx = tid + it * 256;          // 1024
            int i = idx >> 4, q = idx & 15;
            int node = n0 + i;
            float4 v = make_float4(0.f, 0.f, 0.f, 0.f);
            if (node < NN) v = X4[(size_t)node * 16 + q];
            int c = q * 4;
            uint2 r;
            r.x = pack_bf16(v.x * bnS[c] + bnT[c],     v.y * bnS[c + 1] + bnT[c + 1]);
            r.y = pack_bf16(v.z * bnS[c + 2] + bnT[c + 2], v.w * bnS[c + 3] + bnT[c + 3]);
            *(uint2*)(xs + i * 72 + c) = r;
        }
    }
    const float* Wp = W1 + ((size_t)l * 129 + half * 64) * 128;

    float acc[8][4] = {};
    for (int k0 = 0; k0 < 64; k0 += 16) {
        __syncthreads();
        // stage W1 chunk as bf16 pairs: 128 cols x 8 pairs
        #pragma unroll
        for (int it = 0; it < 4; ++it) {
            int idx = tid + it * 256;          // 1024
            int col = idx & 127, kk2 = idx >> 7;
            int k = k0 + 2 * kk2;
            *(unsigned*)(ws + col * 24 + 2 * kk2) =
                pack_bf16(Wp[(size_t)k * 128 + col], Wp[(size_t)(k + 1) * 128 + col]);
        }
        __syncthreads();
        unsigned a0 = *(const unsigned*)(xs + (mb + g) * 72 + k0 + 2 * tg);
        unsigned a1 = *(const unsigned*)(xs + (mb + g + 8) * 72 + k0 + 2 * tg);
        unsigned a2 = *(const unsigned*)(xs + (mb + g) * 72 + k0 + 2 * tg + 8);
        unsigned a3 = *(const unsigned*)(xs + (mb + g + 8) * 72 + k0 + 2 * tg + 8);
        #pragma unroll
        for (int nt = 0; nt < 8; ++nt) {
            int col = nb + nt * 8 + g;
            unsigned b0 = *(const unsigned*)(ws + col * 24 + 2 * tg);
            unsigned b1r = *(const unsigned*)(ws + col * 24 + 2 * tg + 8);
            mma16bf(acc[nt], a0, a1, a2, a3, b0, b1r);
        }
    }
    int row0 = n0 + mb + g, row1 = row0 + 8;
    #pragma unroll
    for (int nt = 0; nt < 8; ++nt) {
        int c0 = nb + nt * 8 + 2 * tg;
        float bb0 = (half == 0) ? b1[l * 128 + c0] : 0.0f;
        float bb1 = (half == 0) ? b1[l * 128 + c0 + 1] : 0.0f;
        if (row0 < NN) {
            *(__half2*)(&g_AB[(size_t)row0 * 256 + half * 128 + c0]) =
                __floats2half2_rn(acc[nt][0] + bb0, acc[nt][1] + bb1);
        }
        if (row1 < NN) {
            *(__half2*)(&g_AB[(size_t)row1 * 256 + half * 128 + c0]) =
                __floats2half2_rn(acc[nt][2] + bb0, acc[nt][3] + bb1);
        }
    }
}

// ---------------- k2: persistent, software-pipelined edge MLP (fp16 AB gathers) ----------------
// smem: w2b bf16[128][136]@0 | h1 bf16[2][64*136]@34816 (m overlays in bf16)
//       srcs2[2][64]@69632 | es2[2][64]@70144 | dsts3[3][64]@70656
//       w1e[128]@71424 | b2s[128]@71936 ; total 72448
#define K2_GRID 444
#define K2_SMEM 72448
__global__ void __launch_bounds__(256, 3) k2_edge(int l,
                                                  const float* __restrict__ W1,
                                                  const float* __restrict__ W2,
                                                  const float* __restrict__ b2) {
    extern __shared__ char sm8[];
    __nv_bfloat16* w2b = (__nv_bfloat16*)sm8;
    __nv_bfloat16* h1base = (__nv_bfloat16*)(sm8 + 34816);
    int* srcs2 = (int*)(sm8 + 69632);
    float* es2 = (float*)(sm8 + 70144);
    int* dsts3 = (int*)(sm8 + 70656);
    float* w1e = (float*)(sm8 + 71424);
    float* b2s = (float*)(sm8 + 71936);

    int tid = threadIdx.x, warp = tid >> 5, lane = tid & 31;
    int g = lane >> 2, tg = lane & 3;
    int mb = (warp & 3) * 16, nb = (warp >> 2) * 64;

    // stage W2 bf16 [col][k] pitch 136 (once)
    #pragma unroll
    for (int it = 0; it < 64; ++it) {
        int idx = tid + it * 256;
        int col = idx & 127, kk = idx >> 7;
        w2b[col * 136 + kk] = __float2bfloat16(W2[((size_t)l * 128 + kk) * 128 + col]);
    }
    if (tid < 128) w1e[tid] = W1[((size_t)l * 129 + 128) * 128 + tid];
    else b2s[tid - 128] = b2[l * 128 + (tid - 128)];

    const uint2* ABh = (const uint2*)g_AB;   // row = 64 uint2 (256 halves)
    const float4* w1e4 = (const float4*)w1e;

    auto stage = [&](int tt, int s, int ds) {
        int i4 = tt * 64 + tid;                // coalesced sorted-array reads
        srcs2[s * 64 + tid] = g_ssrc[i4];
        dsts3[ds * 64 + tid] = g_sdst[i4];
        es2[s * 64 + tid] = g_seat[i4];
    };
    auto phaseA = [&](__nv_bfloat16* H, int s, int ds) {
        int q = lane;
        int eb = warp * 8;
        const int* S = srcs2 + s * 64;
        const float* E = es2 + s * 64;
        const int* D = dsts3 + ds * 64;
        float4 w = w1e4[q];
        float4 aq = make_float4(0.f, 0.f, 0.f, 0.f);
        int prevd = -1;
        #pragma unroll
        for (int j = 0; j < 8; ++j) {
            int e = eb + j;
            int d = D[e];
            if (d != prevd) {
                uint2 ar = ABh[(size_t)d * 64 + q];
                float2 a01 = __half22float2(*(__half2*)&ar.x);
                float2 a23 = __half22float2(*(__half2*)&ar.y);
                aq = make_float4(a01.x, a01.y, a23.x, a23.y);
                prevd = d;
            }
            uint2 br = ABh[(size_t)S[e] * 64 + 32 + q];
            float2 b01 = __half22float2(*(__half2*)&br.x);
            float2 b23 = __half22float2(*(__half2*)&br.y);
            float ev = E[e];
            uint2 r;
            r.x = pack_bf16(spf(aq.x + b01.x + ev * w.x), spf(aq.y + b01.y + ev * w.y));
            r.y = pack_bf16(spf(aq.z + b23.x + ev * w.z), spf(aq.w + b23.y + ev * w.w));
            *(uint2*)(H + e * 136 + q * 4) = r;
        }
    };

    int t0 = blockIdx.x;
    if (t0 < NT && tid < 64) stage(t0, 0, 0);
    __syncthreads();
    if (t0 < NT) phaseA(h1base, 0, 0);
    if (t0 + K2_GRID < NT && tid < 64) stage(t0 + K2_GRID, 1, 1);
    __syncthreads();

    int i = 0;
    for (int t = t0; t < NT; t += K2_GRID, ++i) {
        int p = i & 1, q2 = 1 - p;
        int d_cur = i % 3, d_nxt = (i + 1) % 3, d_stg = (i + 2) % 3;
        __nv_bfloat16* h1p = h1base + p * (64 * 136);
        __nv_bfloat16* h1q = h1base + q2 * (64 * 136);

        // 1. phase B on h1p
        float acc[8][4] = {};
        #pragma unroll
        for (int kc = 0; kc < 128; kc += 16) {
            unsigned a0 = *(const unsigned*)(h1p + (mb + g) * 136 + kc + 2 * tg);
            unsigned a1 = *(const unsigned*)(h1p + (mb + g + 8) * 136 + kc + 2 * tg);
            unsigned a2 = *(const unsigned*)(h1p + (mb + g) * 136 + kc + 2 * tg + 8);
            unsigned a3 = *(const unsigned*)(h1p + (mb + g + 8) * 136 + kc + 2 * tg + 8);
            #pragma unroll
            for (int nt = 0; nt < 8; ++nt) {
                int col = nb + nt * 8 + g;
                unsigned b0 = *(const unsigned*)(w2b + col * 136 + kc + 2 * tg);
                unsigned b1r = *(const unsigned*)(w2b + col * 136 + kc + 2 * tg + 8);
                mma16bf(acc[nt], a0, a1, a2, a3, b0, b1r);
            }
        }

        // 2. phase A for t+G into h1q (overlaps MMA tail)
        int tn = t + K2_GRID;
        if (tn < NT) phaseA(h1q, q2, d_nxt);

        // 3. stage idx for t+2G
        int ts = t + 2 * K2_GRID;
        if (ts < NT && tid < 64) stage(ts, p, d_stg);
        __syncthreads();

        // 4. epilogue: m = spf(D + b2) -> bf16 over h1p
        #pragma unroll
        for (int nt = 0; nt < 8; ++nt) {
            int c0 = nb + nt * 8 + 2 * tg;
            unsigned u0 = pack_bf16(spf(acc[nt][0] + b2s[c0]), spf(acc[nt][1] + b2s[c0 + 1]));
            unsigned u1 = pack_bf16(spf(acc[nt][2] + b2s[c0]), spf(acc[nt][3] + b2s[c0 + 1]));
            *(unsigned*)(h1p + (mb + g) * 136 + c0) = u0;
            *(unsigned*)(h1p + (mb + g + 8) * 136 + c0) = u1;
        }
        __syncthreads();

        // 5. segmented reduction over sorted dst runs
        {
            const int* D = dsts3 + d_cur * 64;
            int c = tid & 127;
            int r0 = (tid >> 7) * 32;
            float racc = 0.0f;
            int prev = D[r0];
            #pragma unroll 4
            for (int r = r0; r < r0 + 32; ++r) {
                int d = D[r];
                if (d != prev) {
                    atomicAdd(&g_aggr[(size_t)prev * 128 + c], racc);
                    racc = 0.0f;
                    prev = d;
                }
                racc += __bfloat162float(h1p[r * 136 + c]);
            }
            atomicAdd(&g_aggr[(size_t)prev * 128 + c], racc);
        }
        __syncthreads();
    }
}

// ---------------- k3: node MLP (M=64, bf16 mma) + residual + BN stats ----------------
// dyn smem: hs f32[64*196]@0 | ws bf16[128*24]@50176 (6144) | ssum@60416 | ssq@60672
//           bnS@60928 | bnT@61184 ; total 61440
#define K3_SMEM 61440
__global__ void __launch_bounds__(256, 3) k3_node(int l, const float* __restrict__ W1,
                                                  const float* __restrict__ b1,
                                                  const float* __restrict__ W2,
                                                  const float* __restrict__ b2,
                                                  const float* __restrict__ gamma,
                                                  const float* __restrict__ beta) {
    extern __shared__ char sm3[];
    float* hs = (float*)sm3;
    __nv_bfloat16* ws = (__nv_bfloat16*)(sm3 + 50176);
    float* ssum = (float*)(sm3 + 60416);
    float* ssq = (float*)(sm3 + 60672);
    float* bnS = (float*)(sm3 + 60928);
    float* bnT = (float*)(sm3 + 61184);

    int tid = threadIdx.x, warp = tid >> 5, lane = tid & 31;
    int g = lane >> 2, tg = lane & 3;
    int mb = (warp & 3) * 16, nb = (warp >> 2) * 64;
    int n0 = blockIdx.x * 64;

    if (tid < 64) {
        ssum[tid] = 0.0f; ssq[tid] = 0.0f;
        bn_coeff(l, tid, gamma, beta, bnS[tid], bnT[tid]);
    }
    __syncthreads();

    for (int it = 0; it < 48; ++it) {
        int idx = tid + it * 256;
        int i = idx / 192, c = idx - i * 192;
        int node = n0 + i;
        float v = 0.0f;
        if (node < NN) {
            if (c < 64) v = g_x[(size_t)node * DD + c] * bnS[c] + bnT[c];
            else v = g_aggr[(size_t)node * HH + (c - 64)];
        }
        hs[i * 196 + c] = v;
    }

    // GEMM1: t = spf([x'|aggr] @ nW1 + b1), M=64, N=128, K=192, bf16 mma
    float acc[8][4] = {};
    for (int k0 = 0; k0 < 192; k0 += 16) {
        __syncthreads();
        #pragma unroll
        for (int it = 0; it < 4; ++it) {
            int idx = tid + it * 256;          // 1024
            int col = idx & 127, kk2 = idx >> 7;
            int k = k0 + 2 * kk2;
            *(unsigned*)(ws + col * 24 + 2 * kk2) =
                pack_bf16(W1[((size_t)l * 192 + k) * 128 + col],
                          W1[((size_t)l * 192 + k + 1) * 128 + col]);
        }
        __syncthreads();
        float2 v0 = *(const float2*)(hs + (mb + g) * 196 + k0 + 2 * tg);
        float2 v1 = *(const float2*)(hs + (mb + g + 8) * 196 + k0 + 2 * tg);
        float2 v2 = *(const float2*)(hs + (mb + g) * 196 + k0 + 2 * tg + 8);
        float2 v3 = *(const float2*)(hs + (mb + g + 8) * 196 + k0 + 2 * tg + 8);
        unsigned a0 = pack_bf16(v0.x, v0.y);
        unsigned a1 = pack_bf16(v1.x, v1.y);
        unsigned a2 = pack_bf16(v2.x, v2.y);
        unsigned a3 = pack_bf16(v3.x, v3.y);
        #pragma unroll
        for (int nt = 0; nt < 8; ++nt) {
            int col = nb + nt * 8 + g;
            unsigned b0 = *(const unsigned*)(ws + col * 24 + 2 * tg);
            unsigned b1r = *(const unsigned*)(ws + col * 24 + 2 * tg + 8);
            mma16bf(acc[nt], a0, a1, a2, a3, b0, b1r);
        }
    }
    __syncthreads();
    #pragma unroll
    for (int nt = 0; nt < 8; ++nt) {
        int c0 = nb + nt * 8 + 2 * tg;
        hs[(mb + g) * 196 + 64 + c0]         = spf(acc[nt][0] + b1[l * 128 + c0]);
        hs[(mb + g) * 196 + 64 + c0 + 1]     = spf(acc[nt][1] + b1[l * 128 + c0 + 1]);
        hs[(mb + g + 8) * 196 + 64 + c0]     = spf(acc[nt][2] + b1[l * 128 + c0]);
        hs[(mb + g + 8) * 196 + 64 + c0 + 1] = spf(acc[nt][3] + b1[l * 128 + c0 + 1]);
    }

    // GEMM2: y = t @ nW2 + b2 + x', M=64, N=64, K=128, bf16 mma
    int nb2 = (warp >> 2) * 32;
    float acc2[4][4] = {};
    for (int k0 = 0; k0 < 128; k0 += 16) {
        __syncthreads();
        #pragma unroll
        for (int it = 0; it < 2; ++it) {
            int idx = tid + it * 256;          // 512
            int col = idx & 63, kk2 = idx >> 6;
            int k = k0 + 2 * kk2;
            *(unsigned*)(ws + col * 24 + 2 * kk2) =
                pack_bf16(W2[((size_t)l * 128 + k) * 64 + col],
                          W2[((size_t)l * 128 + k + 1) * 64 + col]);
        }
        __syncthreads();
        float2 v0 = *(const float2*)(hs + (mb + g) * 196 + 64 + k0 + 2 * tg);
        float2 v1 = *(const float2*)(hs + (mb + g + 8) * 196 + 64 + k0 + 2 * tg);
        float2 v2 = *(const float2*)(hs + (mb + g) * 196 + 64 + k0 + 2 * tg + 8);
        float2 v3 = *(const float2*)(hs + (mb + g + 8) * 196 + 64 + k0 + 2 * tg + 8);
        unsigned a0 = pack_bf16(v0.x, v0.y);
        unsigned a1 = pack_bf16(v1.x, v1.y);
        unsigned a2 = pack_bf16(v2.x, v2.y);
        unsigned a3 = pack_bf16(v3.x, v3.y);
        #pragma unroll
        for (int nt = 0; nt < 4; ++nt) {
            int col = nb2 + nt * 8 + g;
            unsigned b0 = *(const unsigned*)(ws + col * 24 + 2 * tg);
            unsigned b1r = *(const unsigned*)(ws + col * 24 + 2 * tg + 8);
            mma16bf(acc2[nt], a0, a1, a2, a3, b0, b1r);
        }
    }

    #pragma unroll
    for (int nt = 0; nt < 4; ++nt) {
        int c0 = nb2 + nt * 8 + 2 * tg;
        float bb0 = b2[l * 64 + c0], bb1 = b2[l * 64 + c0 + 1];
        int row0 = mb + g, row1 = mb + g + 8;
        int node0 = n0 + row0, node1 = n0 + row1;
        if (node0 < NN) {
            float y0 = acc2[nt][0] + bb0 + hs[row0 * 196 + c0];
            float y1 = acc2[nt][1] + bb1 + hs[row0 * 196 + c0 + 1];
            g_x[(size_t)node0 * DD + c0] = y0;
            g_x[(size_t)node0 * DD + c0 + 1] = y1;
            atomicAdd(&ssum[c0], y0);     atomicAdd(&ssum[c0 + 1], y1);
            atomicAdd(&ssq[c0], y0 * y0); atomicAdd(&ssq[c0 + 1], y1 * y1);
        }
        if (node1 < NN) {
            float y2 = acc2[nt][2] + bb0 + hs[row1 * 196 + c0];
            float y3 = acc2[nt][3] + bb1 + hs[row1 * 196 + c0 + 1];
            g_x[(size_t)node1 * DD + c0] = y2;
            g_x[(size_t)node1 * DD + c0 + 1] = y3;
            atomicAdd(&ssum[c0], y2);     atomicAdd(&ssum[c0 + 1], y3);
            atomicAdd(&ssq[c0], y2 * y2); atomicAdd(&ssq[c0 + 1], y3 * y3);
        }
    }
    __syncthreads();
    if (tid < 64) {
        atomicAdd(&g_stats[l & 1][tid], ssum[tid]);
        atomicAdd(&g_stats[l & 1][64 + tid], ssq[tid]);
    }
}

// ---------------- k5: global mean pool (applies final BN) ----------------
__global__ void k5_pool(const int* __restrict__ batch,
                        const float* __restrict__ gamma, const float* __restrict__ beta) {
    int idx = blockIdx.x * blockDim.x + threadIdx.x;
    if (idx >= NN * DD) return;
    int i = idx >> 6, c = idx & 63;
    const float* sb = g_stats[(NL - 1) & 1];
    const float invN = 1.0f / (float)NN;
    float mu = sb[c] * invN;
    float var = sb[64 + c] * invN - mu * mu;
    float gi = gamma[(NL - 1) * 64 + c] * rsqrtf(var + 1e-5f);
    float v = g_x[idx] * gi + (beta[(NL - 1) * 64 + c] - mu * gi);
    int b = batch[i];
    atomicAdd(&g_pool[b * DD + c], v);
    if (c == 0) atomicAdd(&g_cnt[b], 1.0f);
}

// ---------------- k6: output MLP ----------------
__global__ void k6_out(const float* __restrict__ W1, const float* __restrict__ b1,
                       const float* __restrict__ W2, const float* __restrict__ b2,
                       float* __restrict__ out) {
    __shared__ float p[64];
    __shared__ float red[128];
    int g = blockIdx.x, c = threadIdx.x;
    if (c < 64) p[c] = g_pool[g * DD + c] / fmaxf(g_cnt[g], 1.0f);
    __syncthreads();
    float acc = b1[c];
    #pragma unroll
    for (int d = 0; d < 64; ++d) acc = fmaf(p[d], W1[d * 128 + c], acc);
    red[c] = softplusf(acc) * W2[c];
    __syncthreads();
    for (int s = 64; s > 0; s >>= 1) {
        if (c < s) red[c] += red[c + s];
        __syncthreads();
    }
    if (c == 0) out[g] = red[0] + b2[0];
}

// ---------------- launcher ----------------
extern "C" void kernel_launch(void* const* d_in, const int* in_sizes, int n_in,
                              void* d_out, int out_size) {
    const int*   atom_z = (const int*)  d_in[0];
    const int*   ei     = (const int*)  d_in[1];
    const float* eattr  = (const float*)d_in[2];
    const int*   batch  = (const int*)  d_in[3];
    const float* emb    = (const float*)d_in[4];
    const float* eW1    = (const float*)d_in[5];
    const float* eb1    = (const float*)d_in[6];
    const float* eW2    = (const float*)d_in[7];
    const float* eb2    = (const float*)d_in[8];
    const float* nW1    = (const float*)d_in[9];
    const float* nb1    = (const float*)d_in[10];
    const float* nW2    = (const float*)d_in[11];
    const float* nb2    = (const float*)d_in[12];
    const float* bng    = (const float*)d_in[13];
    const float* bnb    = (const float*)d_in[14];
    const float* oW1    = (const float*)d_in[15];
    const float* ob1    = (const float*)d_in[16];
    const float* oW2    = (const float*)d_in[17];
    const float* ob2    = (const float*)d_in[18];
    float* out = (float*)d_out;

    cudaFuncSetAttribute(k2_edge, cudaFuncAttributeMaxDynamicSharedMemorySize, K2_SMEM);
    cudaFuncSetAttribute(k3_node, cudaFuncAttributeMaxDynamicSharedMemorySize, K3_SMEM);

    int nsb = (NN + 1023) / 1024;

    k0_embed<<<(NN * DD + 255) / 256, 256>>>(atom_z, emb);
    k_hist<<<(NE + 255) / 256, 256>>>(ei);
    k_scan_part<<<nsb, 1024>>>();
    k1_AB<<<dim3((NN + 63) / 64, 2), 256>>>(0, eW1, eb1, bng, bnb);
    k_scan_top<<<1, 64>>>();
    k_scatter<<<(NE + 255) / 256, 256>>>(ei, eattr);

    k2_edge<<<K2_GRID, 256, K2_SMEM>>>(0, eW1, eW2, eb2);
    k3_node<<<(NN + 63) / 64, 256, K3_SMEM>>>(0, nW1, nb1, nW2, nb2, bng, bnb);
    for (int l = 1; l < NL; ++l) {
        k1_AB<<<dim3((NN + 63) / 64, 2), 256>>>(l, eW1, eb1, bng, bnb);
        k2_edge<<<K2_GRID, 256, K2_SMEM>>>(l, eW1, eW2, eb2);
        k3_node<<<(NN + 63) / 64, 256, K3_SMEM>>>(l, nW1, nb1, nW2, nb2, bng, bnb);
    }
    k5_pool<<<(NN * DD + 255) / 256, 256>>>(batch, bng, bnb);
    k6_out<<<GG, 128>>>(oW1, ob1, oW2, ob2, out);
}

// round 14
// speedup vs baseline: 1.2209x; 1.0484x over previous
#include <cuda_runtime.h>
#include <cuda_bf16.h>
#include <cuda_fp16.h>
#include <cstdint>
#include <math.h>

#define NN 50000
#define NE 800000
#define DD 64
#define HH 128
#define GG 128
#define NL 3
#define NT (NE / 64)

// ---------------- device scratch ----------------
__device__ float  g_x[NN * DD];             // pre-BN node features
__device__ __half g_AB[(size_t)NN * 256];   // [A=x'@W1a+b1 | B=x'@W1b] (fp16)
__device__ __half g_aggr[(size_t)NN * HH];  // fp16 message sums
__device__ float  g_stats[2][128];
__device__ float  g_pool[GG * DD];
__device__ float  g_cnt[GG];
__device__ int    g_hist[NN];
__device__ int    g_bsum[64];
__device__ int    g_ssrc[NE];               // dst-sorted edge arrays
__device__ int    g_sdst[NE];
__device__ float  g_seat[NE];

__device__ __forceinline__ float softplusf(float x) {
    return fmaxf(x, 0.0f) + __logf(1.0f + __expf(-fabsf(x)));
}
// fast softplus: 1 MUFU + poly for ln(1+u), u=e^-|x| in [0,1]
__device__ __forceinline__ float spf(float x) {
    float u = __expf(-fabsf(x));
    float p = fmaf(0.0834f, u, -0.2474f);
    p = fmaf(p, u, 0.4427f);
    float l = 0.6931472f * u * fmaf(1.0f - u, p, 1.0f);
    return fmaxf(x, 0.0f) + l;
}
__device__ __forceinline__ unsigned pack_bf16(float lo, float hi) {
    unsigned r;
    asm("cvt.rn.bf16x2.f32 %0, %1, %2;" : "=r"(r) : "f"(hi), "f"(lo));
    return r;
}
__device__ __forceinline__ void mma16bf(float* c, unsigned a0, unsigned a1,
                                        unsigned a2, unsigned a3,
                                        unsigned b0, unsigned b1) {
    asm volatile(
        "mma.sync.aligned.m16n8k16.row.col.f32.bf16.bf16.f32 "
        "{%0,%1,%2,%3}, {%4,%5,%6,%7}, {%8,%9}, {%0,%1,%2,%3};"
        : "+f"(c[0]), "+f"(c[1]), "+f"(c[2]), "+f"(c[3])
        : "r"(a0), "r"(a1), "r"(a2), "r"(a3), "r"(b0), "r"(b1));
}
__device__ __forceinline__ void bn_coeff(int l, int c, const float* gamma,
                                         const float* beta, float& S, float& T) {
    if (l == 0) { S = 1.0f; T = 0.0f; return; }
    const float* sb = g_stats[(l - 1) & 1];
    const float invN = 1.0f / (float)NN;
    float mu = sb[c] * invN;
    float var = sb[64 + c] * invN - mu * mu;
    float gi = gamma[(l - 1) * 64 + c] * rsqrtf(var + 1e-5f);
    S = gi;
    T = beta[(l - 1) * 64 + c] - mu * gi;
}

// ---------------- k0: embedding gather (+ zero g_hist, pool) ----------------
__global__ void k0_embed(const int* __restrict__ az, const float* __restrict__ emb) {
    int idx = blockIdx.x * blockDim.x + threadIdx.x;
    if (idx < NN) g_hist[idx] = 0;
    if (idx < GG * DD) g_pool[idx] = 0.0f;
    if (idx < GG) g_cnt[idx] = 0.0f;
    if (idx >= NN * DD) return;
    int i = idx >> 6, c = idx & 63;
    g_x[idx] = emb[az[i] * DD + c];
}

// ---------------- counting sort (materializes sorted arrays) ----------------
__global__ void k_hist(const int* __restrict__ ei) {
    int e = blockIdx.x * blockDim.x + threadIdx.x;
    if (e < NE) atomicAdd(&g_hist[ei[NE + e]], 1);
}
__global__ void k_scan_part() {
    __shared__ int wsum[32];
    int tid = threadIdx.x, lane = tid & 31, wid = tid >> 5;
    int i = blockIdx.x * 1024 + tid;
    int v = (i < NN) ? g_hist[i] : 0;
    int x = v;
    #pragma unroll
    for (int off = 1; off < 32; off <<= 1) {
        int y = __shfl_up_sync(0xffffffffu, x, off);
        if (lane >= off) x += y;
    }
    if (lane == 31) wsum[wid] = x;
    __syncthreads();
    if (wid == 0) {
        int s = wsum[lane];
        #pragma unroll
        for (int off = 1; off < 32; off <<= 1) {
            int y = __shfl_up_sync(0xffffffffu, s, off);
            if (lane >= off) s += y;
        }
        wsum[lane] = s;
    }
    __syncthreads();
    int woff = (wid > 0) ? wsum[wid - 1] : 0;
    if (i < NN) g_hist[i] = x - v + woff;   // block-local exclusive
    if (tid == 1023) g_bsum[blockIdx.x] = x + woff;
}
__global__ void k_scan_top() {
    __shared__ int s[64];
    int tid = threadIdx.x;
    int nb = (NN + 1023) / 1024;
    int v = (tid < nb) ? g_bsum[tid] : 0;
    s[tid] = v;
    __syncthreads();
    for (int off = 1; off < 64; off <<= 1) {
        int t = (tid >= off) ? s[tid - off] : 0;
        __syncthreads();
        s[tid] += t;
        __syncthreads();
    }
    if (tid < nb) g_bsum[tid] = s[tid] - v;
}
__global__ void k_scatter(const int* __restrict__ ei, const float* __restrict__ eattr) {
    int e = blockIdx.x * blockDim.x + threadIdx.x;
    if (e >= NE) return;
    int d = ei[NE + e];
    int pos = atomicAdd(&g_hist[d], 1) + g_bsum[d >> 10];
    g_ssrc[pos] = ei[e];
    g_sdst[pos] = d;
    g_seat[pos] = eattr[e];
}

// ---------------- k1: AB = x' @ [W1a | W1b] (per-half, bf16 mma); zeroes aggr + stats ----------------
__global__ void __launch_bounds__(256) k1_AB(int l, const float* __restrict__ W1,
                                             const float* __restrict__ b1,
                                             const float* __restrict__ gamma,
                                             const float* __restrict__ beta) {
    __shared__ __nv_bfloat16 xs[64 * 72];  // bf16, BN applied; pitch 72
    __shared__ __nv_bfloat16 ws[128 * 24]; // W1 chunk [col][k], pitch 24
    __shared__ float bnS[64], bnT[64];
    int tid = threadIdx.x, warp = tid >> 5, lane = tid & 31;
    int g = lane >> 2, tg = lane & 3;
    int n0 = blockIdx.x * 64;
    int half = blockIdx.y;
    int mb = (warp & 3) * 16, nb = (warp >> 2) * 64;

    if (tid < 64) bn_coeff(l, tid, gamma, beta, bnS[tid], bnT[tid]);
    if (blockIdx.x == 0 && half == 0 && tid < 128) g_stats[l & 1][tid] = 0.0f;
    // zero this block's slice of g_aggr (nodes n0..n0+63, cols half*64..+63) — fp16
    {
        uint4 z = make_uint4(0u, 0u, 0u, 0u);
        uint4* Az = (uint4*)g_aggr;            // node row = 16 uint4
        #pragma unroll
        for (int it = 0; it < 2; ++it) {
            int idx = tid + it * 256;          // 512
            int i = idx >> 3, qc = idx & 7;
            int node = n0 + i;
            if (node < NN) Az[(size_t)node * 16 + half * 8 + qc] = z;
        }
    }
    __syncthreads();   // bnS ready

    // stage xs as bf16 (float4 loads, BN applied)
    {
        const float4* X4 = (const float4*)g_x;
        #pragma unroll
        for (int it = 0; it < 4; ++it) {
            int idx = tid + it * 256;          // 1024
            int i = idx >> 4, q = idx & 15;
            int node = n0 + i;
            float4 v = make_float4(0.f, 0.f, 0.f, 0.f);
            if (node < NN) v = X4[(size_t)node * 16 + q];
            int c = q * 4;
            uint2 r;
            r.x = pack_bf16(v.x * bnS[c] + bnT[c],     v.y * bnS[c + 1] + bnT[c + 1]);
            r.y = pack_bf16(v.z * bnS[c + 2] + bnT[c + 2], v.w * bnS[c + 3] + bnT[c + 3]);
            *(uint2*)(xs + i * 72 + c) = r;
        }
    }
    const float* Wp = W1 + ((size_t)l * 129 + half * 64) * 128;

    float acc[8][4] = {};
    for (int k0 = 0; k0 < 64; k0 += 16) {
        __syncthreads();
        // stage W1 chunk as bf16 pairs: 128 cols x 8 pairs
        #pragma unroll
        for (int it = 0; it < 4; ++it) {
            int idx = tid + it * 256;          // 1024
            int col = idx & 127, kk2 = idx >> 7;
            int k = k0 + 2 * kk2;
            *(unsigned*)(ws + col * 24 + 2 * kk2) =
                pack_bf16(Wp[(size_t)k * 128 + col], Wp[(size_t)(k + 1) * 128 + col]);
        }
        __syncthreads();
        unsigned a0 = *(const unsigned*)(xs + (mb + g) * 72 + k0 + 2 * tg);
        unsigned a1 = *(const unsigned*)(xs + (mb + g + 8) * 72 + k0 + 2 * tg);
        unsigned a2 = *(const unsigned*)(xs + (mb + g) * 72 + k0 + 2 * tg + 8);
        unsigned a3 = *(const unsigned*)(xs + (mb + g + 8) * 72 + k0 + 2 * tg + 8);
        #pragma unroll
        for (int nt = 0; nt < 8; ++nt) {
            int col = nb + nt * 8 + g;
            unsigned b0 = *(const unsigned*)(ws + col * 24 + 2 * tg);
            unsigned b1r = *(const unsigned*)(ws + col * 24 + 2 * tg + 8);
            mma16bf(acc[nt], a0, a1, a2, a3, b0, b1r);
        }
    }
    int row0 = n0 + mb + g, row1 = row0 + 8;
    #pragma unroll
    for (int nt = 0; nt < 8; ++nt) {
        int c0 = nb + nt * 8 + 2 * tg;
        float bb0 = (half == 0) ? b1[l * 128 + c0] : 0.0f;
        float bb1 = (half == 0) ? b1[l * 128 + c0 + 1] : 0.0f;
        if (row0 < NN) {
            *(__half2*)(&g_AB[(size_t)row0 * 256 + half * 128 + c0]) =
                __floats2half2_rn(acc[nt][0] + bb0, acc[nt][1] + bb1);
        }
        if (row1 < NN) {
            *(__half2*)(&g_AB[(size_t)row1 * 256 + half * 128 + c0]) =
                __floats2half2_rn(acc[nt][2] + bb0, acc[nt][3] + bb1);
        }
    }
}

// ---------------- k2: persistent, software-pipelined edge MLP (fp16 AB, half2 aggr atomics) ----------------
// smem: w2b bf16[128][136]@0 | h1 bf16[2][64*136]@34816 (m overlays in bf16)
//       srcs2[2][64]@69632 | es2[2][64]@70144 | dsts3[3][64]@70656
//       w1e[128]@71424 | b2s[128]@71936 ; total 72448
#define K2_GRID 444
#define K2_SMEM 72448
__global__ void __launch_bounds__(256, 3) k2_edge(int l,
                                                  const float* __restrict__ W1,
                                                  const float* __restrict__ W2,
                                                  const float* __restrict__ b2) {
    extern __shared__ char sm8[];
    __nv_bfloat16* w2b = (__nv_bfloat16*)sm8;
    __nv_bfloat16* h1base = (__nv_bfloat16*)(sm8 + 34816);
    int* srcs2 = (int*)(sm8 + 69632);
    float* es2 = (float*)(sm8 + 70144);
    int* dsts3 = (int*)(sm8 + 70656);
    float* w1e = (float*)(sm8 + 71424);
    float* b2s = (float*)(sm8 + 71936);

    int tid = threadIdx.x, warp = tid >> 5, lane = tid & 31;
    int g = lane >> 2, tg = lane & 3;
    int mb = (warp & 3) * 16, nb = (warp >> 2) * 64;

    // stage W2 bf16 [col][k] pitch 136 (once)
    #pragma unroll
    for (int it = 0; it < 64; ++it) {
        int idx = tid + it * 256;
        int col = idx & 127, kk = idx >> 7;
        w2b[col * 136 + kk] = __float2bfloat16(W2[((size_t)l * 128 + kk) * 128 + col]);
    }
    if (tid < 128) w1e[tid] = W1[((size_t)l * 129 + 128) * 128 + tid];
    else b2s[tid - 128] = b2[l * 128 + (tid - 128)];

    const uint2* ABh = (const uint2*)g_AB;   // row = 64 uint2 (256 halves)
    const float4* w1e4 = (const float4*)w1e;

    auto stage = [&](int tt, int s, int ds) {
        int i4 = tt * 64 + tid;                // coalesced sorted-array reads
        srcs2[s * 64 + tid] = g_ssrc[i4];
        dsts3[ds * 64 + tid] = g_sdst[i4];
        es2[s * 64 + tid] = g_seat[i4];
    };
    auto phaseA = [&](__nv_bfloat16* H, int s, int ds) {
        int q = lane;
        int eb = warp * 8;
        const int* S = srcs2 + s * 64;
        const float* E = es2 + s * 64;
        const int* D = dsts3 + ds * 64;
        float4 w = w1e4[q];
        float4 aq = make_float4(0.f, 0.f, 0.f, 0.f);
        int prevd = -1;
        #pragma unroll
        for (int j = 0; j < 8; ++j) {
            int e = eb + j;
            int d = D[e];
            if (d != prevd) {
                uint2 ar = ABh[(size_t)d * 64 + q];
                float2 a01 = __half22float2(*(__half2*)&ar.x);
                float2 a23 = __half22float2(*(__half2*)&ar.y);
                aq = make_float4(a01.x, a01.y, a23.x, a23.y);
                prevd = d;
            }
            uint2 br = ABh[(size_t)S[e] * 64 + 32 + q];
            float2 b01 = __half22float2(*(__half2*)&br.x);
            float2 b23 = __half22float2(*(__half2*)&br.y);
            float ev = E[e];
            uint2 r;
            r.x = pack_bf16(spf(aq.x + b01.x + ev * w.x), spf(aq.y + b01.y + ev * w.y));
            r.y = pack_bf16(spf(aq.z + b23.x + ev * w.z), spf(aq.w + b23.y + ev * w.w));
            *(uint2*)(H + e * 136 + q * 4) = r;
        }
    };

    int t0 = blockIdx.x;
    if (t0 < NT && tid < 64) stage(t0, 0, 0);
    __syncthreads();
    if (t0 < NT) phaseA(h1base, 0, 0);
    if (t0 + K2_GRID < NT && tid < 64) stage(t0 + K2_GRID, 1, 1);
    __syncthreads();

    int i = 0;
    for (int t = t0; t < NT; t += K2_GRID, ++i) {
        int p = i & 1, q2 = 1 - p;
        int d_cur = i % 3, d_nxt = (i + 1) % 3, d_stg = (i + 2) % 3;
        __nv_bfloat16* h1p = h1base + p * (64 * 136);
        __nv_bfloat16* h1q = h1base + q2 * (64 * 136);

        // 1. phase B on h1p
        float acc[8][4] = {};
        #pragma unroll
        for (int kc = 0; kc < 128; kc += 16) {
            unsigned a0 = *(const unsigned*)(h1p + (mb + g) * 136 + kc + 2 * tg);
            unsigned a1 = *(const unsigned*)(h1p + (mb + g + 8) * 136 + kc + 2 * tg);
            unsigned a2 = *(const unsigned*)(h1p + (mb + g) * 136 + kc + 2 * tg + 8);
            unsigned a3 = *(const unsigned*)(h1p + (mb + g + 8) * 136 + kc + 2 * tg + 8);
            #pragma unroll
            for (int nt = 0; nt < 8; ++nt) {
                int col = nb + nt * 8 + g;
                unsigned b0 = *(const unsigned*)(w2b + col * 136 + kc + 2 * tg);
                unsigned b1r = *(const unsigned*)(w2b + col * 136 + kc + 2 * tg + 8);
                mma16bf(acc[nt], a0, a1, a2, a3, b0, b1r);
            }
        }

        // 2. phase A for t+G into h1q (overlaps MMA tail)
        int tn = t + K2_GRID;
        if (tn < NT) phaseA(h1q, q2, d_nxt);

        // 3. stage idx for t+2G
        int ts = t + 2 * K2_GRID;
        if (ts < NT && tid < 64) stage(ts, p, d_stg);
        __syncthreads();

        // 4. epilogue: m = spf(D + b2) -> bf16 over h1p
        #pragma unroll
        for (int nt = 0; nt < 8; ++nt) {
            int c0 = nb + nt * 8 + 2 * tg;
            unsigned u0 = pack_bf16(spf(acc[nt][0] + b2s[c0]), spf(acc[nt][1] + b2s[c0 + 1]));
            unsigned u1 = pack_bf16(spf(acc[nt][2] + b2s[c0]), spf(acc[nt][3] + b2s[c0 + 1]));
            *(unsigned*)(h1p + (mb + g) * 136 + c0) = u0;
            *(unsigned*)(h1p + (mb + g + 8) * 136 + c0) = u1;
        }
        __syncthreads();

        // 5. segmented reduction over sorted dst runs; half2 atomics (2 cols/thread)
        {
            const int* D = dsts3 + d_cur * 64;
            int c2 = tid & 63;                 // column pair
            int r0 = (tid >> 6) * 16;          // 4 row-groups of 16
            float2 racc = make_float2(0.f, 0.f);
            int prev = D[r0];
            #pragma unroll 4
            for (int r = r0; r < r0 + 16; ++r) {
                int d = D[r];
                if (d != prev) {
                    atomicAdd((__half2*)&g_aggr[(size_t)prev * 128 + 2 * c2],
                              __floats2half2_rn(racc.x, racc.y));
                    racc = make_float2(0.f, 0.f);
                    prev = d;
                }
                unsigned mm = *(const unsigned*)(h1p + r * 136 + 2 * c2);
                float2 f = __bfloat1622float2(*(__nv_bfloat162*)&mm);
                racc.x += f.x;
                racc.y += f.y;
            }
            atomicAdd((__half2*)&g_aggr[(size_t)prev * 128 + 2 * c2],
                      __floats2half2_rn(racc.x, racc.y));
        }
        __syncthreads();
    }
}

// ---------------- k3: node MLP (M=64, bf16 mma) + residual + BN stats ----------------
// dyn smem: hs f32[64*196]@0 | ws bf16[128*24]@50176 (6144) | ssum@60416 | ssq@60672
//           bnS@60928 | bnT@61184 ; total 61440
#define K3_SMEM 61440
__global__ void __launch_bounds__(256, 3) k3_node(int l, const float* __restrict__ W1,
                                                  const float* __restrict__ b1,
                                                  const float* __restrict__ W2,
                                                  const float* __restrict__ b2,
                                                  const float* __restrict__ gamma,
                                                  const float* __restrict__ beta) {
    extern __shared__ char sm3[];
    float* hs = (float*)sm3;
    __nv_bfloat16* ws = (__nv_bfloat16*)(sm3 + 50176);
    float* ssum = (float*)(sm3 + 60416);
    float* ssq = (float*)(sm3 + 60672);
    float* bnS = (float*)(sm3 + 60928);
    float* bnT = (float*)(sm3 + 61184);

    int tid = threadIdx.x, warp = tid >> 5, lane = tid & 31;
    int g = lane >> 2, tg = lane & 3;
    int mb = (warp & 3) * 16, nb = (warp >> 2) * 64;
    int n0 = blockIdx.x * 64;

    if (tid < 64) {
        ssum[tid] = 0.0f; ssq[tid] = 0.0f;
        bn_coeff(l, tid, gamma, beta, bnS[tid], bnT[tid]);
    }
    __syncthreads();

    for (int it = 0; it < 48; ++it) {
        int idx = tid + it * 256;
        int i = idx / 192, c = idx - i * 192;
        int node = n0 + i;
        float v = 0.0f;
        if (node < NN) {
            if (c < 64) v = g_x[(size_t)node * DD + c] * bnS[c] + bnT[c];
            else v = __half2float(g_aggr[(size_t)node * HH + (c - 64)]);
        }
        hs[i * 196 + c] = v;
    }

    // GEMM1: t = spf([x'|aggr] @ nW1 + b1), M=64, N=128, K=192, bf16 mma
    float acc[8][4] = {};
    for (int k0 = 0; k0 < 192; k0 += 16) {
        __syncthreads();
        #pragma unroll
        for (int it = 0; it < 4; ++it) {
            int idx = tid + it * 256;          // 1024
            int col = idx & 127, kk2 = idx >> 7;
            int k = k0 + 2 * kk2;
            *(unsigned*)(ws + col * 24 + 2 * kk2) =
                pack_bf16(W1[((size_t)l * 192 + k) * 128 + col],
                          W1[((size_t)l * 192 + k + 1) * 128 + col]);
        }
        __syncthreads();
        float2 v0 = *(const float2*)(hs + (mb + g) * 196 + k0 + 2 * tg);
        float2 v1 = *(const float2*)(hs + (mb + g + 8) * 196 + k0 + 2 * tg);
        float2 v2 = *(const float2*)(hs + (mb + g) * 196 + k0 + 2 * tg + 8);
        float2 v3 = *(const float2*)(hs + (mb + g + 8) * 196 + k0 + 2 * tg + 8);
        unsigned a0 = pack_bf16(v0.x, v0.y);
        unsigned a1 = pack_bf16(v1.x, v1.y);
        unsigned a2 = pack_bf16(v2.x, v2.y);
        unsigned a3 = pack_bf16(v3.x, v3.y);
        #pragma unroll
        for (int nt = 0; nt < 8; ++nt) {
            int col = nb + nt * 8 + g;
            unsigned b0 = *(const unsigned*)(ws + col * 24 + 2 * tg);
            unsigned b1r = *(const unsigned*)(ws + col * 24 + 2 * tg + 8);
            mma16bf(acc[nt], a0, a1, a2, a3, b0, b1r);
        }
    }
    __syncthreads();
    #pragma unroll
    for (int nt = 0; nt < 8; ++nt) {
        int c0 = nb + nt * 8 + 2 * tg;
        hs[(mb + g) * 196 + 64 + c0]         = spf(acc[nt][0] + b1[l * 128 + c0]);
        hs[(mb + g) * 196 + 64 + c0 + 1]     = spf(acc[nt][1] + b1[l * 128 + c0 + 1]);
        hs[(mb + g + 8) * 196 + 64 + c0]     = spf(acc[nt][2] + b1[l * 128 + c0]);
        hs[(mb + g + 8) * 196 + 64 + c0 + 1] = spf(acc[nt][3] + b1[l * 128 + c0 + 1]);
    }

    // GEMM2: y = t @ nW2 + b2 + x', M=64, N=64, K=128, bf16 mma
    int nb2 = (warp >> 2) * 32;
    float acc2[4][4] = {};
    for (int k0 = 0; k0 < 128; k0 += 16) {
        __syncthreads();
        #pragma unroll
        for (int it = 0; it < 2; ++it) {
            int idx = tid + it * 256;          // 512
            int col = idx & 63, kk2 = idx >> 6;
            int k = k0 + 2 * kk2;
            *(unsigned*)(ws + col * 24 + 2 * kk2) =
                pack_bf16(W2[((size_t)l * 128 + k) * 64 + col],
                          W2[((size_t)l * 128 + k + 1) * 64 + col]);
        }
        __syncthreads();
        float2 v0 = *(const float2*)(hs + (mb + g) * 196 + 64 + k0 + 2 * tg);
        float2 v1 = *(const float2*)(hs + (mb + g + 8) * 196 + 64 + k0 + 2 * tg);
        float2 v2 = *(const float2*)(hs + (mb + g) * 196 + 64 + k0 + 2 * tg + 8);
        float2 v3 = *(const float2*)(hs + (mb + g + 8) * 196 + 64 + k0 + 2 * tg + 8);
        unsigned a0 = pack_bf16(v0.x, v0.y);
        unsigned a1 = pack_bf16(v1.x, v1.y);
        unsigned a2 = pack_bf16(v2.x, v2.y);
        unsigned a3 = pack_bf16(v3.x, v3.y);
        #pragma unroll
        for (int nt = 0; nt < 4; ++nt) {
            int col = nb2 + nt * 8 + g;
            unsigned b0 = *(const unsigned*)(ws + col * 24 + 2 * tg);
            unsigned b1r = *(const unsigned*)(ws + col * 24 + 2 * tg + 8);
            mma16bf(acc2[nt], a0, a1, a2, a3, b0, b1r);
        }
    }

    #pragma unroll
    for (int nt = 0; nt < 4; ++nt) {
        int c0 = nb2 + nt * 8 + 2 * tg;
        float bb0 = b2[l * 64 + c0], bb1 = b2[l * 64 + c0 + 1];
        int row0 = mb + g, row1 = mb + g + 8;
        int node0 = n0 + row0, node1 = n0 + row1;
        if (node0 < NN) {
            float y0 = acc2[nt][0] + bb0 + hs[row0 * 196 + c0];
            float y1 = acc2[nt][1] + bb1 + hs[row0 * 196 + c0 + 1];
            g_x[(size_t)node0 * DD + c0] = y0;
            g_x[(size_t)node0 * DD + c0 + 1] = y1;
            atomicAdd(&ssum[c0], y0);     atomicAdd(&ssum[c0 + 1], y1);
            atomicAdd(&ssq[c0], y0 * y0); atomicAdd(&ssq[c0 + 1], y1 * y1);
        }
        if (node1 < NN) {
            float y2 = acc2[nt][2] + bb0 + hs[row1 * 196 + c0];
            float y3 = acc2[nt][3] + bb1 + hs[row1 * 196 + c0 + 1];
            g_x[(size_t)node1 * DD + c0] = y2;
            g_x[(size_t)node1 * DD + c0 + 1] = y3;
            atomicAdd(&ssum[c0], y2);     atomicAdd(&ssum[c0 + 1], y3);
            atomicAdd(&ssq[c0], y2 * y2); atomicAdd(&ssq[c0 + 1], y3 * y3);
        }
    }
    __syncthreads();
    if (tid < 64) {
        atomicAdd(&g_stats[l & 1][tid], ssum[tid]);
        atomicAdd(&g_stats[l & 1][64 + tid], ssq[tid]);
    }
}

// ---------------- k5: global mean pool (applies final BN) ----------------
__global__ void k5_pool(const int* __restrict__ batch,
                        const float* __restrict__ gamma, const float* __restrict__ beta) {
    int idx = blockIdx.x * blockDim.x + threadIdx.x;
    if (idx >= NN * DD) return;
    int i = idx >> 6, c = idx & 63;
    const float* sb = g_stats[(NL - 1) & 1];
    const float invN = 1.0f / (float)NN;
    float mu = sb[c] * invN;
    float var = sb[64 + c] * invN - mu * mu;
    float gi = gamma[(NL - 1) * 64 + c] * rsqrtf(var + 1e-5f);
    float v = g_x[idx] * gi + (beta[(NL - 1) * 64 + c] - mu * gi);
    int b = batch[i];
    atomicAdd(&g_pool[b * DD + c], v);
    if (c == 0) atomicAdd(&g_cnt[b], 1.0f);
}

// ---------------- k6: output MLP ----------------
__global__ void k6_out(const float* __restrict__ W1, const float* __restrict__ b1,
                       const float* __restrict__ W2, const float* __restrict__ b2,
                       float* __restrict__ out) {
    __shared__ float p[64];
    __shared__ float red[128];
    int g = blockIdx.x, c = threadIdx.x;
    if (c < 64) p[c] = g_pool[g * DD + c] / fmaxf(g_cnt[g], 1.0f);
    __syncthreads();
    float acc = b1[c];
    #pragma unroll
    for (int d = 0; d < 64; ++d) acc = fmaf(p[d], W1[d * 128 + c], acc);
    red[c] = softplusf(acc) * W2[c];
    __syncthreads();
    for (int s = 64; s > 0; s >>= 1) {
        if (c < s) red[c] += red[c + s];
        __syncthreads();
    }
    if (c == 0) out[g] = red[0] + b2[0];
}

// ---------------- launcher ----------------
extern "C" void kernel_launch(void* const* d_in, const int* in_sizes, int n_in,
                              void* d_out, int out_size) {
    const int*   atom_z = (const int*)  d_in[0];
    const int*   ei     = (const int*)  d_in[1];
    const float* eattr  = (const float*)d_in[2];
    const int*   batch  = (const int*)  d_in[3];
    const float* emb    = (const float*)d_in[4];
    const float* eW1    = (const float*)d_in[5];
    const float* eb1    = (const float*)d_in[6];
    const float* eW2    = (const float*)d_in[7];
    const float* eb2    = (const float*)d_in[8];
    const float* nW1    = (const float*)d_in[9];
    const float* nb1    = (const float*)d_in[10];
    const float* nW2    = (const float*)d_in[11];
    const float* nb2    = (const float*)d_in[12];
    const float* bng    = (const float*)d_in[13];
    const float* bnb    = (const float*)d_in[14];
    const float* oW1    = (const float*)d_in[15];
    const float* ob1    = (const float*)d_in[16];
    const float* oW2    = (const float*)d_in[17];
    const float* ob2    = (const float*)d_in[18];
    float* out = (float*)d_out;

    cudaFuncSetAttribute(k2_edge, cudaFuncAttributeMaxDynamicSharedMemorySize, K2_SMEM);
    cudaFuncSetAttribute(k3_node, cudaFuncAttributeMaxDynamicSharedMemorySize, K3_SMEM);

    int nsb = (NN + 1023) / 1024;

    k0_embed<<<(NN * DD + 255) / 256, 256>>>(atom_z, emb);
    k_hist<<<(NE + 255) / 256, 256>>>(ei);
    k_scan_part<<<nsb, 1024>>>();
    k1_AB<<<dim3((NN + 63) / 64, 2), 256>>>(0, eW1, eb1, bng, bnb);
    k_scan_top<<<1, 64>>>();
    k_scatter<<<(NE + 255) / 256, 256>>>(ei, eattr);

    k2_edge<<<K2_GRID, 256, K2_SMEM>>>(0, eW1, eW2, eb2);
    k3_node<<<(NN + 63) / 64, 256, K3_SMEM>>>(0, nW1, nb1, nW2, nb2, bng, bnb);
    for (int l = 1; l < NL; ++l) {
        k1_AB<<<dim3((NN + 63) / 64, 2), 256>>>(l, eW1, eb1, bng, bnb);
        k2_edge<<<K2_GRID, 256, K2_SMEM>>>(l, eW1, eW2, eb2);
        k3_node<<<(NN + 63) / 64, 256, K3_SMEM>>>(l, nW1, nb1, nW2, nb2, bng, bnb);
    }
    k5_pool<<<(NN * DD + 255) / 256, 256>>>(batch, bng, bnb);
    k6_out<<<GG, 128>>>(oW1, ob1, oW2, ob2, out);
}

// round 15
// speedup vs baseline: 1.2667x; 1.0375x over previous
#include <cuda_runtime.h>
#include <cuda_bf16.h>
#include <cuda_fp16.h>
#include <cstdint>
#include <math.h>

#define NN 50000
#define NE 800000
#define DD 64
#define HH 128
#define GG 128
#define NL 3
#define NT (NE / 64)

// ---------------- device scratch ----------------
__device__ float  g_x[NN * DD];             // pre-BN node features
__device__ __half g_AB[(size_t)NN * 256];   // [A=x'@W1a+b1 | B=x'@W1b] (fp16)
__device__ __half g_aggr[(size_t)NN * HH];  // fp16 message sums
__device__ float  g_stats[2][128];
__device__ float  g_pool[GG * DD];
__device__ float  g_cnt[GG];
__device__ int    g_hist[NN];
__device__ int    g_bsum[64];
__device__ int    g_ssrc[NE];               // dst-sorted edge arrays
__device__ int    g_sdst[NE];
__device__ float  g_seat[NE];

__device__ __forceinline__ float softplusf(float x) {
    return fmaxf(x, 0.0f) + __logf(1.0f + __expf(-fabsf(x)));
}
// fast softplus: 1 MUFU + Horner cubic for ln(1+u), u=e^-|x| in [0,1]
// identical polynomial to prior rounds' factored form; |abs err| <~ 3e-4
__device__ __forceinline__ float spf(float x) {
    float u = __expf(-fabsf(x));
    float lg = u * fmaf(u, fmaf(u, fmaf(u, -0.05781f, 0.22930f), -0.47833f), 0.99998f);
    return fmaxf(x, 0.0f) + lg;
}
__device__ __forceinline__ unsigned pack_bf16(float lo, float hi) {
    unsigned r;
    asm("cvt.rn.bf16x2.f32 %0, %1, %2;" : "=r"(r) : "f"(hi), "f"(lo));
    return r;
}
__device__ __forceinline__ void mma16bf(float* c, unsigned a0, unsigned a1,
                                        unsigned a2, unsigned a3,
                                        unsigned b0, unsigned b1) {
    asm volatile(
        "mma.sync.aligned.m16n8k16.row.col.f32.bf16.bf16.f32 "
        "{%0,%1,%2,%3}, {%4,%5,%6,%7}, {%8,%9}, {%0,%1,%2,%3};"
        : "+f"(c[0]), "+f"(c[1]), "+f"(c[2]), "+f"(c[3])
        : "r"(a0), "r"(a1), "r"(a2), "r"(a3), "r"(b0), "r"(b1));
}
__device__ __forceinline__ void bn_coeff(int l, int c, const float* gamma,
                                         const float* beta, float& S, float& T) {
    if (l == 0) { S = 1.0f; T = 0.0f; return; }
    const float* sb = g_stats[(l - 1) & 1];
    const float invN = 1.0f / (float)NN;
    float mu = sb[c] * invN;
    float var = sb[64 + c] * invN - mu * mu;
    float gi = gamma[(l - 1) * 64 + c] * rsqrtf(var + 1e-5f);
    S = gi;
    T = beta[(l - 1) * 64 + c] - mu * gi;
}

// ---------------- k0: embedding gather (+ zero g_hist, pool) ----------------
__global__ void k0_embed(const int* __restrict__ az, const float* __restrict__ emb) {
    int idx = blockIdx.x * blockDim.x + threadIdx.x;
    if (idx < NN) g_hist[idx] = 0;
    if (idx < GG * DD) g_pool[idx] = 0.0f;
    if (idx < GG) g_cnt[idx] = 0.0f;
    if (idx >= NN * DD) return;
    int i = idx >> 6, c = idx & 63;
    g_x[idx] = emb[az[i] * DD + c];
}

// ---------------- counting sort (materializes sorted arrays) ----------------
__global__ void k_hist(const int* __restrict__ ei) {
    int e = blockIdx.x * blockDim.x + threadIdx.x;
    if (e < NE) atomicAdd(&g_hist[ei[NE + e]], 1);
}
__global__ void k_scan_part() {
    __shared__ int wsum[32];
    int tid = threadIdx.x, lane = tid & 31, wid = tid >> 5;
    int i = blockIdx.x * 1024 + tid;
    int v = (i < NN) ? g_hist[i] : 0;
    int x = v;
    #pragma unroll
    for (int off = 1; off < 32; off <<= 1) {
        int y = __shfl_up_sync(0xffffffffu, x, off);
        if (lane >= off) x += y;
    }
    if (lane == 31) wsum[wid] = x;
    __syncthreads();
    if (wid == 0) {
        int s = wsum[lane];
        #pragma unroll
        for (int off = 1; off < 32; off <<= 1) {
            int y = __shfl_up_sync(0xffffffffu, s, off);
            if (lane >= off) s += y;
        }
        wsum[lane] = s;
    }
    __syncthreads();
    int woff = (wid > 0) ? wsum[wid - 1] : 0;
    if (i < NN) g_hist[i] = x - v + woff;   // block-local exclusive
    if (tid == 1023) g_bsum[blockIdx.x] = x + woff;
}
__global__ void k_scan_top() {
    __shared__ int s[64];
    int tid = threadIdx.x;
    int nb = (NN + 1023) / 1024;
    int v = (tid < nb) ? g_bsum[tid] : 0;
    s[tid] = v;
    __syncthreads();
    for (int off = 1; off < 64; off <<= 1) {
        int t = (tid >= off) ? s[tid - off] : 0;
        __syncthreads();
        s[tid] += t;
        __syncthreads();
    }
    if (tid < nb) g_bsum[tid] = s[tid] - v;
}
__global__ void k_scatter(const int* __restrict__ ei, const float* __restrict__ eattr) {
    int e = blockIdx.x * blockDim.x + threadIdx.x;
    if (e >= NE) return;
    int d = ei[NE + e];
    int pos = atomicAdd(&g_hist[d], 1) + g_bsum[d >> 10];
    g_ssrc[pos] = ei[e];
    g_sdst[pos] = d;
    g_seat[pos] = eattr[e];
}

// ---------------- k1: AB = x' @ [W1a | W1b] (per-half, bf16 mma); zeroes aggr + stats ----------------
__global__ void __launch_bounds__(256) k1_AB(int l, const float* __restrict__ W1,
                                             const float* __restrict__ b1,
                                             const float* __restrict__ gamma,
                                             const float* __restrict__ beta) {
    __shared__ __nv_bfloat16 xs[64 * 72];  // bf16, BN applied; pitch 72
    __shared__ __nv_bfloat16 ws[128 * 24]; // W1 chunk [col][k], pitch 24
    __shared__ float bnS[64], bnT[64];
    int tid = threadIdx.x, warp = tid >> 5, lane = tid & 31;
    int g = lane >> 2, tg = lane & 3;
    int n0 = blockIdx.x * 64;
    int half = blockIdx.y;
    int mb = (warp & 3) * 16, nb = (warp >> 2) * 64;

    if (tid < 64) bn_coeff(l, tid, gamma, beta, bnS[tid], bnT[tid]);
    if (blockIdx.x == 0 && half == 0 && tid < 128) g_stats[l & 1][tid] = 0.0f;
    // zero this block's slice of g_aggr (nodes n0..n0+63, cols half*64..+63) — fp16
    {
        uint4 z = make_uint4(0u, 0u, 0u, 0u);
        uint4* Az = (uint4*)g_aggr;            // node row = 16 uint4
        #pragma unroll
        for (int it = 0; it < 2; ++it) {
            int idx = tid + it * 256;          // 512
            int i = idx >> 3, qc = idx & 7;
            int node = n0 + i;
            if (node < NN) Az[(size_t)node * 16 + half * 8 + qc] = z;
        }
    }
    __syncthreads();   // bnS ready

    // stage xs as bf16 (float4 loads, BN applied)
    {
        const float4* X4 = (const float4*)g_x;
        #pragma unroll
        for (int it = 0; it < 4; ++it) {
            int idx = tid + it * 256;          // 1024
            int i = idx >> 4, q = idx & 15;
            int node = n0 + i;
            float4 v = make_float4(0.f, 0.f, 0.f, 0.f);
            if (node < NN) v = X4[(size_t)node * 16 + q];
            int c = q * 4;
            uint2 r;
            r.x = pack_bf16(v.x * bnS[c] + bnT[c],     v.y * bnS[c + 1] + bnT[c + 1]);
            r.y = pack_bf16(v.z * bnS[c + 2] + bnT[c + 2], v.w * bnS[c + 3] + bnT[c + 3]);
            *(uint2*)(xs + i * 72 + c) = r;
        }
    }
    const float* Wp = W1 + ((size_t)l * 129 + half * 64) * 128;

    float acc[8][4] = {};
    for (int k0 = 0; k0 < 64; k0 += 16) {
        __syncthreads();
        // stage W1 chunk as bf16 pairs: 128 cols x 8 pairs
        #pragma unroll
        for (int it = 0; it < 4; ++it) {
            int idx = tid + it * 256;          // 1024
            int col = idx & 127, kk2 = idx >> 7;
            int k = k0 + 2 * kk2;
            *(unsigned*)(ws + col * 24 + 2 * kk2) =
                pack_bf16(Wp[(size_t)k * 128 + col], Wp[(size_t)(k + 1) * 128 + col]);
        }
        __syncthreads();
        unsigned a0 = *(const unsigned*)(xs + (mb + g) * 72 + k0 + 2 * tg);
        unsigned a1 = *(const unsigned*)(xs + (mb + g + 8) * 72 + k0 + 2 * tg);
        unsigned a2 = *(const unsigned*)(xs + (mb + g) * 72 + k0 + 2 * tg + 8);
        unsigned a3 = *(const unsigned*)(xs + (mb + g + 8) * 72 + k0 + 2 * tg + 8);
        #pragma unroll
        for (int nt = 0; nt < 8; ++nt) {
            int col = nb + nt * 8 + g;
            unsigned b0 = *(const unsigned*)(ws + col * 24 + 2 * tg);
            unsigned b1r = *(const unsigned*)(ws + col * 24 + 2 * tg + 8);
            mma16bf(acc[nt], a0, a1, a2, a3, b0, b1r);
        }
    }
    int row0 = n0 + mb + g, row1 = row0 + 8;
    #pragma unroll
    for (int nt = 0; nt < 8; ++nt) {
        int c0 = nb + nt * 8 + 2 * tg;
        float bb0 = (half == 0) ? b1[l * 128 + c0] : 0.0f;
        float bb1 = (half == 0) ? b1[l * 128 + c0 + 1] : 0.0f;
        if (row0 < NN) {
            *(__half2*)(&g_AB[(size_t)row0 * 256 + half * 128 + c0]) =
                __floats2half2_rn(acc[nt][0] + bb0, acc[nt][1] + bb1);
        }
        if (row1 < NN) {
            *(__half2*)(&g_AB[(size_t)row1 * 256 + half * 128 + c0]) =
                __floats2half2_rn(acc[nt][2] + bb0, acc[nt][3] + bb1);
        }
    }
}

// ---------------- k2: persistent, software-pipelined edge MLP (32x32 warp tiles) ----------------
// smem: w2b bf16[128][136]@0 | h1 bf16[2][64*136]@34816 (m overlays in bf16)
//       srcs2[2][64]@69632 | es2[2][64]@70144 | dsts3[3][64]@70656
//       w1e[128]@71424 | b2s[128]@71936 ; total 72448
#define K2_GRID 444
#define K2_SMEM 72448
__global__ void __launch_bounds__(256, 3) k2_edge(int l,
                                                  const float* __restrict__ W1,
                                                  const float* __restrict__ W2,
                                                  const float* __restrict__ b2) {
    extern __shared__ char sm8[];
    __nv_bfloat16* w2b = (__nv_bfloat16*)sm8;
    __nv_bfloat16* h1base = (__nv_bfloat16*)(sm8 + 34816);
    int* srcs2 = (int*)(sm8 + 69632);
    float* es2 = (float*)(sm8 + 70144);
    int* dsts3 = (int*)(sm8 + 70656);
    float* w1e = (float*)(sm8 + 71424);
    float* b2s = (float*)(sm8 + 71936);

    int tid = threadIdx.x, warp = tid >> 5, lane = tid & 31;
    int g = lane >> 2, tg = lane & 3;
    int mb = (warp & 1) * 32, nb = (warp >> 1) * 32;   // 32x32 warp tile

    // stage W2 bf16 [col][k] pitch 136 (once)
    #pragma unroll
    for (int it = 0; it < 64; ++it) {
        int idx = tid + it * 256;
        int col = idx & 127, kk = idx >> 7;
        w2b[col * 136 + kk] = __float2bfloat16(W2[((size_t)l * 128 + kk) * 128 + col]);
    }
    if (tid < 128) w1e[tid] = W1[((size_t)l * 129 + 128) * 128 + tid];
    else b2s[tid - 128] = b2[l * 128 + (tid - 128)];

    const uint2* ABh = (const uint2*)g_AB;   // row = 64 uint2 (256 halves)
    const float4* w1e4 = (const float4*)w1e;

    auto stage = [&](int tt, int s, int ds) {
        int i4 = tt * 64 + tid;                // coalesced sorted-array reads
        srcs2[s * 64 + tid] = g_ssrc[i4];
        dsts3[ds * 64 + tid] = g_sdst[i4];
        es2[s * 64 + tid] = g_seat[i4];
    };
    auto phaseA = [&](__nv_bfloat16* H, int s, int ds) {
        int q = lane;
        int eb = warp * 8;
        const int* S = srcs2 + s * 64;
        const float* E = es2 + s * 64;
        const int* D = dsts3 + ds * 64;
        float4 w = w1e4[q];
        float4 aq = make_float4(0.f, 0.f, 0.f, 0.f);
        int prevd = -1;
        #pragma unroll
        for (int j = 0; j < 8; ++j) {
            int e = eb + j;
            int d = D[e];
            if (d != prevd) {
                uint2 ar = ABh[(size_t)d * 64 + q];
                float2 a01 = __half22float2(*(__half2*)&ar.x);
                float2 a23 = __half22float2(*(__half2*)&ar.y);
                aq = make_float4(a01.x, a01.y, a23.x, a23.y);
                prevd = d;
            }
            uint2 br = ABh[(size_t)S[e] * 64 + 32 + q];
            float2 b01 = __half22float2(*(__half2*)&br.x);
            float2 b23 = __half22float2(*(__half2*)&br.y);
            float ev = E[e];
            uint2 r;
            r.x = pack_bf16(spf(aq.x + b01.x + ev * w.x), spf(aq.y + b01.y + ev * w.y));
            r.y = pack_bf16(spf(aq.z + b23.x + ev * w.z), spf(aq.w + b23.y + ev * w.w));
            *(uint2*)(H + e * 136 + q * 4) = r;
        }
    };

    int t0 = blockIdx.x;
    if (t0 < NT && tid < 64) stage(t0, 0, 0);
    __syncthreads();
    if (t0 < NT) phaseA(h1base, 0, 0);
    if (t0 + K2_GRID < NT && tid < 64) stage(t0 + K2_GRID, 1, 1);
    __syncthreads();

    int i = 0;
    for (int t = t0; t < NT; t += K2_GRID, ++i) {
        int p = i & 1, q2 = 1 - p;
        int d_cur = i % 3, d_nxt = (i + 1) % 3, d_stg = (i + 2) % 3;
        __nv_bfloat16* h1p = h1base + p * (64 * 136);
        __nv_bfloat16* h1q = h1base + q2 * (64 * 136);

        // 1. phase B on h1p: warp = 32 rows x 32 cols
        float acc[2][4][4] = {};
        #pragma unroll
        for (int kc = 0; kc < 128; kc += 16) {
            unsigned a[2][4];
            #pragma unroll
            for (int mt = 0; mt < 2; ++mt) {
                int r0 = mb + mt * 16 + g;
                a[mt][0] = *(const unsigned*)(h1p + r0 * 136 + kc + 2 * tg);
                a[mt][1] = *(const unsigned*)(h1p + (r0 + 8) * 136 + kc + 2 * tg);
                a[mt][2] = *(const unsigned*)(h1p + r0 * 136 + kc + 2 * tg + 8);
                a[mt][3] = *(const unsigned*)(h1p + (r0 + 8) * 136 + kc + 2 * tg + 8);
            }
            #pragma unroll
            for (int nt = 0; nt < 4; ++nt) {
                int col = nb + nt * 8 + g;
                unsigned b0 = *(const unsigned*)(w2b + col * 136 + kc + 2 * tg);
                unsigned b1r = *(const unsigned*)(w2b + col * 136 + kc + 2 * tg + 8);
                mma16bf(acc[0][nt], a[0][0], a[0][1], a[0][2], a[0][3], b0, b1r);
                mma16bf(acc[1][nt], a[1][0], a[1][1], a[1][2], a[1][3], b0, b1r);
            }
        }

        // 2. phase A for t+G into h1q (overlaps MMA tail)
        int tn = t + K2_GRID;
        if (tn < NT) phaseA(h1q, q2, d_nxt);

        // 3. stage idx for t+2G
        int ts = t + 2 * K2_GRID;
        if (ts < NT && tid < 64) stage(ts, p, d_stg);
        __syncthreads();

        // 4. epilogue: m = spf(D + b2) -> bf16 over h1p
        #pragma unroll
        for (int mt = 0; mt < 2; ++mt) {
            int r0 = mb + mt * 16 + g;
            #pragma unroll
            for (int nt = 0; nt < 4; ++nt) {
                int c0 = nb + nt * 8 + 2 * tg;
                unsigned u0 = pack_bf16(spf(acc[mt][nt][0] + b2s[c0]),
                                        spf(acc[mt][nt][1] + b2s[c0 + 1]));
                unsigned u1 = pack_bf16(spf(acc[mt][nt][2] + b2s[c0]),
                                        spf(acc[mt][nt][3] + b2s[c0 + 1]));
                *(unsigned*)(h1p + r0 * 136 + c0) = u0;
                *(unsigned*)(h1p + (r0 + 8) * 136 + c0) = u1;
            }
        }
        __syncthreads();

        // 5. segmented reduction over sorted dst runs; half2 atomics (2 cols/thread)
        {
            const int* D = dsts3 + d_cur * 64;
            int c2 = tid & 63;                 // column pair
            int r0 = (tid >> 6) * 16;          // 4 row-groups of 16
            float2 racc = make_float2(0.f, 0.f);
            int prev = D[r0];
            #pragma unroll 4
            for (int r = r0; r < r0 + 16; ++r) {
                int d = D[r];
                if (d != prev) {
                    atomicAdd((__half2*)&g_aggr[(size_t)prev * 128 + 2 * c2],
                              __floats2half2_rn(racc.x, racc.y));
                    racc = make_float2(0.f, 0.f);
                    prev = d;
                }
                unsigned mm = *(const unsigned*)(h1p + r * 136 + 2 * c2);
                float2 f = __bfloat1622float2(*(__nv_bfloat162*)&mm);
                racc.x += f.x;
                racc.y += f.y;
            }
            atomicAdd((__half2*)&g_aggr[(size_t)prev * 128 + 2 * c2],
                      __floats2half2_rn(racc.x, racc.y));
        }
        __syncthreads();
    }
}

// ---------------- k3: node MLP (M=64, bf16 mma) + residual + BN stats ----------------
// dyn smem: hs f32[64*196]@0 | ws bf16[128*24]@50176 (6144) | ssum@60416 | ssq@60672
//           bnS@60928 | bnT@61184 ; total 61440
#define K3_SMEM 61440
__global__ void __launch_bounds__(256, 3) k3_node(int l, const float* __restrict__ W1,
                                                  const float* __restrict__ b1,
                                                  const float* __restrict__ W2,
                                                  const float* __restrict__ b2,
                                                  const float* __restrict__ gamma,
                                                  const float* __restrict__ beta) {
    extern __shared__ char sm3[];
    float* hs = (float*)sm3;
    __nv_bfloat16* ws = (__nv_bfloat16*)(sm3 + 50176);
    float* ssum = (float*)(sm3 + 60416);
    float* ssq = (float*)(sm3 + 60672);
    float* bnS = (float*)(sm3 + 60928);
    float* bnT = (float*)(sm3 + 61184);

    int tid = threadIdx.x, warp = tid >> 5, lane = tid & 31;
    int g = lane >> 2, tg = lane & 3;
    int mb = (warp & 3) * 16, nb = (warp >> 2) * 64;
    int n0 = blockIdx.x * 64;

    if (tid < 64) {
        ssum[tid] = 0.0f; ssq[tid] = 0.0f;
        bn_coeff(l, tid, gamma, beta, bnS[tid], bnT[tid]);
    }
    __syncthreads();

    for (int it = 0; it < 48; ++it) {
        int idx = tid + it * 256;
        int i = idx / 192, c = idx - i * 192;
        int node = n0 + i;
        float v = 0.0f;
        if (node < NN) {
            if (c < 64) v = g_x[(size_t)node * DD + c] * bnS[c] + bnT[c];
            else v = __half2float(g_aggr[(size_t)node * HH + (c - 64)]);
        }
        hs[i * 196 + c] = v;
    }

    // GEMM1: t = spf([x'|aggr] @ nW1 + b1), M=64, N=128, K=192, bf16 mma
    float acc[8][4] = {};
    for (int k0 = 0; k0 < 192; k0 += 16) {
        __syncthreads();
        #pragma unroll
        for (int it = 0; it < 4; ++it) {
            int idx = tid + it * 256;          // 1024
            int col = idx & 127, kk2 = idx >> 7;
            int k = k0 + 2 * kk2;
            *(unsigned*)(ws + col * 24 + 2 * kk2) =
                pack_bf16(W1[((size_t)l * 192 + k) * 128 + col],
                          W1[((size_t)l * 192 + k + 1) * 128 + col]);
        }
        __syncthreads();
        float2 v0 = *(const float2*)(hs + (mb + g) * 196 + k0 + 2 * tg);
        float2 v1 = *(const float2*)(hs + (mb + g + 8) * 196 + k0 + 2 * tg);
        float2 v2 = *(const float2*)(hs + (mb + g) * 196 + k0 + 2 * tg + 8);
        float2 v3 = *(const float2*)(hs + (mb + g + 8) * 196 + k0 + 2 * tg + 8);
        unsigned a0 = pack_bf16(v0.x, v0.y);
        unsigned a1 = pack_bf16(v1.x, v1.y);
        unsigned a2 = pack_bf16(v2.x, v2.y);
        unsigned a3 = pack_bf16(v3.x, v3.y);
        #pragma unroll
        for (int nt = 0; nt < 8; ++nt) {
            int col = nb + nt * 8 + g;
            unsigned b0 = *(const unsigned*)(ws + col * 24 + 2 * tg);
            unsigned b1r = *(const unsigned*)(ws + col * 24 + 2 * tg + 8);
            mma16bf(acc[nt], a0, a1, a2, a3, b0, b1r);
        }
    }
    __syncthreads();
    #pragma unroll
    for (int nt = 0; nt < 8; ++nt) {
        int c0 = nb + nt * 8 + 2 * tg;
        hs[(mb + g) * 196 + 64 + c0]         = spf(acc[nt][0] + b1[l * 128 + c0]);
        hs[(mb + g) * 196 + 64 + c0 + 1]     = spf(acc[nt][1] + b1[l * 128 + c0 + 1]);
        hs[(mb + g + 8) * 196 + 64 + c0]     = spf(acc[nt][2] + b1[l * 128 + c0]);
        hs[(mb + g + 8) * 196 + 64 + c0 + 1] = spf(acc[nt][3] + b1[l * 128 + c0 + 1]);
    }

    // GEMM2: y = t @ nW2 + b2 + x', M=64, N=64, K=128, bf16 mma
    int nb2 = (warp >> 2) * 32;
    float acc2[4][4] = {};
    for (int k0 = 0; k0 < 128; k0 += 16) {
        __syncthreads();
        #pragma unroll
        for (int it = 0; it < 2; ++it) {
            int idx = tid + it * 256;          // 512
            int col = idx & 63, kk2 = idx >> 6;
            int k = k0 + 2 * kk2;
            *(unsigned*)(ws + col * 24 + 2 * kk2) =
                pack_bf16(W2[((size_t)l * 128 + k) * 64 + col],
                          W2[((size_t)l * 128 + k + 1) * 64 + col]);
        }
        __syncthreads();
        float2 v0 = *(const float2*)(hs + (mb + g) * 196 + 64 + k0 + 2 * tg);
        float2 v1 = *(const float2*)(hs + (mb + g + 8) * 196 + 64 + k0 + 2 * tg);
        float2 v2 = *(const float2*)(hs + (mb + g) * 196 + 64 + k0 + 2 * tg + 8);
        float2 v3 = *(const float2*)(hs + (mb + g + 8) * 196 + 64 + k0 + 2 * tg + 8);
        unsigned a0 = pack_bf16(v0.x, v0.y);
        unsigned a1 = pack_bf16(v1.x, v1.y);
        unsigned a2 = pack_bf16(v2.x, v2.y);
        unsigned a3 = pack_bf16(v3.x, v3.y);
        #pragma unroll
        for (int nt = 0; nt < 4; ++nt) {
            int col = nb2 + nt * 8 + g;
            unsigned b0 = *(const unsigned*)(ws + col * 24 + 2 * tg);
            unsigned b1r = *(const unsigned*)(ws + col * 24 + 2 * tg + 8);
            mma16bf(acc2[nt], a0, a1, a2, a3, b0, b1r);
        }
    }

    #pragma unroll
    for (int nt = 0; nt < 4; ++nt) {
        int c0 = nb2 + nt * 8 + 2 * tg;
        float bb0 = b2[l * 64 + c0], bb1 = b2[l * 64 + c0 + 1];
        int row0 = mb + g, row1 = mb + g + 8;
        int node0 = n0 + row0, node1 = n0 + row1;
        if (node0 < NN) {
            float y0 = acc2[nt][0] + bb0 + hs[row0 * 196 + c0];
            float y1 = acc2[nt][1] + bb1 + hs[row0 * 196 + c0 + 1];
            g_x[(size_t)node0 * DD + c0] = y0;
            g_x[(size_t)node0 * DD + c0 + 1] = y1;
            atomicAdd(&ssum[c0], y0);     atomicAdd(&ssum[c0 + 1], y1);
            atomicAdd(&ssq[c0], y0 * y0); atomicAdd(&ssq[c0 + 1], y1 * y1);
        }
        if (node1 < NN) {
            float y2 = acc2[nt][2] + bb0 + hs[row1 * 196 + c0];
            float y3 = acc2[nt][3] + bb1 + hs[row1 * 196 + c0 + 1];
            g_x[(size_t)node1 * DD + c0] = y2;
            g_x[(size_t)node1 * DD + c0 + 1] = y3;
            atomicAdd(&ssum[c0], y2);     atomicAdd(&ssum[c0 + 1], y3);
            atomicAdd(&ssq[c0], y2 * y2); atomicAdd(&ssq[c0 + 1], y3 * y3);
        }
    }
    __syncthreads();
    if (tid < 64) {
        atomicAdd(&g_stats[l & 1][tid], ssum[tid]);
        atomicAdd(&g_stats[l & 1][64 + tid], ssq[tid]);
    }
}

// ---------------- k5: global mean pool (applies final BN) ----------------
__global__ void k5_pool(const int* __restrict__ batch,
                        const float* __restrict__ gamma, const float* __restrict__ beta) {
    int idx = blockIdx.x * blockDim.x + threadIdx.x;
    if (idx >= NN * DD) return;
    int i = idx >> 6, c = idx & 63;
    const float* sb = g_stats[(NL - 1) & 1];
    const float invN = 1.0f / (float)NN;
    float mu = sb[c] * invN;
    float var = sb[64 + c] * invN - mu * mu;
    float gi = gamma[(NL - 1) * 64 + c] * rsqrtf(var + 1e-5f);
    float v = g_x[idx] * gi + (beta[(NL - 1) * 64 + c] - mu * gi);
    int b = batch[i];
    atomicAdd(&g_pool[b * DD + c], v);
    if (c == 0) atomicAdd(&g_cnt[b], 1.0f);
}

// ---------------- k6: output MLP ----------------
__global__ void k6_out(const float* __restrict__ W1, const float* __restrict__ b1,
                       const float* __restrict__ W2, const float* __restrict__ b2,
                       float* __restrict__ out) {
    __shared__ float p[64];
    __shared__ float red[128];
    int g = blockIdx.x, c = threadIdx.x;
    if (c < 64) p[c] = g_pool[g * DD + c] / fmaxf(g_cnt[g], 1.0f);
    __syncthreads();
    float acc = b1[c];
    #pragma unroll
    for (int d = 0; d < 64; ++d) acc = fmaf(p[d], W1[d * 128 + c], acc);
    red[c] = softplusf(acc) * W2[c];
    __syncthreads();
    for (int s = 64; s > 0; s >>= 1) {
        if (c < s) red[c] += red[c + s];
        __syncthreads();
    }
    if (c == 0) out[g] = red[0] + b2[0];
}

// ---------------- launcher ----------------
extern "C" void kernel_launch(void* const* d_in, const int* in_sizes, int n_in,
                              void* d_out, int out_size) {
    const int*   atom_z = (const int*)  d_in[0];
    const int*   ei     = (const int*)  d_in[1];
    const float* eattr  = (const float*)d_in[2];
    const int*   batch  = (const int*)  d_in[3];
    const float* emb    = (const float*)d_in[4];
    const float* eW1    = (const float*)d_in[5];
    const float* eb1    = (const float*)d_in[6];
    const float* eW2    = (const float*)d_in[7];
    const float* eb2    = (const float*)d_in[8];
    const float* nW1    = (const float*)d_in[9];
    const float* nb1    = (const float*)d_in[10];
    const float* nW2    = (const float*)d_in[11];
    const float* nb2    = (const float*)d_in[12];
    const float* bng    = (const float*)d_in[13];
    const float* bnb    = (const float*)d_in[14];
    const float* oW1    = (const float*)d_in[15];
    const float* ob1    = (const float*)d_in[16];
    const float* oW2    = (const float*)d_in[17];
    const float* ob2    = (const float*)d_in[18];
    float* out = (float*)d_out;

    cudaFuncSetAttribute(k2_edge, cudaFuncAttributeMaxDynamicSharedMemorySize, K2_SMEM);
    cudaFuncSetAttribute(k3_node, cudaFuncAttributeMaxDynamicSharedMemorySize, K3_SMEM);

    int nsb = (NN + 1023) / 1024;

    k0_embed<<<(NN * DD + 255) / 256, 256>>>(atom_z, emb);
    k_hist<<<(NE + 255) / 256, 256>>>(ei);
    k_scan_part<<<nsb, 1024>>>();
    k1_AB<<<dim3((NN + 63) / 64, 2), 256>>>(0, eW1, eb1, bng, bnb);
    k_scan_top<<<1, 64>>>();
    k_scatter<<<(NE + 255) / 256, 256>>>(ei, eattr);

    k2_edge<<<K2_GRID, 256, K2_SMEM>>>(0, eW1, eW2, eb2);
    k3_node<<<(NN + 63) / 64, 256, K3_SMEM>>>(0, nW1, nb1, nW2, nb2, bng, bnb);
    for (int l = 1; l < NL; ++l) {
        k1_AB<<<dim3((NN + 63) / 64, 2), 256>>>(l, eW1, eb1, bng, bnb);
        k2_edge<<<K2_GRID, 256, K2_SMEM>>>(l, eW1, eW2, eb2);
        k3_node<<<(NN + 63) / 64, 256, K3_SMEM>>>(l, nW1, nb1, nW2, nb2, bng, bnb);
    }
    k5_pool<<<(NN * DD + 255) / 256, 256>>>(batch, bng, bnb);
    k6_out<<<GG, 128>>>(oW1, ob1, oW2, ob2, out);
}

// round 16
// speedup vs baseline: 1.2870x; 1.0160x over previous
#include <cuda_runtime.h>
#include <cuda_bf16.h>
#include <cuda_fp16.h>
#include <cstdint>
#include <math.h>

#define NN 50000
#define NE 800000
#define DD 64
#define HH 128
#define GG 128
#define NL 3
#define NT (NE / 64)

// ---------------- device scratch ----------------
__device__ float  g_x[NN * DD];             // pre-BN node features
__device__ __half g_AB[(size_t)NN * 256];   // [A=x'@W1a+b1 | B=x'@W1b] (fp16)
__device__ __half g_aggr[(size_t)NN * HH];  // fp16 message sums
__device__ float  g_stats[2][128];
__device__ float  g_pool[GG * DD];
__device__ float  g_cnt[GG];
__device__ int    g_hist[NN];
__device__ int    g_bsum[64];
__device__ int    g_ssrc[NE];               // dst-sorted edge arrays
__device__ int    g_sdst[NE];
__device__ float  g_seat[NE];

__device__ __forceinline__ float softplusf(float x) {
    return fmaxf(x, 0.0f) + __logf(1.0f + __expf(-fabsf(x)));
}
// fast softplus: 1 MUFU + Horner cubic for ln(1+u), u=e^-|x| in [0,1]
__device__ __forceinline__ float spf(float x) {
    float u = __expf(-fabsf(x));
    float lg = u * fmaf(u, fmaf(u, fmaf(u, -0.05781f, 0.22930f), -0.47833f), 0.99998f);
    return fmaxf(x, 0.0f) + lg;
}
__device__ __forceinline__ unsigned pack_bf16(float lo, float hi) {
    unsigned r;
    asm("cvt.rn.bf16x2.f32 %0, %1, %2;" : "=r"(r) : "f"(hi), "f"(lo));
    return r;
}
__device__ __forceinline__ void mma16bf(float* c, unsigned a0, unsigned a1,
                                        unsigned a2, unsigned a3,
                                        unsigned b0, unsigned b1) {
    asm volatile(
        "mma.sync.aligned.m16n8k16.row.col.f32.bf16.bf16.f32 "
        "{%0,%1,%2,%3}, {%4,%5,%6,%7}, {%8,%9}, {%0,%1,%2,%3};"
        : "+f"(c[0]), "+f"(c[1]), "+f"(c[2]), "+f"(c[3])
        : "r"(a0), "r"(a1), "r"(a2), "r"(a3), "r"(b0), "r"(b1));
}
__device__ __forceinline__ void bn_coeff(int l, int c, const float* gamma,
                                         const float* beta, float& S, float& T) {
    if (l == 0) { S = 1.0f; T = 0.0f; return; }
    const float* sb = g_stats[(l - 1) & 1];
    const float invN = 1.0f / (float)NN;
    float mu = sb[c] * invN;
    float var = sb[64 + c] * invN - mu * mu;
    float gi = gamma[(l - 1) * 64 + c] * rsqrtf(var + 1e-5f);
    S = gi;
    T = beta[(l - 1) * 64 + c] - mu * gi;
}

// ---------------- k0: embedding gather (+ zero g_hist, pool) ----------------
__global__ void k0_embed(const int* __restrict__ az, const float* __restrict__ emb) {
    int idx = blockIdx.x * blockDim.x + threadIdx.x;
    if (idx < NN) g_hist[idx] = 0;
    if (idx < GG * DD) g_pool[idx] = 0.0f;
    if (idx < GG) g_cnt[idx] = 0.0f;
    if (idx >= NN * DD) return;
    int i = idx >> 6, c = idx & 63;
    g_x[idx] = emb[az[i] * DD + c];
}

// ---------------- counting sort (materializes sorted arrays) ----------------
__global__ void k_hist(const int* __restrict__ ei) {
    int e = blockIdx.x * blockDim.x + threadIdx.x;
    if (e < NE) atomicAdd(&g_hist[ei[NE + e]], 1);
}
__global__ void k_scan_part() {
    __shared__ int wsum[32];
    int tid = threadIdx.x, lane = tid & 31, wid = tid >> 5;
    int i = blockIdx.x * 1024 + tid;
    int v = (i < NN) ? g_hist[i] : 0;
    int x = v;
    #pragma unroll
    for (int off = 1; off < 32; off <<= 1) {
        int y = __shfl_up_sync(0xffffffffu, x, off);
        if (lane >= off) x += y;
    }
    if (lane == 31) wsum[wid] = x;
    __syncthreads();
    if (wid == 0) {
        int s = wsum[lane];
        #pragma unroll
        for (int off = 1; off < 32; off <<= 1) {
            int y = __shfl_up_sync(0xffffffffu, s, off);
            if (lane >= off) s += y;
        }
        wsum[lane] = s;
    }
    __syncthreads();
    int woff = (wid > 0) ? wsum[wid - 1] : 0;
    if (i < NN) g_hist[i] = x - v + woff;   // block-local exclusive
    if (tid == 1023) g_bsum[blockIdx.x] = x + woff;
}
__global__ void k_scan_top() {
    __shared__ int s[64];
    int tid = threadIdx.x;
    int nb = (NN + 1023) / 1024;
    int v = (tid < nb) ? g_bsum[tid] : 0;
    s[tid] = v;
    __syncthreads();
    for (int off = 1; off < 64; off <<= 1) {
        int t = (tid >= off) ? s[tid - off] : 0;
        __syncthreads();
        s[tid] += t;
        __syncthreads();
    }
    if (tid < nb) g_bsum[tid] = s[tid] - v;
}
__global__ void k_scatter(const int* __restrict__ ei, const float* __restrict__ eattr) {
    int e = blockIdx.x * blockDim.x + threadIdx.x;
    if (e >= NE) return;
    int d = ei[NE + e];
    int pos = atomicAdd(&g_hist[d], 1) + g_bsum[d >> 10];
    g_ssrc[pos] = ei[e];
    g_sdst[pos] = d;
    g_seat[pos] = eattr[e];
}

// ---------------- k1: AB = x' @ [W1a | W1b] (per-half, bf16 mma); zeroes aggr + stats ----------------
__global__ void __launch_bounds__(256) k1_AB(int l, const float* __restrict__ W1,
                                             const float* __restrict__ b1,
                                             const float* __restrict__ gamma,
                                             const float* __restrict__ beta) {
    __shared__ __nv_bfloat16 xs[64 * 72];  // bf16, BN applied; pitch 72
    __shared__ __nv_bfloat16 ws[128 * 24]; // W1 chunk [col][k], pitch 24
    __shared__ float bnS[64], bnT[64];
    int tid = threadIdx.x, warp = tid >> 5, lane = tid & 31;
    int g = lane >> 2, tg = lane & 3;
    int n0 = blockIdx.x * 64;
    int half = blockIdx.y;
    int mb = (warp & 3) * 16, nb = (warp >> 2) * 64;

    if (tid < 64) bn_coeff(l, tid, gamma, beta, bnS[tid], bnT[tid]);
    if (blockIdx.x == 0 && half == 0 && tid < 128) g_stats[l & 1][tid] = 0.0f;
    // zero this block's slice of g_aggr (nodes n0..n0+63, cols half*64..+63) — fp16
    {
        uint4 z = make_uint4(0u, 0u, 0u, 0u);
        uint4* Az = (uint4*)g_aggr;            // node row = 16 uint4
        #pragma unroll
        for (int it = 0; it < 2; ++it) {
            int idx = tid + it * 256;          // 512
            int i = idx >> 3, qc = idx & 7;
            int node = n0 + i;
            if (node < NN) Az[(size_t)node * 16 + half * 8 + qc] = z;
        }
    }
    __syncthreads();   // bnS ready

    // stage xs as bf16 (float4 loads, BN applied)
    {
        const float4* X4 = (const float4*)g_x;
        #pragma unroll
        for (int it = 0; it < 4; ++it) {
            int idx = tid + it * 256;          // 1024
            int i = idx >> 4, q = idx & 15;
            int node = n0 + i;
            float4 v = make_float4(0.f, 0.f, 0.f, 0.f);
            if (node < NN) v = X4[(size_t)node * 16 + q];
            int c = q * 4;
            uint2 r;
            r.x = pack_bf16(v.x * bnS[c] + bnT[c],     v.y * bnS[c + 1] + bnT[c + 1]);
            r.y = pack_bf16(v.z * bnS[c + 2] + bnT[c + 2], v.w * bnS[c + 3] + bnT[c + 3]);
            *(uint2*)(xs + i * 72 + c) = r;
        }
    }
    const float* Wp = W1 + ((size_t)l * 129 + half * 64) * 128;

    float acc[8][4] = {};
    for (int k0 = 0; k0 < 64; k0 += 16) {
        __syncthreads();
        // stage W1 chunk as bf16 pairs: 128 cols x 8 pairs
        #pragma unroll
        for (int it = 0; it < 4; ++it) {
            int idx = tid + it * 256;          // 1024
            int col = idx & 127, kk2 = idx >> 7;
            int k = k0 + 2 * kk2;
            *(unsigned*)(ws + col * 24 + 2 * kk2) =
                pack_bf16(Wp[(size_t)k * 128 + col], Wp[(size_t)(k + 1) * 128 + col]);
        }
        __syncthreads();
        unsigned a0 = *(const unsigned*)(xs + (mb + g) * 72 + k0 + 2 * tg);
        unsigned a1 = *(const unsigned*)(xs + (mb + g + 8) * 72 + k0 + 2 * tg);
        unsigned a2 = *(const unsigned*)(xs + (mb + g) * 72 + k0 + 2 * tg + 8);
        unsigned a3 = *(const unsigned*)(xs + (mb + g + 8) * 72 + k0 + 2 * tg + 8);
        #pragma unroll
        for (int nt = 0; nt < 8; ++nt) {
            int col = nb + nt * 8 + g;
            unsigned b0 = *(const unsigned*)(ws + col * 24 + 2 * tg);
            unsigned b1r = *(const unsigned*)(ws + col * 24 + 2 * tg + 8);
            mma16bf(acc[nt], a0, a1, a2, a3, b0, b1r);
        }
    }
    int row0 = n0 + mb + g, row1 = row0 + 8;
    #pragma unroll
    for (int nt = 0; nt < 8; ++nt) {
        int c0 = nb + nt * 8 + 2 * tg;
        float bb0 = (half == 0) ? b1[l * 128 + c0] : 0.0f;
        float bb1 = (half == 0) ? b1[l * 128 + c0 + 1] : 0.0f;
        if (row0 < NN) {
            *(__half2*)(&g_AB[(size_t)row0 * 256 + half * 128 + c0]) =
                __floats2half2_rn(acc[nt][0] + bb0, acc[nt][1] + bb1);
        }
        if (row1 < NN) {
            *(__half2*)(&g_AB[(size_t)row1 * 256 + half * 128 + c0]) =
                __floats2half2_rn(acc[nt][2] + bb0, acc[nt][3] + bb1);
        }
    }
}

// ---------------- k2: persistent, software-pipelined edge MLP (32x32 warp tiles) ----------------
// smem: w2b bf16[128][136]@0 | h1 bf16[2][64*136]@34816 (m overlays in bf16)
//       srcs2[2][64]@69632 | es2[2][64]@70144 | dsts3[3][64]@70656
//       w1e[128]@71424 | b2s[128]@71936 ; total 72448
#define K2_GRID 444
#define K2_SMEM 72448
__global__ void __launch_bounds__(256, 3) k2_edge(int l,
                                                  const float* __restrict__ W1,
                                                  const float* __restrict__ W2,
                                                  const float* __restrict__ b2) {
    extern __shared__ char sm8[];
    __nv_bfloat16* w2b = (__nv_bfloat16*)sm8;
    __nv_bfloat16* h1base = (__nv_bfloat16*)(sm8 + 34816);
    int* srcs2 = (int*)(sm8 + 69632);
    float* es2 = (float*)(sm8 + 70144);
    int* dsts3 = (int*)(sm8 + 70656);
    float* w1e = (float*)(sm8 + 71424);
    float* b2s = (float*)(sm8 + 71936);

    int tid = threadIdx.x, warp = tid >> 5, lane = tid & 31;
    int g = lane >> 2, tg = lane & 3;
    int mb = (warp & 1) * 32, nb = (warp >> 1) * 32;   // 32x32 warp tile

    // stage W2 bf16 [col][k] pitch 136 (once)
    #pragma unroll
    for (int it = 0; it < 64; ++it) {
        int idx = tid + it * 256;
        int col = idx & 127, kk = idx >> 7;
        w2b[col * 136 + kk] = __float2bfloat16(W2[((size_t)l * 128 + kk) * 128 + col]);
    }
    if (tid < 128) w1e[tid] = W1[((size_t)l * 129 + 128) * 128 + tid];
    else b2s[tid - 128] = b2[l * 128 + (tid - 128)];

    const uint2* ABh = (const uint2*)g_AB;   // row = 64 uint2 (256 halves)
    const float4* w1e4 = (const float4*)w1e;

    auto stage = [&](int tt, int s, int ds) {
        int i4 = tt * 64 + tid;                // coalesced sorted-array reads
        srcs2[s * 64 + tid] = g_ssrc[i4];
        dsts3[ds * 64 + tid] = g_sdst[i4];
        es2[s * 64 + tid] = g_seat[i4];
    };
    auto phaseA = [&](__nv_bfloat16* H, int s, int ds) {
        int q = lane;
        int eb = warp * 8;
        const int* S = srcs2 + s * 64;
        const float* E = es2 + s * 64;
        const int* D = dsts3 + ds * 64;
        float4 w = w1e4[q];
        float4 aq = make_float4(0.f, 0.f, 0.f, 0.f);
        int prevd = -1;
        #pragma unroll
        for (int j = 0; j < 8; ++j) {
            int e = eb + j;
            int d = D[e];
            if (d != prevd) {
                uint2 ar = ABh[(size_t)d * 64 + q];
                float2 a01 = __half22float2(*(__half2*)&ar.x);
                float2 a23 = __half22float2(*(__half2*)&ar.y);
                aq = make_float4(a01.x, a01.y, a23.x, a23.y);
                prevd = d;
            }
            uint2 br = ABh[(size_t)S[e] * 64 + 32 + q];
            float2 b01 = __half22float2(*(__half2*)&br.x);
            float2 b23 = __half22float2(*(__half2*)&br.y);
            float ev = E[e];
            uint2 r;
            r.x = pack_bf16(spf(aq.x + b01.x + ev * w.x), spf(aq.y + b01.y + ev * w.y));
            r.y = pack_bf16(spf(aq.z + b23.x + ev * w.z), spf(aq.w + b23.y + ev * w.w));
            *(uint2*)(H + e * 136 + q * 4) = r;
        }
    };

    int t0 = blockIdx.x;
    if (t0 < NT && tid < 64) stage(t0, 0, 0);
    __syncthreads();
    if (t0 < NT) phaseA(h1base, 0, 0);
    if (t0 + K2_GRID < NT && tid < 64) stage(t0 + K2_GRID, 1, 1);
    __syncthreads();

    int i = 0;
    for (int t = t0; t < NT; t += K2_GRID, ++i) {
        int p = i & 1, q2 = 1 - p;
        int d_cur = i % 3, d_nxt = (i + 1) % 3, d_stg = (i + 2) % 3;
        __nv_bfloat16* h1p = h1base + p * (64 * 136);
        __nv_bfloat16* h1q = h1base + q2 * (64 * 136);

        // 1. phase B on h1p: warp = 32 rows x 32 cols
        float acc[2][4][4] = {};
        #pragma unroll
        for (int kc = 0; kc < 128; kc += 16) {
            unsigned a[2][4];
            #pragma unroll
            for (int mt = 0; mt < 2; ++mt) {
                int r0 = mb + mt * 16 + g;
                a[mt][0] = *(const unsigned*)(h1p + r0 * 136 + kc + 2 * tg);
                a[mt][1] = *(const unsigned*)(h1p + (r0 + 8) * 136 + kc + 2 * tg);
                a[mt][2] = *(const unsigned*)(h1p + r0 * 136 + kc + 2 * tg + 8);
                a[mt][3] = *(const unsigned*)(h1p + (r0 + 8) * 136 + kc + 2 * tg + 8);
            }
            #pragma unroll
            for (int nt = 0; nt < 4; ++nt) {
                int col = nb + nt * 8 + g;
                unsigned b0 = *(const unsigned*)(w2b + col * 136 + kc + 2 * tg);
                unsigned b1r = *(const unsigned*)(w2b + col * 136 + kc + 2 * tg + 8);
                mma16bf(acc[0][nt], a[0][0], a[0][1], a[0][2], a[0][3], b0, b1r);
                mma16bf(acc[1][nt], a[1][0], a[1][1], a[1][2], a[1][3], b0, b1r);
            }
        }

        // 2. phase A for t+G into h1q (overlaps MMA tail)
        int tn = t + K2_GRID;
        if (tn < NT) phaseA(h1q, q2, d_nxt);

        // 3. stage idx for t+2G
        int ts = t + 2 * K2_GRID;
        if (ts < NT && tid < 64) stage(ts, p, d_stg);
        __syncthreads();

        // 4. epilogue: m = spf(D + b2) -> bf16 over h1p
        #pragma unroll
        for (int mt = 0; mt < 2; ++mt) {
            int r0 = mb + mt * 16 + g;
            #pragma unroll
            for (int nt = 0; nt < 4; ++nt) {
                int c0 = nb + nt * 8 + 2 * tg;
                unsigned u0 = pack_bf16(spf(acc[mt][nt][0] + b2s[c0]),
                                        spf(acc[mt][nt][1] + b2s[c0 + 1]));
                unsigned u1 = pack_bf16(spf(acc[mt][nt][2] + b2s[c0]),
                                        spf(acc[mt][nt][3] + b2s[c0 + 1]));
                *(unsigned*)(h1p + r0 * 136 + c0) = u0;
                *(unsigned*)(h1p + (r0 + 8) * 136 + c0) = u1;
            }
        }
        __syncthreads();

        // 5. segmented reduction over sorted dst runs; half2 atomics (2 cols/thread)
        {
            const int* D = dsts3 + d_cur * 64;
            int c2 = tid & 63;                 // column pair
            int r0 = (tid >> 6) * 16;          // 4 row-groups of 16
            float2 racc = make_float2(0.f, 0.f);
            int prev = D[r0];
            #pragma unroll 4
            for (int r = r0; r < r0 + 16; ++r) {
                int d = D[r];
                if (d != prev) {
                    atomicAdd((__half2*)&g_aggr[(size_t)prev * 128 + 2 * c2],
                              __floats2half2_rn(racc.x, racc.y));
                    racc = make_float2(0.f, 0.f);
                    prev = d;
                }
                unsigned mm = *(const unsigned*)(h1p + r * 136 + 2 * c2);
                float2 f = __bfloat1622float2(*(__nv_bfloat162*)&mm);
                racc.x += f.x;
                racc.y += f.y;
            }
            atomicAdd((__half2*)&g_aggr[(size_t)prev * 128 + 2 * c2],
                      __floats2half2_rn(racc.x, racc.y));
        }
        __syncthreads();
    }
}

// ---------------- k3: node MLP (M=64, bf16 mma, bf16 staging) + residual + BN stats ----------------
// dyn smem: hsb bf16[64][200]@0 (25600) | xres f32[64][68]@25600 (17408)
//           ws bf16[128*24]@43008 (6144) | ssum@49152 | ssq@49408 | bnS@49664 | bnT@49920
//           total 50176
#define K3_SMEM 50176
__global__ void __launch_bounds__(256, 3) k3_node(int l, const float* __restrict__ W1,
                                                  const float* __restrict__ b1,
                                                  const float* __restrict__ W2,
                                                  const float* __restrict__ b2,
                                                  const float* __restrict__ gamma,
                                                  const float* __restrict__ beta) {
    extern __shared__ char sm3[];
    __nv_bfloat16* hsb = (__nv_bfloat16*)sm3;
    float* xres = (float*)(sm3 + 25600);
    __nv_bfloat16* ws = (__nv_bfloat16*)(sm3 + 43008);
    float* ssum = (float*)(sm3 + 49152);
    float* ssq = (float*)(sm3 + 49408);
    float* bnS = (float*)(sm3 + 49664);
    float* bnT = (float*)(sm3 + 49920);

    int tid = threadIdx.x, warp = tid >> 5, lane = tid & 31;
    int g = lane >> 2, tg = lane & 3;
    int mb = (warp & 3) * 16, nb = (warp >> 2) * 64;
    int n0 = blockIdx.x * 64;

    if (tid < 64) {
        ssum[tid] = 0.0f; ssq[tid] = 0.0f;
        bn_coeff(l, tid, gamma, beta, bnS[tid], bnT[tid]);
    }
    __syncthreads();

    // stage: cols 0..63 = x' (bf16 + fp32 copy), cols 64..191 = aggr (bf16)
    for (int it = 0; it < 48; ++it) {
        int idx = tid + it * 256;              // 12288
        int i = idx / 192, c = idx - i * 192;
        int node = n0 + i;
        float v = 0.0f;
        if (node < NN) {
            if (c < 64) v = g_x[(size_t)node * DD + c] * bnS[c] + bnT[c];
            else v = __half2float(g_aggr[(size_t)node * HH + (c - 64)]);
        }
        hsb[i * 200 + c] = __float2bfloat16(v);
        if (c < 64) xres[i * 68 + c] = v;
    }

    // GEMM1: t = spf([x'|aggr] @ nW1 + b1), M=64, N=128, K=192, bf16 mma
    float acc[8][4] = {};
    for (int k0 = 0; k0 < 192; k0 += 16) {
        __syncthreads();
        #pragma unroll
        for (int it = 0; it < 4; ++it) {
            int idx = tid + it * 256;          // 1024
            int col = idx & 127, kk2 = idx >> 7;
            int k = k0 + 2 * kk2;
            *(unsigned*)(ws + col * 24 + 2 * kk2) =
                pack_bf16(W1[((size_t)l * 192 + k) * 128 + col],
                          W1[((size_t)l * 192 + k + 1) * 128 + col]);
        }
        __syncthreads();
        unsigned a0 = *(const unsigned*)(hsb + (mb + g) * 200 + k0 + 2 * tg);
        unsigned a1 = *(const unsigned*)(hsb + (mb + g + 8) * 200 + k0 + 2 * tg);
        unsigned a2 = *(const unsigned*)(hsb + (mb + g) * 200 + k0 + 2 * tg + 8);
        unsigned a3 = *(const unsigned*)(hsb + (mb + g + 8) * 200 + k0 + 2 * tg + 8);
        #pragma unroll
        for (int nt = 0; nt < 8; ++nt) {
            int col = nb + nt * 8 + g;
            unsigned b0 = *(const unsigned*)(ws + col * 24 + 2 * tg);
            unsigned b1r = *(const unsigned*)(ws + col * 24 + 2 * tg + 8);
            mma16bf(acc[nt], a0, a1, a2, a3, b0, b1r);
        }
    }
    __syncthreads();
    // t -> bf16 into hsb cols 64..191 (aggr fully consumed)
    #pragma unroll
    for (int nt = 0; nt < 8; ++nt) {
        int c0 = nb + nt * 8 + 2 * tg;
        unsigned u0 = pack_bf16(spf(acc[nt][0] + b1[l * 128 + c0]),
                                spf(acc[nt][1] + b1[l * 128 + c0 + 1]));
        unsigned u1 = pack_bf16(spf(acc[nt][2] + b1[l * 128 + c0]),
                                spf(acc[nt][3] + b1[l * 128 + c0 + 1]));
        *(unsigned*)(hsb + (mb + g) * 200 + 64 + c0) = u0;
        *(unsigned*)(hsb + (mb + g + 8) * 200 + 64 + c0) = u1;
    }

    // GEMM2: y = t @ nW2 + b2 + x', M=64, N=64, K=128, bf16 mma
    int nb2 = (warp >> 2) * 32;
    float acc2[4][4] = {};
    for (int k0 = 0; k0 < 128; k0 += 16) {
        __syncthreads();
        #pragma unroll
        for (int it = 0; it < 2; ++it) {
            int idx = tid + it * 256;          // 512
            int col = idx & 63, kk2 = idx >> 6;
            int k = k0 + 2 * kk2;
            *(unsigned*)(ws + col * 24 + 2 * kk2) =
                pack_bf16(W2[((size_t)l * 128 + k) * 64 + col],
                          W2[((size_t)l * 128 + k + 1) * 64 + col]);
        }
        __syncthreads();
        unsigned a0 = *(const unsigned*)(hsb + (mb + g) * 200 + 64 + k0 + 2 * tg);
        unsigned a1 = *(const unsigned*)(hsb + (mb + g + 8) * 200 + 64 + k0 + 2 * tg);
        unsigned a2 = *(const unsigned*)(hsb + (mb + g) * 200 + 64 + k0 + 2 * tg + 8);
        unsigned a3 = *(const unsigned*)(hsb + (mb + g + 8) * 200 + 64 + k0 + 2 * tg + 8);
        #pragma unroll
        for (int nt = 0; nt < 4; ++nt) {
            int col = nb2 + nt * 8 + g;
            unsigned b0 = *(const unsigned*)(ws + col * 24 + 2 * tg);
            unsigned b1r = *(const unsigned*)(ws + col * 24 + 2 * tg + 8);
            mma16bf(acc2[nt], a0, a1, a2, a3, b0, b1r);
        }
    }

    #pragma unroll
    for (int nt = 0; nt < 4; ++nt) {
        int c0 = nb2 + nt * 8 + 2 * tg;
        float bb0 = b2[l * 64 + c0], bb1 = b2[l * 64 + c0 + 1];
        int row0 = mb + g, row1 = mb + g + 8;
        int node0 = n0 + row0, node1 = n0 + row1;
        if (node0 < NN) {
            float y0 = acc2[nt][0] + bb0 + xres[row0 * 68 + c0];
            float y1 = acc2[nt][1] + bb1 + xres[row0 * 68 + c0 + 1];
            g_x[(size_t)node0 * DD + c0] = y0;
            g_x[(size_t)node0 * DD + c0 + 1] = y1;
            atomicAdd(&ssum[c0], y0);     atomicAdd(&ssum[c0 + 1], y1);
            atomicAdd(&ssq[c0], y0 * y0); atomicAdd(&ssq[c0 + 1], y1 * y1);
        }
        if (node1 < NN) {
            float y2 = acc2[nt][2] + bb0 + xres[row1 * 68 + c0];
            float y3 = acc2[nt][3] + bb1 + xres[row1 * 68 + c0 + 1];
            g_x[(size_t)node1 * DD + c0] = y2;
            g_x[(size_t)node1 * DD + c0 + 1] = y3;
            atomicAdd(&ssum[c0], y2);     atomicAdd(&ssum[c0 + 1], y3);
            atomicAdd(&ssq[c0], y2 * y2); atomicAdd(&ssq[c0 + 1], y3 * y3);
        }
    }
    __syncthreads();
    if (tid < 64) {
        atomicAdd(&g_stats[l & 1][tid], ssum[tid]);
        atomicAdd(&g_stats[l & 1][64 + tid], ssq[tid]);
    }
}

// ---------------- k5: global mean pool (applies final BN) ----------------
__global__ void k5_pool(const int* __restrict__ batch,
                        const float* __restrict__ gamma, const float* __restrict__ beta) {
    int idx = blockIdx.x * blockDim.x + threadIdx.x;
    if (idx >= NN * DD) return;
    int i = idx >> 6, c = idx & 63;
    const float* sb = g_stats[(NL - 1) & 1];
    const float invN = 1.0f / (float)NN;
    float mu = sb[c] * invN;
    float var = sb[64 + c] * invN - mu * mu;
    float gi = gamma[(NL - 1) * 64 + c] * rsqrtf(var + 1e-5f);
    float v = g_x[idx] * gi + (beta[(NL - 1) * 64 + c] - mu * gi);
    int b = batch[i];
    atomicAdd(&g_pool[b * DD + c], v);
    if (c == 0) atomicAdd(&g_cnt[b], 1.0f);
}

// ---------------- k6: output MLP ----------------
__global__ void k6_out(const float* __restrict__ W1, const float* __restrict__ b1,
                       const float* __restrict__ W2, const float* __restrict__ b2,
                       float* __restrict__ out) {
    __shared__ float p[64];
    __shared__ float red[128];
    int g = blockIdx.x, c = threadIdx.x;
    if (c < 64) p[c] = g_pool[g * DD + c] / fmaxf(g_cnt[g], 1.0f);
    __syncthreads();
    float acc = b1[c];
    #pragma unroll
    for (int d = 0; d < 64; ++d) acc = fmaf(p[d], W1[d * 128 + c], acc);
    red[c] = softplusf(acc) * W2[c];
    __syncthreads();
    for (int s = 64; s > 0; s >>= 1) {
        if (c < s) red[c] += red[c + s];
        __syncthreads();
    }
    if (c == 0) out[g] = red[0] + b2[0];
}

// ---------------- launcher ----------------
extern "C" void kernel_launch(void* const* d_in, const int* in_sizes, int n_in,
                              void* d_out, int out_size) {
    const int*   atom_z = (const int*)  d_in[0];
    const int*   ei     = (const int*)  d_in[1];
    const float* eattr  = (const float*)d_in[2];
    const int*   batch  = (const int*)  d_in[3];
    const float* emb    = (const float*)d_in[4];
    const float* eW1    = (const float*)d_in[5];
    const float* eb1    = (const float*)d_in[6];
    const float* eW2    = (const float*)d_in[7];
    const float* eb2    = (const float*)d_in[8];
    const float* nW1    = (const float*)d_in[9];
    const float* nb1    = (const float*)d_in[10];
    const float* nW2    = (const float*)d_in[11];
    const float* nb2    = (const float*)d_in[12];
    const float* bng    = (const float*)d_in[13];
    const float* bnb    = (const float*)d_in[14];
    const float* oW1    = (const float*)d_in[15];
    const float* ob1    = (const float*)d_in[16];
    const float* oW2    = (const float*)d_in[17];
    const float* ob2    = (const float*)d_in[18];
    float* out = (float*)d_out;

    cudaFuncSetAttribute(k2_edge, cudaFuncAttributeMaxDynamicSharedMemorySize, K2_SMEM);
    cudaFuncSetAttribute(k3_node, cudaFuncAttributeMaxDynamicSharedMemorySize, K3_SMEM);

    int nsb = (NN + 1023) / 1024;

    k0_embed<<<(NN * DD + 255) / 256, 256>>>(atom_z, emb);
    k_hist<<<(NE + 255) / 256, 256>>>(ei);
    k_scan_part<<<nsb, 1024>>>();
    k1_AB<<<dim3((NN + 63) / 64, 2), 256>>>(0, eW1, eb1, bng, bnb);
    k_scan_top<<<1, 64>>>();
    k_scatter<<<(NE + 255) / 256, 256>>>(ei, eattr);

    k2_edge<<<K2_GRID, 256, K2_SMEM>>>(0, eW1, eW2, eb2);
    k3_node<<<(NN + 63) / 64, 256, K3_SMEM>>>(0, nW1, nb1, nW2, nb2, bng, bnb);
    for (int l = 1; l < NL; ++l) {
        k1_AB<<<dim3((NN + 63) / 64, 2), 256>>>(l, eW1, eb1, bng, bnb);
        k2_edge<<<K2_GRID, 256, K2_SMEM>>>(l, eW1, eW2, eb2);
        k3_node<<<(NN + 63) / 64, 256, K3_SMEM>>>(l, nW1, nb1, nW2, nb2, bng, bnb);
    }
    k5_pool<<<(NN * DD + 255) / 256, 256>>>(batch, bng, bnb);
    k6_out<<<GG, 128>>>(oW1, ob1, oW2, ob2, out);
}

// round 17
// speedup vs baseline: 1.3023x; 1.0119x over previous
#include <cuda_runtime.h>
#include <cuda_bf16.h>
#include <cuda_fp16.h>
#include <cstdint>
#include <math.h>

#define NN 50000
#define NE 800000
#define DD 64
#define HH 128
#define GG 128
#define NL 3
#define NT (NE / 64)

// ---------------- device scratch ----------------
__device__ float  g_x[NN * DD];             // pre-BN node features
__device__ __half g_AB[(size_t)NN * 256];   // [A=x'@W1a+b1 | B=x'@W1b] (fp16)
__device__ __half g_aggr[(size_t)NN * HH];  // fp16 message sums
__device__ float  g_stats[2][128];
__device__ float  g_pool[GG * DD];
__device__ float  g_cnt[GG];
__device__ int    g_hist[NN];
__device__ int    g_bsum[64];
__device__ int    g_ssrc[NE];               // dst-sorted edge arrays
__device__ int    g_sdst[NE];
__device__ float  g_seat[NE];

__device__ __forceinline__ float softplusf(float x) {
    return fmaxf(x, 0.0f) + __logf(1.0f + __expf(-fabsf(x)));
}
// fast softplus: 1 MUFU + Horner cubic for ln(1+u), u=e^-|x| in [0,1]
__device__ __forceinline__ float spf(float x) {
    float u = __expf(-fabsf(x));
    float lg = u * fmaf(u, fmaf(u, fmaf(u, -0.05781f, 0.22930f), -0.47833f), 0.99998f);
    return fmaxf(x, 0.0f) + lg;
}
__device__ __forceinline__ unsigned pack_bf16(float lo, float hi) {
    unsigned r;
    asm("cvt.rn.bf16x2.f32 %0, %1, %2;" : "=r"(r) : "f"(hi), "f"(lo));
    return r;
}
__device__ __forceinline__ void mma16bf(float* c, unsigned a0, unsigned a1,
                                        unsigned a2, unsigned a3,
                                        unsigned b0, unsigned b1) {
    asm volatile(
        "mma.sync.aligned.m16n8k16.row.col.f32.bf16.bf16.f32 "
        "{%0,%1,%2,%3}, {%4,%5,%6,%7}, {%8,%9}, {%0,%1,%2,%3};"
        : "+f"(c[0]), "+f"(c[1]), "+f"(c[2]), "+f"(c[3])
        : "r"(a0), "r"(a1), "r"(a2), "r"(a3), "r"(b0), "r"(b1));
}
__device__ __forceinline__ void ldsm_x4(unsigned* r, uint32_t addr) {
    asm volatile(
        "ldmatrix.sync.aligned.m8n8.x4.shared.b16 {%0,%1,%2,%3}, [%4];"
        : "=r"(r[0]), "=r"(r[1]), "=r"(r[2]), "=r"(r[3]) : "r"(addr));
}
__device__ __forceinline__ uint32_t smem_u32(const void* p) {
    uint32_t a;
    asm("{ .reg .u64 t; cvta.to.shared.u64 t, %1; cvt.u32.u64 %0, t; }" : "=r"(a) : "l"(p));
    return a;
}
__device__ __forceinline__ void bn_coeff(int l, int c, const float* gamma,
                                         const float* beta, float& S, float& T) {
    if (l == 0) { S = 1.0f; T = 0.0f; return; }
    const float* sb = g_stats[(l - 1) & 1];
    const float invN = 1.0f / (float)NN;
    float mu = sb[c] * invN;
    float var = sb[64 + c] * invN - mu * mu;
    float gi = gamma[(l - 1) * 64 + c] * rsqrtf(var + 1e-5f);
    S = gi;
    T = beta[(l - 1) * 64 + c] - mu * gi;
}

// ---------------- k0: embedding gather (+ zero g_hist, pool) ----------------
__global__ void k0_embed(const int* __restrict__ az, const float* __restrict__ emb) {
    int idx = blockIdx.x * blockDim.x + threadIdx.x;
    if (idx < NN) g_hist[idx] = 0;
    if (idx < GG * DD) g_pool[idx] = 0.0f;
    if (idx < GG) g_cnt[idx] = 0.0f;
    if (idx >= NN * DD) return;
    int i = idx >> 6, c = idx & 63;
    g_x[idx] = emb[az[i] * DD + c];
}

// ---------------- counting sort (materializes sorted arrays) ----------------
__global__ void k_hist(const int* __restrict__ ei) {
    int e = blockIdx.x * blockDim.x + threadIdx.x;
    if (e < NE) atomicAdd(&g_hist[ei[NE + e]], 1);
}
__global__ void k_scan_part() {
    __shared__ int wsum[32];
    int tid = threadIdx.x, lane = tid & 31, wid = tid >> 5;
    int i = blockIdx.x * 1024 + tid;
    int v = (i < NN) ? g_hist[i] : 0;
    int x = v;
    #pragma unroll
    for (int off = 1; off < 32; off <<= 1) {
        int y = __shfl_up_sync(0xffffffffu, x, off);
        if (lane >= off) x += y;
    }
    if (lane == 31) wsum[wid] = x;
    __syncthreads();
    if (wid == 0) {
        int s = wsum[lane];
        #pragma unroll
        for (int off = 1; off < 32; off <<= 1) {
            int y = __shfl_up_sync(0xffffffffu, s, off);
            if (lane >= off) s += y;
        }
        wsum[lane] = s;
    }
    __syncthreads();
    int woff = (wid > 0) ? wsum[wid - 1] : 0;
    if (i < NN) g_hist[i] = x - v + woff;   // block-local exclusive
    if (tid == 1023) g_bsum[blockIdx.x] = x + woff;
}
__global__ void k_scan_top() {
    __shared__ int s[64];
    int tid = threadIdx.x;
    int nb = (NN + 1023) / 1024;
    int v = (tid < nb) ? g_bsum[tid] : 0;
    s[tid] = v;
    __syncthreads();
    for (int off = 1; off < 64; off <<= 1) {
        int t = (tid >= off) ? s[tid - off] : 0;
        __syncthreads();
        s[tid] += t;
        __syncthreads();
    }
    if (tid < nb) g_bsum[tid] = s[tid] - v;
}
__global__ void k_scatter(const int* __restrict__ ei, const float* __restrict__ eattr) {
    int e = blockIdx.x * blockDim.x + threadIdx.x;
    if (e >= NE) return;
    int d = ei[NE + e];
    int pos = atomicAdd(&g_hist[d], 1) + g_bsum[d >> 10];
    g_ssrc[pos] = ei[e];
    g_sdst[pos] = d;
    g_seat[pos] = eattr[e];
}

// ---------------- k1: AB = x' @ [W1a | W1b] (per-half, bf16 mma); zeroes aggr + stats ----------------
__global__ void __launch_bounds__(256) k1_AB(int l, const float* __restrict__ W1,
                                             const float* __restrict__ b1,
                                             const float* __restrict__ gamma,
                                             const float* __restrict__ beta) {
    __shared__ __nv_bfloat16 xs[64 * 72];  // bf16, BN applied; pitch 72
    __shared__ __nv_bfloat16 ws[128 * 24]; // W1 chunk [col][k], pitch 24
    __shared__ float bnS[64], bnT[64];
    int tid = threadIdx.x, warp = tid >> 5, lane = tid & 31;
    int g = lane >> 2, tg = lane & 3;
    int n0 = blockIdx.x * 64;
    int half = blockIdx.y;
    int mb = (warp & 3) * 16, nb = (warp >> 2) * 64;

    if (tid < 64) bn_coeff(l, tid, gamma, beta, bnS[tid], bnT[tid]);
    if (blockIdx.x == 0 && half == 0 && tid < 128) g_stats[l & 1][tid] = 0.0f;
    // zero this block's slice of g_aggr (nodes n0..n0+63, cols half*64..+63) — fp16
    {
        uint4 z = make_uint4(0u, 0u, 0u, 0u);
        uint4* Az = (uint4*)g_aggr;            // node row = 16 uint4
        #pragma unroll
        for (int it = 0; it < 2; ++it) {
            int idx = tid + it * 256;          // 512
            int i = idx >> 3, qc = idx & 7;
            int node = n0 + i;
            if (node < NN) Az[(size_t)node * 16 + half * 8 + qc] = z;
        }
    }
    __syncthreads();   // bnS ready

    // stage xs as bf16 (float4 loads, BN applied)
    {
        const float4* X4 = (const float4*)g_x;
        #pragma unroll
        for (int it = 0; it < 4; ++it) {
            int idx = tid + it * 256;          // 1024
            int i = idx >> 4, q = idx & 15;
            int node = n0 + i;
            float4 v = make_float4(0.f, 0.f, 0.f, 0.f);
            if (node < NN) v = X4[(size_t)node * 16 + q];
            int c = q * 4;
            uint2 r;
            r.x = pack_bf16(v.x * bnS[c] + bnT[c],     v.y * bnS[c + 1] + bnT[c + 1]);
            r.y = pack_bf16(v.z * bnS[c + 2] + bnT[c + 2], v.w * bnS[c + 3] + bnT[c + 3]);
            *(uint2*)(xs + i * 72 + c) = r;
        }
    }
    const float* Wp = W1 + ((size_t)l * 129 + half * 64) * 128;

    float acc[8][4] = {};
    for (int k0 = 0; k0 < 64; k0 += 16) {
        __syncthreads();
        // stage W1 chunk as bf16 pairs: 128 cols x 8 pairs
        #pragma unroll
        for (int it = 0; it < 4; ++it) {
            int idx = tid + it * 256;          // 1024
            int col = idx & 127, kk2 = idx >> 7;
            int k = k0 + 2 * kk2;
            *(unsigned*)(ws + col * 24 + 2 * kk2) =
                pack_bf16(Wp[(size_t)k * 128 + col], Wp[(size_t)(k + 1) * 128 + col]);
        }
        __syncthreads();
        unsigned a0 = *(const unsigned*)(xs + (mb + g) * 72 + k0 + 2 * tg);
        unsigned a1 = *(const unsigned*)(xs + (mb + g + 8) * 72 + k0 + 2 * tg);
        unsigned a2 = *(const unsigned*)(xs + (mb + g) * 72 + k0 + 2 * tg + 8);
        unsigned a3 = *(const unsigned*)(xs + (mb + g + 8) * 72 + k0 + 2 * tg + 8);
        #pragma unroll
        for (int nt = 0; nt < 8; ++nt) {
            int col = nb + nt * 8 + g;
            unsigned b0 = *(const unsigned*)(ws + col * 24 + 2 * tg);
            unsigned b1r = *(const unsigned*)(ws + col * 24 + 2 * tg + 8);
            mma16bf(acc[nt], a0, a1, a2, a3, b0, b1r);
        }
    }
    int row0 = n0 + mb + g, row1 = row0 + 8;
    #pragma unroll
    for (int nt = 0; nt < 8; ++nt) {
        int c0 = nb + nt * 8 + 2 * tg;
        float bb0 = (half == 0) ? b1[l * 128 + c0] : 0.0f;
        float bb1 = (half == 0) ? b1[l * 128 + c0 + 1] : 0.0f;
        if (row0 < NN) {
            *(__half2*)(&g_AB[(size_t)row0 * 256 + half * 128 + c0]) =
                __floats2half2_rn(acc[nt][0] + bb0, acc[nt][1] + bb1);
        }
        if (row1 < NN) {
            *(__half2*)(&g_AB[(size_t)row1 * 256 + half * 128 + c0]) =
                __floats2half2_rn(acc[nt][2] + bb0, acc[nt][3] + bb1);
        }
    }
}

// ---------------- k2: persistent, software-pipelined edge MLP (ldmatrix phase B) ----------------
// smem: w2b bf16[128][136]@0 | h1 bf16[2][64*136]@34816 (m overlays in bf16)
//       srcs2[2][64]@69632 | es2[2][64]@70144 | dsts3[3][64]@70656
//       w1e[128]@71424 | b2s[128]@71936 ; total 72448
#define K2_GRID 456
#define K2_SMEM 72448
__global__ void __launch_bounds__(256, 3) k2_edge(int l,
                                                  const float* __restrict__ W1,
                                                  const float* __restrict__ W2,
                                                  const float* __restrict__ b2) {
    extern __shared__ char sm8[];
    __nv_bfloat16* w2b = (__nv_bfloat16*)sm8;
    __nv_bfloat16* h1base = (__nv_bfloat16*)(sm8 + 34816);
    int* srcs2 = (int*)(sm8 + 69632);
    float* es2 = (float*)(sm8 + 70144);
    int* dsts3 = (int*)(sm8 + 70656);
    float* w1e = (float*)(sm8 + 71424);
    float* b2s = (float*)(sm8 + 71936);

    int tid = threadIdx.x, warp = tid >> 5, lane = tid & 31;
    int g = lane >> 2, tg = lane & 3;
    int mb = (warp & 1) * 32, nb = (warp >> 1) * 32;   // 32x32 warp tile

    // stage W2 bf16 [col][k] pitch 136 (once)
    #pragma unroll
    for (int it = 0; it < 64; ++it) {
        int idx = tid + it * 256;
        int col = idx & 127, kk = idx >> 7;
        w2b[col * 136 + kk] = __float2bfloat16(W2[((size_t)l * 128 + kk) * 128 + col]);
    }
    if (tid < 128) w1e[tid] = W1[((size_t)l * 129 + 128) * 128 + tid];
    else b2s[tid - 128] = b2[l * 128 + (tid - 128)];

    const uint2* ABh = (const uint2*)g_AB;   // row = 64 uint2 (256 halves)
    const float4* w1e4 = (const float4*)w1e;

    // ldmatrix base addresses (bytes)
    uint32_t h1u = smem_u32(h1base);
    uint32_t w2u = smem_u32(w2b);
    int arow = lane & 15, acol8 = (lane >> 4) << 3;
    uint32_t aoff0 = (uint32_t)(((mb + arow) * 136 + acol8) * 2);
    uint32_t aoff1 = aoff0 + 16 * 136 * 2;
    uint32_t boff = w2u + (uint32_t)((nb + lane) * 136 * 2);

    auto stage = [&](int tt, int s, int ds) {
        int i4 = tt * 64 + tid;                // coalesced sorted-array reads
        srcs2[s * 64 + tid] = g_ssrc[i4];
        dsts3[ds * 64 + tid] = g_sdst[i4];
        es2[s * 64 + tid] = g_seat[i4];
    };
    auto phaseA = [&](__nv_bfloat16* H, int s, int ds) {
        int q = lane;
        int eb = warp * 8;
        const int* S = srcs2 + s * 64;
        const float* E = es2 + s * 64;
        const int* D = dsts3 + ds * 64;
        float4 w = w1e4[q];
        float4 aq = make_float4(0.f, 0.f, 0.f, 0.f);
        int prevd = -1;
        #pragma unroll
        for (int j = 0; j < 8; ++j) {
            int e = eb + j;
            int d = D[e];
            if (d != prevd) {
                uint2 ar = ABh[(size_t)d * 64 + q];
                float2 a01 = __half22float2(*(__half2*)&ar.x);
                float2 a23 = __half22float2(*(__half2*)&ar.y);
                aq = make_float4(a01.x, a01.y, a23.x, a23.y);
                prevd = d;
            }
            uint2 br = ABh[(size_t)S[e] * 64 + 32 + q];
            float2 b01 = __half22float2(*(__half2*)&br.x);
            float2 b23 = __half22float2(*(__half2*)&br.y);
            float ev = E[e];
            uint2 r;
            r.x = pack_bf16(spf(aq.x + b01.x + ev * w.x), spf(aq.y + b01.y + ev * w.y));
            r.y = pack_bf16(spf(aq.z + b23.x + ev * w.z), spf(aq.w + b23.y + ev * w.w));
            *(uint2*)(H + e * 136 + q * 4) = r;
        }
    };

    int t0 = blockIdx.x;
    if (t0 < NT && tid < 64) stage(t0, 0, 0);
    __syncthreads();
    if (t0 < NT) phaseA(h1base, 0, 0);
    if (t0 + K2_GRID < NT && tid < 64) stage(t0 + K2_GRID, 1, 1);
    __syncthreads();

    int i = 0;
    for (int t = t0; t < NT; t += K2_GRID, ++i) {
        int p = i & 1, q2 = 1 - p;
        int d_cur = i % 3, d_nxt = (i + 1) % 3, d_stg = (i + 2) % 3;
        __nv_bfloat16* h1p = h1base + p * (64 * 136);
        __nv_bfloat16* h1q = h1base + q2 * (64 * 136);
        uint32_t h1pu = h1u + (uint32_t)(p * (64 * 136 * 2));

        // 1. phase B on h1p: warp = 32 rows x 32 cols, ldmatrix operands
        float acc[2][4][4] = {};
        #pragma unroll
        for (int kc = 0; kc < 128; kc += 16) {
            unsigned a[2][4], bv0[4], bv1[4];
            ldsm_x4(a[0], h1pu + aoff0 + kc * 2);
            ldsm_x4(a[1], h1pu + aoff1 + kc * 2);
            ldsm_x4(bv0, boff + kc * 2);
            ldsm_x4(bv1, boff + kc * 2 + 16);
            #pragma unroll
            for (int nt = 0; nt < 4; ++nt) {
                mma16bf(acc[0][nt], a[0][0], a[0][1], a[0][2], a[0][3], bv0[nt], bv1[nt]);
                mma16bf(acc[1][nt], a[1][0], a[1][1], a[1][2], a[1][3], bv0[nt], bv1[nt]);
            }
        }

        // 2. phase A for t+G into h1q (overlaps MMA tail)
        int tn = t + K2_GRID;
        if (tn < NT) phaseA(h1q, q2, d_nxt);

        // 3. stage idx for t+2G
        int ts = t + 2 * K2_GRID;
        if (ts < NT && tid < 64) stage(ts, p, d_stg);
        __syncthreads();

        // 4. epilogue: m = spf(D + b2) -> bf16 over h1p
        #pragma unroll
        for (int mt = 0; mt < 2; ++mt) {
            int r0 = mb + mt * 16 + g;
            #pragma unroll
            for (int nt = 0; nt < 4; ++nt) {
                int c0 = nb + nt * 8 + 2 * tg;
                unsigned u0 = pack_bf16(spf(acc[mt][nt][0] + b2s[c0]),
                                        spf(acc[mt][nt][1] + b2s[c0 + 1]));
                unsigned u1 = pack_bf16(spf(acc[mt][nt][2] + b2s[c0]),
                                        spf(acc[mt][nt][3] + b2s[c0 + 1]));
                *(unsigned*)(h1p + r0 * 136 + c0) = u0;
                *(unsigned*)(h1p + (r0 + 8) * 136 + c0) = u1;
            }
        }
        __syncthreads();

        // 5. segmented reduction over sorted dst runs; half2 atomics (2 cols/thread)
        {
            const int* D = dsts3 + d_cur * 64;
            int c2 = tid & 63;                 // column pair
            int r0 = (tid >> 6) * 16;          // 4 row-groups of 16
            float2 racc = make_float2(0.f, 0.f);
            int prev = D[r0];
            #pragma unroll 4
            for (int r = r0; r < r0 + 16; ++r) {
                int d = D[r];
                if (d != prev) {
                    atomicAdd((__half2*)&g_aggr[(size_t)prev * 128 + 2 * c2],
                              __floats2half2_rn(racc.x, racc.y));
                    racc = make_float2(0.f, 0.f);
                    prev = d;
                }
                unsigned mm = *(const unsigned*)(h1p + r * 136 + 2 * c2);
                float2 f = __bfloat1622float2(*(__nv_bfloat162*)&mm);
                racc.x += f.x;
                racc.y += f.y;
            }
            atomicAdd((__half2*)&g_aggr[(size_t)prev * 128 + 2 * c2],
                      __floats2half2_rn(racc.x, racc.y));
        }
        __syncthreads();
    }
}

// ---------------- k3: node MLP (M=64, bf16 mma, bf16 staging) + residual + BN stats ----------------
// dyn smem: hsb bf16[64][200]@0 (25600) | xres f32[64][68]@25600 (17408)
//           ws bf16[128*24]@43008 (6144) | ssum@49152 | ssq@49408 | bnS@49664 | bnT@49920
//           total 50176
#define K3_SMEM 50176
__global__ void __launch_bounds__(256, 3) k3_node(int l, const float* __restrict__ W1,
                                                  const float* __restrict__ b1,
                                                  const float* __restrict__ W2,
                                                  const float* __restrict__ b2,
                                                  const float* __restrict__ gamma,
                                                  const float* __restrict__ beta) {
    extern __shared__ char sm3[];
    __nv_bfloat16* hsb = (__nv_bfloat16*)sm3;
    float* xres = (float*)(sm3 + 25600);
    __nv_bfloat16* ws = (__nv_bfloat16*)(sm3 + 43008);
    float* ssum = (float*)(sm3 + 49152);
    float* ssq = (float*)(sm3 + 49408);
    float* bnS = (float*)(sm3 + 49664);
    float* bnT = (float*)(sm3 + 49920);

    int tid = threadIdx.x, warp = tid >> 5, lane = tid & 31;
    int g = lane >> 2, tg = lane & 3;
    int mb = (warp & 3) * 16, nb = (warp >> 2) * 64;
    int n0 = blockIdx.x * 64;

    if (tid < 64) {
        ssum[tid] = 0.0f; ssq[tid] = 0.0f;
        bn_coeff(l, tid, gamma, beta, bnS[tid], bnT[tid]);
    }
    __syncthreads();

    // stage: cols 0..63 = x' (bf16 + fp32 copy), cols 64..191 = aggr (bf16)
    for (int it = 0; it < 48; ++it) {
        int idx = tid + it * 256;              // 12288
        int i = idx / 192, c = idx - i * 192;
        int node = n0 + i;
        float v = 0.0f;
        if (node < NN) {
            if (c < 64) v = g_x[(size_t)node * DD + c] * bnS[c] + bnT[c];
            else v = __half2float(g_aggr[(size_t)node * HH + (c - 64)]);
        }
        hsb[i * 200 + c] = __float2bfloat16(v);
        if (c < 64) xres[i * 68 + c] = v;
    }

    // GEMM1: t = spf([x'|aggr] @ nW1 + b1), M=64, N=128, K=192, bf16 mma
    float acc[8][4] = {};
    for (int k0 = 0; k0 < 192; k0 += 16) {
        __syncthreads();
        #pragma unroll
        for (int it = 0; it < 4; ++it) {
            int idx = tid + it * 256;          // 1024
            int col = idx & 127, kk2 = idx >> 7;
            int k = k0 + 2 * kk2;
            *(unsigned*)(ws + col * 24 + 2 * kk2) =
                pack_bf16(W1[((size_t)l * 192 + k) * 128 + col],
                          W1[((size_t)l * 192 + k + 1) * 128 + col]);
        }
        __syncthreads();
        unsigned a0 = *(const unsigned*)(hsb + (mb + g) * 200 + k0 + 2 * tg);
        unsigned a1 = *(const unsigned*)(hsb + (mb + g + 8) * 200 + k0 + 2 * tg);
        unsigned a2 = *(const unsigned*)(hsb + (mb + g) * 200 + k0 + 2 * tg + 8);
        unsigned a3 = *(const unsigned*)(hsb + (mb + g + 8) * 200 + k0 + 2 * tg + 8);
        #pragma unroll
        for (int nt = 0; nt < 8; ++nt) {
            int col = nb + nt * 8 + g;
            unsigned b0 = *(const unsigned*)(ws + col * 24 + 2 * tg);
            unsigned b1r = *(const unsigned*)(ws + col * 24 + 2 * tg + 8);
            mma16bf(acc[nt], a0, a1, a2, a3, b0, b1r);
        }
    }
    __syncthreads();
    // t -> bf16 into hsb cols 64..191 (aggr fully consumed)
    #pragma unroll
    for (int nt = 0; nt < 8; ++nt) {
        int c0 = nb + nt * 8 + 2 * tg;
        unsigned u0 = pack_bf16(spf(acc[nt][0] + b1[l * 128 + c0]),
                                spf(acc[nt][1] + b1[l * 128 + c0 + 1]));
        unsigned u1 = pack_bf16(spf(acc[nt][2] + b1[l * 128 + c0]),
                                spf(acc[nt][3] + b1[l * 128 + c0 + 1]));
        *(unsigned*)(hsb + (mb + g) * 200 + 64 + c0) = u0;
        *(unsigned*)(hsb + (mb + g + 8) * 200 + 64 + c0) = u1;
    }

    // GEMM2: y = t @ nW2 + b2 + x', M=64, N=64, K=128, bf16 mma
    int nb2 = (warp >> 2) * 32;
    float acc2[4][4] = {};
    for (int k0 = 0; k0 < 128; k0 += 16) {
        __syncthreads();
        #pragma unroll
        for (int it = 0; it < 2; ++it) {
            int idx = tid + it * 256;          // 512
            int col = idx & 63, kk2 = idx >> 6;
            int k = k0 + 2 * kk2;
            *(unsigned*)(ws + col * 24 + 2 * kk2) =
                pack_bf16(W2[((size_t)l * 128 + k) * 64 + col],
                          W2[((size_t)l * 128 + k + 1) * 64 + col]);
        }
        __syncthreads();
        unsigned a0 = *(const unsigned*)(hsb + (mb + g) * 200 + 64 + k0 + 2 * tg);
        unsigned a1 = *(const unsigned*)(hsb + (mb + g + 8) * 200 + 64 + k0 + 2 * tg);
        unsigned a2 = *(const unsigned*)(hsb + (mb + g) * 200 + 64 + k0 + 2 * tg + 8);
        unsigned a3 = *(const unsigned*)(hsb + (mb + g + 8) * 200 + 64 + k0 + 2 * tg + 8);
        #pragma unroll
        for (int nt = 0; nt < 4; ++nt) {
            int col = nb2 + nt * 8 + g;
            unsigned b0 = *(const unsigned*)(ws + col * 24 + 2 * tg);
            unsigned b1r = *(const unsigned*)(ws + col * 24 + 2 * tg + 8);
            mma16bf(acc2[nt], a0, a1, a2, a3, b0, b1r);
        }
    }

    #pragma unroll
    for (int nt = 0; nt < 4; ++nt) {
        int c0 = nb2 + nt * 8 + 2 * tg;
        float bb0 = b2[l * 64 + c0], bb1 = b2[l * 64 + c0 + 1];
        int row0 = mb + g, row1 = mb + g + 8;
        int node0 = n0 + row0, node1 = n0 + row1;
        if (node0 < NN) {
            float y0 = acc2[nt][0] + bb0 + xres[row0 * 68 + c0];
            float y1 = acc2[nt][1] + bb1 + xres[row0 * 68 + c0 + 1];
            g_x[(size_t)node0 * DD + c0] = y0;
            g_x[(size_t)node0 * DD + c0 + 1] = y1;
            atomicAdd(&ssum[c0], y0);     atomicAdd(&ssum[c0 + 1], y1);
            atomicAdd(&ssq[c0], y0 * y0); atomicAdd(&ssq[c0 + 1], y1 * y1);
        }
        if (node1 < NN) {
            float y2 = acc2[nt][2] + bb0 + xres[row1 * 68 + c0];
            float y3 = acc2[nt][3] + bb1 + xres[row1 * 68 + c0 + 1];
            g_x[(size_t)node1 * DD + c0] = y2;
            g_x[(size_t)node1 * DD + c0 + 1] = y3;
            atomicAdd(&ssum[c0], y2);     atomicAdd(&ssum[c0 + 1], y3);
            atomicAdd(&ssq[c0], y2 * y2); atomicAdd(&ssq[c0 + 1], y3 * y3);
        }
    }
    __syncthreads();
    if (tid < 64) {
        atomicAdd(&g_stats[l & 1][tid], ssum[tid]);
        atomicAdd(&g_stats[l & 1][64 + tid], ssq[tid]);
    }
}

// ---------------- k5: global mean pool (applies final BN) ----------------
__global__ void k5_pool(const int* __restrict__ batch,
                        const float* __restrict__ gamma, const float* __restrict__ beta) {
    int idx = blockIdx.x * blockDim.x + threadIdx.x;
    if (idx >= NN * DD) return;
    int i = idx >> 6, c = idx & 63;
    const float* sb = g_stats[(NL - 1) & 1];
    const float invN = 1.0f / (float)NN;
    float mu = sb[c] * invN;
    float var = sb[64 + c] * invN - mu * mu;
    float gi = gamma[(NL - 1) * 64 + c] * rsqrtf(var + 1e-5f);
    float v = g_x[idx] * gi + (beta[(NL - 1) * 64 + c] - mu * gi);
    int b = batch[i];
    atomicAdd(&g_pool[b * DD + c], v);
    if (c == 0) atomicAdd(&g_cnt[b], 1.0f);
}

// ---------------- k6: output MLP ----------------
__global__ void k6_out(const float* __restrict__ W1, const float* __restrict__ b1,
                       const float* __restrict__ W2, const float* __restrict__ b2,
                       float* __restrict__ out) {
    __shared__ float p[64];
    __shared__ float red[128];
    int g = blockIdx.x, c = threadIdx.x;
    if (c < 64) p[c] = g_pool[g * DD + c] / fmaxf(g_cnt[g], 1.0f);
    __syncthreads();
    float acc = b1[c];
    #pragma unroll
    for (int d = 0; d < 64; ++d) acc = fmaf(p[d], W1[d * 128 + c], acc);
    red[c] = softplusf(acc) * W2[c];
    __syncthreads();
    for (int s = 64; s > 0; s >>= 1) {
        if (c < s) red[c] += red[c + s];
        __syncthreads();
    }
    if (c == 0) out[g] = red[0] + b2[0];
}

// ---------------- launcher ----------------
extern "C" void kernel_launch(void* const* d_in, const int* in_sizes, int n_in,
                              void* d_out, int out_size) {
    const int*   atom_z = (const int*)  d_in[0];
    const int*   ei     = (const int*)  d_in[1];
    const float* eattr  = (const float*)d_in[2];
    const int*   batch  = (const int*)  d_in[3];
    const float* emb    = (const float*)d_in[4];
    const float* eW1    = (const float*)d_in[5];
    const float* eb1    = (const float*)d_in[6];
    const float* eW2    = (const float*)d_in[7];
    const float* eb2    = (const float*)d_in[8];
    const float* nW1    = (const float*)d_in[9];
    const float* nb1    = (const float*)d_in[10];
    const float* nW2    = (const float*)d_in[11];
    const float* nb2    = (const float*)d_in[12];
    const float* bng    = (const float*)d_in[13];
    const float* bnb    = (const float*)d_in[14];
    const float* oW1    = (const float*)d_in[15];
    const float* ob1    = (const float*)d_in[16];
    const float* oW2    = (const float*)d_in[17];
    const float* ob2    = (const float*)d_in[18];
    float* out = (float*)d_out;

    cudaFuncSetAttribute(k2_edge, cudaFuncAttributeMaxDynamicSharedMemorySize, K2_SMEM);
    cudaFuncSetAttribute(k3_node, cudaFuncAttributeMaxDynamicSharedMemorySize, K3_SMEM);

    int nsb = (NN + 1023) / 1024;

    k0_embed<<<(NN * DD + 255) / 256, 256>>>(atom_z, emb);
    k_hist<<<(NE + 255) / 256, 256>>>(ei);
    k_scan_part<<<nsb, 1024>>>();
    k1_AB<<<dim3((NN + 63) / 64, 2), 256>>>(0, eW1, eb1, bng, bnb);
    k_scan_top<<<1, 64>>>();
    k_scatter<<<(NE + 255) / 256, 256>>>(ei, eattr);

    k2_edge<<<K2_GRID, 256, K2_SMEM>>>(0, eW1, eW2, eb2);
    k3_node<<<(NN + 63) / 64, 256, K3_SMEM>>>(0, nW1, nb1, nW2, nb2, bng, bnb);
    for (int l = 1; l < NL; ++l) {
        k1_AB<<<dim3((NN + 63) / 64, 2), 256>>>(l, eW1, eb1, bng, bnb);
        k2_edge<<<K2_GRID, 256, K2_SMEM>>>(l, eW1, eW2, eb2);
        k3_node<<<(NN + 63) / 64, 256, K3_SMEM>>>(l, nW1, nb1, nW2, nb2, bng, bnb);
    }
    k5_pool<<<(NN * DD + 255) / 256, 256>>>(batch, bng, bnb);
    k6_out<<<GG, 128>>>(oW1, ob1, oW2, ob2, out);
}